// round 4
// baseline (speedup 1.0000x reference)
#include <cuda_runtime.h>
#include <cuda_bf16.h>
#include <math.h>
#include <stdint.h>

// Problem constants
#define BB 2
#define EE 1024
#define HH 16
#define DD 64
#define SS 4096            // 64*64 spatial tokens per batch
#define BNS (BB*SS)        // 8192 total tokens
#define E4 (4*EE)          // 4096 ffn hidden

typedef __nv_bfloat16 bf16;
typedef __nv_bfloat162 bf162;

// ---------------- device scratch ----------------
__device__ float g_adad[(long)BNS*EE];     // o-proj out
__device__ float g_q   [(long)BNS*EE];
__device__ float g_k   [(long)BNS*EE];
__device__ float g_v   [(long)BNS*EE];
__device__ float g_ffno[(long)BNS*EE];     // ffn2 out
__device__ float g_work[(long)BNS*EE];
__device__ bf16  g_xh  [(long)BNS*EE];
__device__ bf16  g_xl  [(long)BNS*EE];
__device__ bf16  g_wh  [(long)E4*EE];
__device__ bf16  g_wl  [(long)E4*EE];
__device__ bf16  g_hh  [(long)BNS*E4];
__device__ bf16  g_hl  [(long)BNS*E4];
__device__ float g_kv  [BB*HH*DD*DD];
__device__ float g_ksum[BB*HH*DD];
__device__ float g_sumsq[BB*EE];
__device__ float g_meangx[BB];

// ================= helpers =================
__device__ __forceinline__ uint32_t smem_u32(const void* p) {
    uint32_t a;
    asm("{ .reg .u64 t; cvta.to.shared.u64 t, %1; cvt.u32.u64 %0, t; }" : "=r"(a) : "l"(p));
    return a;
}
__device__ __forceinline__ void cp16(uint32_t dst, const void* src) {
    asm volatile("cp.async.cg.shared.global [%0], [%1], 16;" :: "r"(dst), "l"(src));
}
__device__ __forceinline__ void ldm_x4(uint32_t* r, uint32_t addr) {
    asm volatile("ldmatrix.sync.aligned.m8n8.x4.shared.b16 {%0,%1,%2,%3}, [%4];"
        : "=r"(r[0]), "=r"(r[1]), "=r"(r[2]), "=r"(r[3]) : "r"(addr));
}
__device__ __forceinline__ void mma16816(float* c, const uint32_t* a, const uint32_t* b) {
    asm volatile(
        "mma.sync.aligned.m16n8k16.row.col.f32.bf16.bf16.f32 "
        "{%0,%1,%2,%3}, {%4,%5,%6,%7}, {%8,%9}, {%0,%1,%2,%3};"
        : "+f"(c[0]), "+f"(c[1]), "+f"(c[2]), "+f"(c[3])
        : "r"(a[0]), "r"(a[1]), "r"(a[2]), "r"(a[3]), "r"(b[0]), "r"(b[1]));
}
__device__ __forceinline__ void split_bf16(float v, bf16& h, bf16& l) {
    h = __float2bfloat16(v);
    l = __float2bfloat16(v - __bfloat162float(h));
}

// ================= GEMM: C[M,N] = (Ah+Al)(Wh+Wl)^T + bias (3-pass bf16) =====
// Block 128x128, KT=32, 8 warps (2 M x 4 N), warp tile 64x32, ldmatrix fragments.
#define TPITCH 80
#define TBYTES (128*TPITCH)          // 10240
#define STAGEB (4*TBYTES)            // 40960
#define GSMEM  (2*STAGEB)            // 81920

template<int EPI>
__global__ __launch_bounds__(256, 2) void gemm_hmma(
    const bf16* __restrict__ Ah, const bf16* __restrict__ Al,
    const bf16* __restrict__ Wh, const bf16* __restrict__ Wl,
    const float* __restrict__ bias,
    float* __restrict__ C, bf16* __restrict__ CH, bf16* __restrict__ CL,
    int M, int N, int K)
{
    extern __shared__ char sm[];
    const uint32_t sbase = smem_u32(sm);
    const int tid = threadIdx.x;
    const int lane = tid & 31, wid = tid >> 5;
    const int warp_m = wid >> 2, warp_n = wid & 3;
    const int m0 = blockIdx.y * 128, n0 = blockIdx.x * 128;
    const int lrow = lane >> 2, lpair = lane & 3;
    // ldmatrix lane addressing: row = lane&15, 16B-chunk = lane>>4
    const uint32_t lmrow = (lane & 15), lmch = (lane >> 4) * 16;

    float acc[4][4][4];
    #pragma unroll
    for (int i = 0; i < 4; i++)
        #pragma unroll
        for (int j = 0; j < 4; j++)
            #pragma unroll
            for (int t = 0; t < 4; t++) acc[i][j][t] = 0.f;

    const int nk = K >> 5;

    auto load_stage = [&](int buf, int kc) {
        const long kq = (long)kc * 32;
        uint32_t sb = sbase + buf * STAGEB;
        #pragma unroll
        for (int i = 0; i < 2; i++) {
            int p = tid + i * 256;
            int row = p >> 2, ch = p & 3;
            long goff = (long)(m0 + row) * K + kq + ch * 8;
            uint32_t d = sb + row * TPITCH + ch * 16;
            cp16(d,            Ah + goff);
            cp16(d + TBYTES,   Al + goff);
            long boff = (long)(n0 + row) * K + kq + ch * 8;
            cp16(d + 2*TBYTES, Wh + boff);
            cp16(d + 3*TBYTES, Wl + boff);
        }
        asm volatile("cp.async.commit_group;");
    };

    load_stage(0, 0);
    if (nk > 1) load_stage(1, 1);

    for (int kc = 0; kc < nk; kc++) {
        const int buf = kc & 1;
        if (kc + 2 < nk) asm volatile("cp.async.wait_group 1;");
        else             asm volatile("cp.async.wait_group 0;");
        __syncthreads();

        const uint32_t aHb = sbase + buf * STAGEB;
        const uint32_t aLb = aHb + TBYTES;
        const uint32_t bHb = aHb + 2*TBYTES;
        const uint32_t bLb = aHb + 3*TBYTES;
        // per-lane ldmatrix base offsets
        const uint32_t aoff = (warp_m * 64 + lmrow) * TPITCH + lmch;
        const uint32_t boff = (warp_n * 32 + lmrow) * TPITCH + lmch;

        #pragma unroll
        for (int s = 0; s < 2; s++) {
            const uint32_t ks = s * 32;
            uint32_t aH[4][4], bH[4][2], t[4];
            // load B hi: 2 x ldmatrix.x4, each covers n16 x k16
            #pragma unroll
            for (int g = 0; g < 2; g++) {
                ldm_x4(t, bHb + boff + g * 16 * TPITCH + ks);
                bH[g*2+0][0] = t[0]; bH[g*2+0][1] = t[2];
                bH[g*2+1][0] = t[1]; bH[g*2+1][1] = t[3];
            }
            // load A hi: 4 x ldmatrix.x4
            #pragma unroll
            for (int mt = 0; mt < 4; mt++)
                ldm_x4(aH[mt], aHb + aoff + mt * 16 * TPITCH + ks);
            // pass 1: Ah x Bh
            #pragma unroll
            for (int mt = 0; mt < 4; mt++)
                #pragma unroll
                for (int nt = 0; nt < 4; nt++)
                    mma16816(acc[mt][nt], aH[mt], bH[nt]);
            // pass 2: Ah x Bl
            {
                uint32_t bL[4][2];
                #pragma unroll
                for (int g = 0; g < 2; g++) {
                    ldm_x4(t, bLb + boff + g * 16 * TPITCH + ks);
                    bL[g*2+0][0] = t[0]; bL[g*2+0][1] = t[2];
                    bL[g*2+1][0] = t[1]; bL[g*2+1][1] = t[3];
                }
                #pragma unroll
                for (int mt = 0; mt < 4; mt++)
                    #pragma unroll
                    for (int nt = 0; nt < 4; nt++)
                        mma16816(acc[mt][nt], aH[mt], bL[nt]);
            }
            // pass 3: Al x Bh
            {
                uint32_t aL[4];
                #pragma unroll
                for (int mt = 0; mt < 4; mt++) {
                    ldm_x4(aL, aLb + aoff + mt * 16 * TPITCH + ks);
                    #pragma unroll
                    for (int nt = 0; nt < 4; nt++)
                        mma16816(acc[mt][nt], aL, bH[nt]);
                }
            }
        }
        __syncthreads();
        if (kc + 2 < nk) load_stage(buf, kc + 2);
    }

    // ---- epilogue ----
    #pragma unroll
    for (int mt = 0; mt < 4; mt++) {
        #pragma unroll
        for (int nt = 0; nt < 4; nt++) {
            long row = m0 + warp_m * 64 + mt * 16 + lrow;
            int col = n0 + warp_n * 32 + nt * 8 + lpair * 2;
            float b0 = bias[col], b1 = bias[col + 1];
            #pragma unroll
            for (int half = 0; half < 2; half++) {
                long r = row + half * 8;
                float v0 = acc[mt][nt][half*2 + 0] + b0;
                float v1 = acc[mt][nt][half*2 + 1] + b1;
                if (EPI == 0) {
                    *(float2*)(C + r * N + col) = make_float2(v0, v1);
                } else {
                    v0 = v0 / (1.f + expf(-v0));
                    v1 = v1 / (1.f + expf(-v1));
                    bf16 h0, l0, h1, l1;
                    split_bf16(v0, h0, l0);
                    split_bf16(v1, h1, l1);
                    *(bf162*)(CH + r * N + col) = __halves2bfloat162(h0, h1);
                    *(bf162*)(CL + r * N + col) = __halves2bfloat162(l0, l1);
                }
            }
        }
    }
}

// ================= converters =================
__global__ __launch_bounds__(256) void cvt_split(const float* __restrict__ x,
                                                 bf16* __restrict__ oh,
                                                 bf16* __restrict__ ol) {
    long i = ((long)blockIdx.x * 256 + threadIdx.x) * 4;
    float4 v = *(const float4*)(x + i);
    bf16 h0, l0, h1, l1, h2, l2, h3, l3;
    split_bf16(v.x, h0, l0); split_bf16(v.y, h1, l1);
    split_bf16(v.z, h2, l2); split_bf16(v.w, h3, l3);
    *(bf162*)(oh + i)     = __halves2bfloat162(h0, h1);
    *(bf162*)(oh + i + 2) = __halves2bfloat162(h2, h3);
    *(bf162*)(ol + i)     = __halves2bfloat162(l0, l1);
    *(bf162*)(ol + i + 2) = __halves2bfloat162(l2, l3);
}

// transpose [B,E,S] fp32 -> [B,S,E] bf16 hi/lo
__global__ void cvt_T(const float* __restrict__ x, bf16* __restrict__ oh,
                      bf16* __restrict__ ol) {
    __shared__ float t[32][33];
    int sx = blockIdx.x * 32, cy = blockIdx.y * 32, b = blockIdx.z;
    int lx = threadIdx.x;
    for (int r = threadIdx.y; r < 32; r += 8)
        t[r][lx] = x[((long)b * EE + cy + r) * SS + sx + lx];
    __syncthreads();
    for (int r = threadIdx.y; r < 32; r += 8) {
        float v = t[lx][r];
        long o = ((long)b * SS + sx + r) * EE + cy + lx;
        bf16 h, l;
        split_bf16(v, h, l);
        oh[o] = h; ol[o] = l;
    }
}

// GRN1 apply fused with transpose + bf16 split:
// out[b,s,c] = grn(qimg)[b,c,s], written token-major hi/lo
__global__ void grn1_T(const float* __restrict__ x,
                       const float* __restrict__ sumsq,
                       const float* __restrict__ meangx,
                       const float* __restrict__ gamma,
                       const float* __restrict__ beta,
                       bf16* __restrict__ oh, bf16* __restrict__ ol) {
    __shared__ float t[32][33];
    int sx = blockIdx.x * 32, cy = blockIdx.y * 32, b = blockIdx.z;
    int lx = threadIdx.x;
    for (int r = threadIdx.y; r < 32; r += 8)
        t[r][lx] = x[((long)b * EE + cy + r) * SS + sx + lx];
    __syncthreads();
    int c = cy + lx;
    float nx = sqrtf(sumsq[b*EE + c]) / (meangx[b] + 1e-6f);
    float g1 = 1.f + gamma[c], be = beta[c];
    for (int r = threadIdx.y; r < 32; r += 8) {
        float v = t[lx][r];
        float o = g1 * v * nx + be + v;
        long oi = ((long)b * SS + sx + r) * EE + c;
        bf16 h, l;
        split_bf16(o, h, l);
        oh[oi] = h; ol[oi] = l;
    }
}

// ---------------- small helpers ----------------
__inline__ __device__ void blockReduce2(float& a, float& b) {
    #pragma unroll
    for (int off = 16; off > 0; off >>= 1) {
        a += __shfl_down_sync(0xffffffffu, a, off);
        b += __shfl_down_sync(0xffffffffu, b, off);
    }
    __shared__ float sa[8], sb[8];
    int w = threadIdx.x >> 5, l = threadIdx.x & 31;
    if (l == 0) { sa[w] = a; sb[w] = b; }
    __syncthreads();
    if (w == 0) {
        a = (l < 8) ? sa[l] : 0.f;
        b = (l < 8) ? sb[l] : 0.f;
        #pragma unroll
        for (int off = 4; off > 0; off >>= 1) {
            a += __shfl_down_sync(0xffu, a, off);
            b += __shfl_down_sync(0xffu, b, off);
        }
        if (l == 0) { sa[0] = a; sb[0] = b; }
    }
    __syncthreads();
    a = sa[0]; b = sb[0];
}

__global__ void zero_f(float* __restrict__ p, int n) {
    int i = blockIdx.x * blockDim.x + threadIdx.x;
    if (i < n) p[i] = 0.f;
}

// ---------------- GRN reductions ----------------
__global__ __launch_bounds__(256) void grn_sumsq_cm(const float* __restrict__ x,
                                                    float* __restrict__ sumsq) {
    const float* xr = x + (long)blockIdx.x * SS;
    float acc = 0.f, dummy = 0.f;
    for (int i = threadIdx.x * 4; i < SS; i += 1024) {
        float4 v = *(const float4*)(xr + i);
        acc += v.x*v.x + v.y*v.y + v.z*v.z + v.w*v.w;
    }
    blockReduce2(acc, dummy);
    if (threadIdx.x == 0) sumsq[blockIdx.x] = acc;
}

__global__ __launch_bounds__(256) void grn_mean(const float* __restrict__ sumsq,
                                                float* __restrict__ meangx) {
    int b = blockIdx.x;
    float s = 0.f, dummy = 0.f;
    for (int c = threadIdx.x; c < EE; c += 256) s += sqrtf(sumsq[b*EE + c]);
    blockReduce2(s, dummy);
    if (threadIdx.x == 0) meangx[b] = s / (float)EE;
}

__global__ __launch_bounds__(256) void grn2_sumsq(const float* __restrict__ w,
                                                  float* __restrict__ sumsq) {
    int c = blockIdx.x * 256 + threadIdx.x;
    int b = blockIdx.z;
    long base = ((long)b * SS + (long)blockIdx.y * 256) * EE + c;
    float acc = 0.f;
    #pragma unroll 4
    for (int r = 0; r < 256; r++) {
        float v = w[base + (long)r * EE];
        acc += v * v;
    }
    atomicAdd(&sumsq[b*EE + c], acc);
}

// GRN2 apply, token-major, writes bf16 hi/lo directly
__global__ __launch_bounds__(256) void grn2_apply(const float* __restrict__ x,
                                                  const float* __restrict__ sumsq,
                                                  const float* __restrict__ meangx,
                                                  const float* __restrict__ gamma,
                                                  const float* __restrict__ beta,
                                                  bf16* __restrict__ oh,
                                                  bf16* __restrict__ ol) {
    long i4 = ((long)blockIdx.x * 256 + threadIdx.x) * 4;
    int c0 = (int)(i4 & 1023);
    int b = (int)(i4 >> 22);
    float4 g4 = *(const float4*)(gamma + c0);
    float4 b4 = *(const float4*)(beta + c0);
    float4 s4 = *(const float4*)(sumsq + b*EE + c0);
    float mg = meangx[b] + 1e-6f;
    float4 v = *(const float4*)(x + i4);
    float o0 = (1.f+g4.x) * v.x * (sqrtf(s4.x)/mg) + b4.x + v.x;
    float o1 = (1.f+g4.y) * v.y * (sqrtf(s4.y)/mg) + b4.y + v.y;
    float o2 = (1.f+g4.z) * v.z * (sqrtf(s4.z)/mg) + b4.z + v.z;
    float o3 = (1.f+g4.w) * v.w * (sqrtf(s4.w)/mg) + b4.w + v.w;
    bf16 h0, l0, h1, l1, h2, l2, h3, l3;
    split_bf16(o0, h0, l0); split_bf16(o1, h1, l1);
    split_bf16(o2, h2, l2); split_bf16(o3, h3, l3);
    *(bf162*)(oh + i4)     = __halves2bfloat162(h0, h1);
    *(bf162*)(oh + i4 + 2) = __halves2bfloat162(h2, h3);
    *(bf162*)(ol + i4)     = __halves2bfloat162(l0, l1);
    *(bf162*)(ol + i4 + 2) = __halves2bfloat162(l2, l3);
}

// ---------------- LayerNorm + (elu+1) ----------------
__global__ __launch_bounds__(256) void ln_elu(float* __restrict__ x,
                                              const float* __restrict__ w,
                                              const float* __restrict__ b) {
    float* xr = x + (long)blockIdx.x * EE;
    int tid = threadIdx.x;
    float4 v = *(const float4*)(xr + tid*4);
    float s  = v.x + v.y + v.z + v.w;
    float sq = v.x*v.x + v.y*v.y + v.z*v.z + v.w*v.w;
    blockReduce2(s, sq);
    float mean = s / (float)EE;
    float var = sq / (float)EE - mean*mean;
    float rstd = rsqrtf(var + 1e-5f);
    float4 wv = *(const float4*)(w + tid*4);
    float4 bv = *(const float4*)(b + tid*4);
    float y;
    y = (v.x-mean)*rstd*wv.x + bv.x; v.x = (y > 0.f) ? y + 1.f : expf(y);
    y = (v.y-mean)*rstd*wv.y + bv.y; v.y = (y > 0.f) ? y + 1.f : expf(y);
    y = (v.z-mean)*rstd*wv.z + bv.z; v.z = (y > 0.f) ? y + 1.f : expf(y);
    y = (v.w-mean)*rstd*wv.w + bv.w; v.w = (y > 0.f) ? y + 1.f : expf(y);
    *(float4*)(xr + tid*4) = v;
}

// ---------------- linear attention ----------------
__global__ __launch_bounds__(256) void kvsum_kernel(const float* __restrict__ k,
                                                    const float* __restrict__ v,
                                                    float* __restrict__ kv,
                                                    float* __restrict__ ksum) {
    int bh = blockIdx.x;
    int b = bh >> 4, h = bh & 15;
    int tid = threadIdx.x;
    __shared__ float ks[16][68], vs[16][68];
    int d0 = (tid >> 4) * 4, e0 = (tid & 15) * 4;
    float acc[4][4] = {};
    float accks[4] = {};
    long base = ((long)b * SS + (long)blockIdx.y * 256) * EE + h * DD;
    int ltok = tid >> 4, lc = (tid & 15) * 4;
    for (int t0 = 0; t0 < 256; t0 += 16) {
        *(float4*)&ks[ltok][lc] = *(const float4*)(k + base + (long)(t0+ltok)*EE + lc);
        *(float4*)&vs[ltok][lc] = *(const float4*)(v + base + (long)(t0+ltok)*EE + lc);
        __syncthreads();
        #pragma unroll
        for (int t = 0; t < 16; t++) {
            float a[4], bb[4];
            #pragma unroll
            for (int i = 0; i < 4; i++) a[i] = ks[t][d0+i];
            #pragma unroll
            for (int j = 0; j < 4; j++) bb[j] = vs[t][e0+j];
            #pragma unroll
            for (int i = 0; i < 4; i++)
                #pragma unroll
                for (int j = 0; j < 4; j++) acc[i][j] += a[i]*bb[j];
            if (e0 == 0) {
                #pragma unroll
                for (int i = 0; i < 4; i++) accks[i] += a[i];
            }
        }
        __syncthreads();
    }
    long kvbase = (long)bh * DD * DD;
    #pragma unroll
    for (int i = 0; i < 4; i++)
        #pragma unroll
        for (int j = 0; j < 4; j++)
            atomicAdd(&kv[kvbase + (d0+i)*DD + e0+j], acc[i][j]);
    if (e0 == 0)
        #pragma unroll
        for (int i = 0; i < 4; i++) atomicAdd(&ksum[bh*DD + d0+i], accks[i]);
}

// attn = (q @ kv) / (q . ksum + 1e-8), writes bf16 hi/lo directly
__global__ __launch_bounds__(256) void attn_apply_kernel(const float* __restrict__ q,
                                                         const float* __restrict__ kv,
                                                         const float* __restrict__ ksum,
                                                         bf16* __restrict__ oh,
                                                         bf16* __restrict__ ol) {
    int bh = blockIdx.x, sblk = blockIdx.y;
    int b = bh >> 4, h = bh & 15;
    int tid = threadIdx.x;
    __shared__ float qs[64][68];
    __shared__ float kvs[64][64];
    __shared__ float kss[64];
    long kvbase = (long)bh * DD * DD;
    #pragma unroll
    for (int r = 0; r < 4; r++) {
        int idx = (r*256 + tid) * 4;
        *(float4*)&kvs[idx >> 6][idx & 63] = *(const float4*)(kv + kvbase + idx);
    }
    if (tid < 64) kss[tid] = ksum[bh*DD + tid];
    long qbase = ((long)b * SS + (long)sblk * 64) * EE + h * DD;
    int ltok = tid >> 4, lc = (tid & 15) * 4;
    #pragma unroll
    for (int r = 0; r < 4; r++)
        *(float4*)&qs[ltok + r*16][lc] =
            *(const float4*)(q + qbase + (long)(ltok + r*16)*EE + lc);
    __syncthreads();
    int tok = tid >> 2, e0 = (tid & 3) * 16;
    float num[16] = {};
    float den = 0.f;
    #pragma unroll 8
    for (int d = 0; d < 64; d++) {
        float qd = qs[tok][d];
        den += qd * kss[d];
        #pragma unroll
        for (int j = 0; j < 16; j++) num[j] += qd * kvs[d][e0+j];
    }
    float r = 1.f / (den + 1e-8f);
    long obase = ((long)b * SS + (long)sblk * 64 + tok) * EE + h * DD + e0;
    #pragma unroll
    for (int j = 0; j < 16; j += 2) {
        bf16 h0, l0, h1, l1;
        split_bf16(num[j]   * r, h0, l0);
        split_bf16(num[j+1] * r, h1, l1);
        *(bf162*)(oh + obase + j) = __halves2bfloat162(h0, h1);
        *(bf162*)(ol + obase + j) = __halves2bfloat162(l0, l1);
    }
}

// ---------------- residual / transpose kernels ----------------
__global__ void make_working(const float* __restrict__ qimg,
                             const float* __restrict__ attn_out,
                             const float* __restrict__ ascal,
                             float* __restrict__ work) {
    __shared__ float t[32][33];
    int sx = blockIdx.x * 32, cy = blockIdx.y * 32, b = blockIdx.z;
    int x = threadIdx.x;
    for (int r = threadIdx.y; r < 32; r += 8)
        t[r][x] = qimg[((long)b*EE + cy + r)*SS + sx + x];
    __syncthreads();
    for (int r = threadIdx.y; r < 32; r += 8) {
        long o = ((long)b*SS + sx + r)*EE + cy + x;
        work[o] = t[x][r] + attn_out[o] * ascal[cy + x];
    }
}

__global__ void final_kernel(const float* __restrict__ qimg,
                             const float* __restrict__ work,
                             const float* __restrict__ ffn,
                             const float* __restrict__ fscal,
                             const float* __restrict__ finscal,
                             float* __restrict__ out) {
    __shared__ float t[32][33];
    int sx = blockIdx.x * 32, cy = blockIdx.y * 32, b = blockIdx.z;
    int x = threadIdx.x;
    for (int r = threadIdx.y; r < 32; r += 8) {
        long o = ((long)b*SS + sx + r)*EE + cy + x;
        t[r][x] = (work[o] + ffn[o] * fscal[cy + x]) * finscal[cy + x];
    }
    __syncthreads();
    for (int r = threadIdx.y; r < 32; r += 8) {
        long o = ((long)b*EE + cy + r)*SS + sx + x;
        out[o] = qimg[o] + t[x][r];
    }
}

// ---------------- host launcher ----------------
extern "C" void kernel_launch(void* const* d_in, const int* in_sizes, int n_in,
                              void* d_out, int out_size) {
    const float* qimg   = (const float*)d_in[0];
    const float* kimg   = (const float*)d_in[1];
    const float* vimg   = (const float*)d_in[2];
    const float* grn1_g = (const float*)d_in[3];
    const float* grn1_b = (const float*)d_in[4];
    const float* q_w    = (const float*)d_in[5];
    const float* q_b    = (const float*)d_in[6];
    const float* k_w    = (const float*)d_in[7];
    const float* k_b    = (const float*)d_in[8];
    const float* v_w    = (const float*)d_in[9];
    const float* v_b    = (const float*)d_in[10];
    const float* o_w    = (const float*)d_in[11];
    const float* o_b    = (const float*)d_in[12];
    const float* lnq_w  = (const float*)d_in[13];
    const float* lnq_b  = (const float*)d_in[14];
    const float* lnk_w  = (const float*)d_in[15];
    const float* lnk_b  = (const float*)d_in[16];
    const float* ascal  = (const float*)d_in[17];
    const float* grn2_g = (const float*)d_in[18];
    const float* grn2_b = (const float*)d_in[19];
    const float* w1     = (const float*)d_in[20];
    const float* b1     = (const float*)d_in[21];
    const float* w2     = (const float*)d_in[22];
    const float* b2     = (const float*)d_in[23];
    const float* fscal  = (const float*)d_in[24];
    const float* finscal= (const float*)d_in[25];

    float *adad, *qb, *kb, *vb, *ffno, *work, *kv, *ksum, *sumsq, *meang;
    bf16 *xh, *xl, *wh, *wl, *hh, *hl;
    cudaGetSymbolAddress((void**)&adad, g_adad);
    cudaGetSymbolAddress((void**)&qb,   g_q);
    cudaGetSymbolAddress((void**)&kb,   g_k);
    cudaGetSymbolAddress((void**)&vb,   g_v);
    cudaGetSymbolAddress((void**)&ffno, g_ffno);
    cudaGetSymbolAddress((void**)&work, g_work);
    cudaGetSymbolAddress((void**)&xh,   g_xh);
    cudaGetSymbolAddress((void**)&xl,   g_xl);
    cudaGetSymbolAddress((void**)&wh,   g_wh);
    cudaGetSymbolAddress((void**)&wl,   g_wl);
    cudaGetSymbolAddress((void**)&hh,   g_hh);
    cudaGetSymbolAddress((void**)&hl,   g_hl);
    cudaGetSymbolAddress((void**)&kv,   g_kv);
    cudaGetSymbolAddress((void**)&ksum, g_ksum);
    cudaGetSymbolAddress((void**)&sumsq,g_sumsq);
    cudaGetSymbolAddress((void**)&meang,g_meangx);

    cudaFuncSetAttribute(gemm_hmma<0>, cudaFuncAttributeMaxDynamicSharedMemorySize, GSMEM);
    cudaFuncSetAttribute(gemm_hmma<1>, cudaFuncAttributeMaxDynamicSharedMemorySize, GSMEM);

    const long ES = (long)EE * SS;
    dim3 tgrid(SS/32, EE/32, BB);
    dim3 tblk(32, 8);

    // GRN1 on query image (apply fused with transpose + bf16 split)
    grn_sumsq_cm<<<BB*EE, 256>>>(qimg, sumsq);
    grn_mean<<<BB, 256>>>(sumsq, meang);
    grn1_T<<<tgrid, tblk>>>(qimg, sumsq, meang, grn1_g, grn1_b, xh, xl);

    // Q projection
    cvt_split<<<EE*EE/1024, 256>>>(q_w, wh, wl);
    gemm_hmma<0><<<dim3(EE/128, BNS/128), 256, GSMEM>>>(xh, xl, wh, wl, q_b,
        qb, nullptr, nullptr, BNS, EE, EE);
    // K projection
    cvt_T<<<tgrid, tblk>>>(kimg, xh, xl);
    cvt_split<<<EE*EE/1024, 256>>>(k_w, wh, wl);
    gemm_hmma<0><<<dim3(EE/128, BNS/128), 256, GSMEM>>>(xh, xl, wh, wl, k_b,
        kb, nullptr, nullptr, BNS, EE, EE);
    // V projection
    cvt_T<<<tgrid, tblk>>>(vimg, xh, xl);
    cvt_split<<<EE*EE/1024, 256>>>(v_w, wh, wl);
    gemm_hmma<0><<<dim3(EE/128, BNS/128), 256, GSMEM>>>(xh, xl, wh, wl, v_b,
        vb, nullptr, nullptr, BNS, EE, EE);

    // LayerNorm + elu+1 (in place)
    ln_elu<<<BNS, 256>>>(qb, lnq_w, lnq_b);
    ln_elu<<<BNS, 256>>>(kb, lnk_w, lnk_b);

    // linear attention (output straight to bf16 hi/lo)
    zero_f<<<(BB*HH*DD*DD + 255)/256, 256>>>(kv, BB*HH*DD*DD);
    zero_f<<<(BB*HH*DD + 255)/256, 256>>>(ksum, BB*HH*DD);
    kvsum_kernel<<<dim3(BB*HH, 16), 256>>>(kb, vb, kv, ksum);
    attn_apply_kernel<<<dim3(BB*HH, SS/64), 256>>>(qb, kv, ksum, xh, xl);

    // O projection -> adad (token-major fp32)
    cvt_split<<<EE*EE/1024, 256>>>(o_w, wh, wl);
    gemm_hmma<0><<<dim3(EE/128, BNS/128), 256, GSMEM>>>(xh, xl, wh, wl, o_b,
        adad, nullptr, nullptr, BNS, EE, EE);

    // working = qimg^T + oproj * attn_scalar (token-major)
    make_working<<<tgrid, tblk>>>(qimg, adad, ascal, work);

    // GRN2 on working (apply writes bf16 hi/lo directly)
    zero_f<<<(BB*EE + 255)/256, 256>>>(sumsq, BB*EE);
    grn2_sumsq<<<dim3(EE/256, SS/256, BB), 256>>>(work, sumsq);
    grn_mean<<<BB, 256>>>(sumsq, meang);
    grn2_apply<<<(int)(BB*ES/1024), 256>>>(work, sumsq, meang, grn2_g, grn2_b, xh, xl);

    // FFN1: silu epilogue -> bf16 hi/lo hidden
    cvt_split<<<E4*EE/1024, 256>>>(w1, wh, wl);
    gemm_hmma<1><<<dim3(E4/128, BNS/128), 256, GSMEM>>>(xh, xl, wh, wl, b1,
        nullptr, hh, hl, BNS, E4, EE);

    // FFN2
    cvt_split<<<EE*E4/1024, 256>>>(w2, wh, wl);
    gemm_hmma<0><<<dim3(EE/128, BNS/128), 256, GSMEM>>>(hh, hl, wh, wl, b2,
        ffno, nullptr, nullptr, BNS, EE, E4);

    // final residual (transpose back to channel-major)
    final_kernel<<<tgrid, tblk>>>(qimg, work, ffno, fscal, finscal, (float*)d_out);
}

// round 5
// speedup vs baseline: 1.0873x; 1.0873x over previous
#include <cuda_runtime.h>
#include <cuda_bf16.h>
#include <math.h>
#include <stdint.h>

// Problem constants
#define BB 2
#define EE 1024
#define HH 16
#define DD 64
#define SS 4096            // 64*64 spatial tokens per batch
#define BNS (BB*SS)        // 8192 total tokens
#define E4 (4*EE)          // 4096 ffn hidden

typedef __nv_bfloat16 bf16;
typedef __nv_bfloat162 bf162;

// ---------------- device scratch ----------------
__device__ float g_adad[(long)BNS*EE];     // o-proj out
__device__ float g_q   [(long)BNS*EE];
__device__ float g_k   [(long)BNS*EE];
__device__ float g_v   [(long)BNS*EE];
__device__ float g_ffno[(long)BNS*EE];     // ffn2 out
__device__ float g_work[(long)BNS*EE];
__device__ bf16  g_xh  [(long)BNS*EE];
__device__ bf16  g_xl  [(long)BNS*EE];
__device__ bf16  g_wh  [(long)E4*EE];
__device__ bf16  g_wl  [(long)E4*EE];
__device__ bf16  g_hh  [(long)BNS*E4];
__device__ bf16  g_hl  [(long)BNS*E4];
__device__ float g_kv  [BB*HH*DD*DD];
__device__ float g_ksum[BB*HH*DD];
__device__ float g_sumsq[BB*EE];
__device__ float g_meangx[BB];

// ================= helpers =================
__device__ __forceinline__ uint32_t smem_u32(const void* p) {
    uint32_t a;
    asm("{ .reg .u64 t; cvta.to.shared.u64 t, %1; cvt.u32.u64 %0, t; }" : "=r"(a) : "l"(p));
    return a;
}
__device__ __forceinline__ void cp16(uint32_t dst, const void* src) {
    asm volatile("cp.async.cg.shared.global [%0], [%1], 16;" :: "r"(dst), "l"(src));
}
__device__ __forceinline__ uint32_t lds32(uint32_t a) {
    uint32_t v;
    asm volatile("ld.shared.u32 %0, [%1];" : "=r"(v) : "r"(a));
    return v;
}
__device__ __forceinline__ void mma16816(float* c, const uint32_t* a, const uint32_t* b) {
    asm volatile(
        "mma.sync.aligned.m16n8k16.row.col.f32.bf16.bf16.f32 "
        "{%0,%1,%2,%3}, {%4,%5,%6,%7}, {%8,%9}, {%0,%1,%2,%3};"
        : "+f"(c[0]), "+f"(c[1]), "+f"(c[2]), "+f"(c[3])
        : "r"(a[0]), "r"(a[1]), "r"(a[2]), "r"(a[3]), "r"(b[0]), "r"(b[1]));
}
__device__ __forceinline__ void split_bf16(float v, bf16& h, bf16& l) {
    h = __float2bfloat16(v);
    l = __float2bfloat16(v - __bfloat162float(h));
}

// ================= GEMM: C[M,N] = (Ah+Al)(Wh+Wl)^T + bias (3-pass bf16) =====
// Block 128x128, KT=32, 8 warps (2 M x 4 N), warp tile 64x32, scalar LDS frags.
#define TPITCH 80
#define TBYTES (128*TPITCH)          // 10240
#define STAGEB (4*TBYTES)            // 40960
#define GSMEM  (2*STAGEB)            // 81920

template<int EPI>
__global__ __launch_bounds__(256, 2) void gemm_hmma(
    const bf16* __restrict__ Ah, const bf16* __restrict__ Al,
    const bf16* __restrict__ Wh, const bf16* __restrict__ Wl,
    const float* __restrict__ bias,
    float* __restrict__ C, bf16* __restrict__ CH, bf16* __restrict__ CL,
    int M, int N, int K)
{
    extern __shared__ char sm[];
    const uint32_t sbase = smem_u32(sm);
    const int tid = threadIdx.x;
    const int lane = tid & 31, wid = tid >> 5;
    const int warp_m = wid >> 2, warp_n = wid & 3;
    const int m0 = blockIdx.y * 128, n0 = blockIdx.x * 128;
    const int lrow = lane >> 2, lpair = lane & 3;

    float acc[4][4][4];
    #pragma unroll
    for (int i = 0; i < 4; i++)
        #pragma unroll
        for (int j = 0; j < 4; j++)
            #pragma unroll
            for (int t = 0; t < 4; t++) acc[i][j][t] = 0.f;

    const int nk = K >> 5;

    auto load_stage = [&](int buf, int kc) {
        const long kq = (long)kc * 32;
        uint32_t sb = sbase + buf * STAGEB;
        #pragma unroll
        for (int i = 0; i < 2; i++) {
            int p = tid + i * 256;
            int row = p >> 2, ch = p & 3;
            long goff = (long)(m0 + row) * K + kq + ch * 8;
            uint32_t d = sb + row * TPITCH + ch * 16;
            cp16(d,            Ah + goff);
            cp16(d + TBYTES,   Al + goff);
            long boff = (long)(n0 + row) * K + kq + ch * 8;
            cp16(d + 2*TBYTES, Wh + boff);
            cp16(d + 3*TBYTES, Wl + boff);
        }
        asm volatile("cp.async.commit_group;");
    };

    load_stage(0, 0);
    if (nk > 1) load_stage(1, 1);

    for (int kc = 0; kc < nk; kc++) {
        const int buf = kc & 1;
        if (kc + 2 < nk) asm volatile("cp.async.wait_group 1;");
        else             asm volatile("cp.async.wait_group 0;");
        __syncthreads();

        const uint32_t aHb = sbase + buf * STAGEB;
        const uint32_t aLb = aHb + TBYTES;
        const uint32_t bHb = aHb + 2*TBYTES;
        const uint32_t bLb = aHb + 3*TBYTES;

        #pragma unroll
        for (int s = 0; s < 2; s++) {
            const uint32_t koff = (s * 8 + lpair) * 4;
            uint32_t aH[4][4], bH[4][2];
            #pragma unroll
            for (int mt = 0; mt < 4; mt++) {
                uint32_t r = (warp_m * 64 + mt * 16 + lrow) * TPITCH;
                aH[mt][0] = lds32(aHb + r + koff);
                aH[mt][1] = lds32(aHb + r + 8*TPITCH + koff);
                aH[mt][2] = lds32(aHb + r + koff + 16);
                aH[mt][3] = lds32(aHb + r + 8*TPITCH + koff + 16);
            }
            #pragma unroll
            for (int nt = 0; nt < 4; nt++) {
                uint32_t r = (warp_n * 32 + nt * 8 + lrow) * TPITCH;
                bH[nt][0] = lds32(bHb + r + koff);
                bH[nt][1] = lds32(bHb + r + koff + 16);
            }
            #pragma unroll
            for (int mt = 0; mt < 4; mt++)
                #pragma unroll
                for (int nt = 0; nt < 4; nt++)
                    mma16816(acc[mt][nt], aH[mt], bH[nt]);
            // pass 2: Al x Bh
            {
                uint32_t aL[4][4];
                #pragma unroll
                for (int mt = 0; mt < 4; mt++) {
                    uint32_t r = (warp_m * 64 + mt * 16 + lrow) * TPITCH;
                    aL[mt][0] = lds32(aLb + r + koff);
                    aL[mt][1] = lds32(aLb + r + 8*TPITCH + koff);
                    aL[mt][2] = lds32(aLb + r + koff + 16);
                    aL[mt][3] = lds32(aLb + r + 8*TPITCH + koff + 16);
                }
                #pragma unroll
                for (int mt = 0; mt < 4; mt++)
                    #pragma unroll
                    for (int nt = 0; nt < 4; nt++)
                        mma16816(acc[mt][nt], aL[mt], bH[nt]);
            }
            // pass 3: Ah x Bl
            {
                uint32_t bL[4][2];
                #pragma unroll
                for (int nt = 0; nt < 4; nt++) {
                    uint32_t r = (warp_n * 32 + nt * 8 + lrow) * TPITCH;
                    bL[nt][0] = lds32(bLb + r + koff);
                    bL[nt][1] = lds32(bLb + r + koff + 16);
                }
                #pragma unroll
                for (int mt = 0; mt < 4; mt++)
                    #pragma unroll
                    for (int nt = 0; nt < 4; nt++)
                        mma16816(acc[mt][nt], aH[mt], bL[nt]);
            }
        }
        __syncthreads();
        if (kc + 2 < nk) load_stage(buf, kc + 2);
    }

    // ---- epilogue ----
    #pragma unroll
    for (int mt = 0; mt < 4; mt++) {
        #pragma unroll
        for (int nt = 0; nt < 4; nt++) {
            long row = m0 + warp_m * 64 + mt * 16 + lrow;
            int col = n0 + warp_n * 32 + nt * 8 + lpair * 2;
            float b0 = bias[col], b1 = bias[col + 1];
            #pragma unroll
            for (int half = 0; half < 2; half++) {
                long r = row + half * 8;
                float v0 = acc[mt][nt][half*2 + 0] + b0;
                float v1 = acc[mt][nt][half*2 + 1] + b1;
                if (EPI == 0) {
                    *(float2*)(C + r * N + col) = make_float2(v0, v1);
                } else {
                    v0 = v0 / (1.f + expf(-v0));
                    v1 = v1 / (1.f + expf(-v1));
                    bf16 h0, l0, h1, l1;
                    split_bf16(v0, h0, l0);
                    split_bf16(v1, h1, l1);
                    *(bf162*)(CH + r * N + col) = __halves2bfloat162(h0, h1);
                    *(bf162*)(CL + r * N + col) = __halves2bfloat162(l0, l1);
                }
            }
        }
    }
}

// ================= converters =================
__global__ __launch_bounds__(256) void cvt_split(const float* __restrict__ x,
                                                 bf16* __restrict__ oh,
                                                 bf16* __restrict__ ol) {
    long i = ((long)blockIdx.x * 256 + threadIdx.x) * 4;
    float4 v = *(const float4*)(x + i);
    bf16 h0, l0, h1, l1, h2, l2, h3, l3;
    split_bf16(v.x, h0, l0); split_bf16(v.y, h1, l1);
    split_bf16(v.z, h2, l2); split_bf16(v.w, h3, l3);
    *(bf162*)(oh + i)     = __halves2bfloat162(h0, h1);
    *(bf162*)(oh + i + 2) = __halves2bfloat162(h2, h3);
    *(bf162*)(ol + i)     = __halves2bfloat162(l0, l1);
    *(bf162*)(ol + i + 2) = __halves2bfloat162(l2, l3);
}

// transpose [B,E,S] fp32 -> [B,S,E] bf16 hi/lo
__global__ void cvt_T(const float* __restrict__ x, bf16* __restrict__ oh,
                      bf16* __restrict__ ol) {
    __shared__ float t[32][33];
    int sx = blockIdx.x * 32, cy = blockIdx.y * 32, b = blockIdx.z;
    int lx = threadIdx.x;
    for (int r = threadIdx.y; r < 32; r += 8)
        t[r][lx] = x[((long)b * EE + cy + r) * SS + sx + lx];
    __syncthreads();
    for (int r = threadIdx.y; r < 32; r += 8) {
        float v = t[lx][r];
        long o = ((long)b * SS + sx + r) * EE + cy + lx;
        bf16 h, l;
        split_bf16(v, h, l);
        oh[o] = h; ol[o] = l;
    }
}

// GRN1 apply fused with transpose + bf16 split
__global__ void grn1_T(const float* __restrict__ x,
                       const float* __restrict__ sumsq,
                       const float* __restrict__ meangx,
                       const float* __restrict__ gamma,
                       const float* __restrict__ beta,
                       bf16* __restrict__ oh, bf16* __restrict__ ol) {
    __shared__ float t[32][33];
    int sx = blockIdx.x * 32, cy = blockIdx.y * 32, b = blockIdx.z;
    int lx = threadIdx.x;
    for (int r = threadIdx.y; r < 32; r += 8)
        t[r][lx] = x[((long)b * EE + cy + r) * SS + sx + lx];
    __syncthreads();
    int c = cy + lx;
    float nx = sqrtf(sumsq[b*EE + c]) / (meangx[b] + 1e-6f);
    float g1 = 1.f + gamma[c], be = beta[c];
    for (int r = threadIdx.y; r < 32; r += 8) {
        float v = t[lx][r];
        float o = g1 * v * nx + be + v;
        long oi = ((long)b * SS + sx + r) * EE + c;
        bf16 h, l;
        split_bf16(o, h, l);
        oh[oi] = h; ol[oi] = l;
    }
}

// ---------------- small helpers ----------------
__inline__ __device__ void blockReduce2(float& a, float& b) {
    #pragma unroll
    for (int off = 16; off > 0; off >>= 1) {
        a += __shfl_down_sync(0xffffffffu, a, off);
        b += __shfl_down_sync(0xffffffffu, b, off);
    }
    __shared__ float sa[8], sb[8];
    int w = threadIdx.x >> 5, l = threadIdx.x & 31;
    if (l == 0) { sa[w] = a; sb[w] = b; }
    __syncthreads();
    if (w == 0) {
        a = (l < 8) ? sa[l] : 0.f;
        b = (l < 8) ? sb[l] : 0.f;
        #pragma unroll
        for (int off = 4; off > 0; off >>= 1) {
            a += __shfl_down_sync(0xffu, a, off);
            b += __shfl_down_sync(0xffu, b, off);
        }
        if (l == 0) { sa[0] = a; sb[0] = b; }
    }
    __syncthreads();
    a = sa[0]; b = sb[0];
}

__global__ void zero_f(float* __restrict__ p, int n) {
    int i = blockIdx.x * blockDim.x + threadIdx.x;
    if (i < n) p[i] = 0.f;
}

// ---------------- GRN reductions ----------------
__global__ __launch_bounds__(256) void grn_sumsq_cm(const float* __restrict__ x,
                                                    float* __restrict__ sumsq) {
    const float* xr = x + (long)blockIdx.x * SS;
    float acc = 0.f, dummy = 0.f;
    for (int i = threadIdx.x * 4; i < SS; i += 1024) {
        float4 v = *(const float4*)(xr + i);
        acc += v.x*v.x + v.y*v.y + v.z*v.z + v.w*v.w;
    }
    blockReduce2(acc, dummy);
    if (threadIdx.x == 0) sumsq[blockIdx.x] = acc;
}

__global__ __launch_bounds__(256) void grn_mean(const float* __restrict__ sumsq,
                                                float* __restrict__ meangx) {
    int b = blockIdx.x;
    float s = 0.f, dummy = 0.f;
    for (int c = threadIdx.x; c < EE; c += 256) s += sqrtf(sumsq[b*EE + c]);
    blockReduce2(s, dummy);
    if (threadIdx.x == 0) meangx[b] = s / (float)EE;
}

__global__ __launch_bounds__(256) void grn2_sumsq(const float* __restrict__ w,
                                                  float* __restrict__ sumsq) {
    int c = blockIdx.x * 256 + threadIdx.x;
    int b = blockIdx.z;
    long base = ((long)b * SS + (long)blockIdx.y * 256) * EE + c;
    float acc = 0.f;
    #pragma unroll 4
    for (int r = 0; r < 256; r++) {
        float v = w[base + (long)r * EE];
        acc += v * v;
    }
    atomicAdd(&sumsq[b*EE + c], acc);
}

// GRN2 apply, token-major, writes bf16 hi/lo directly
__global__ __launch_bounds__(256) void grn2_apply(const float* __restrict__ x,
                                                  const float* __restrict__ sumsq,
                                                  const float* __restrict__ meangx,
                                                  const float* __restrict__ gamma,
                                                  const float* __restrict__ beta,
                                                  bf16* __restrict__ oh,
                                                  bf16* __restrict__ ol) {
    long i4 = ((long)blockIdx.x * 256 + threadIdx.x) * 4;
    int c0 = (int)(i4 & 1023);
    int b = (int)(i4 >> 22);
    float4 g4 = *(const float4*)(gamma + c0);
    float4 b4 = *(const float4*)(beta + c0);
    float4 s4 = *(const float4*)(sumsq + b*EE + c0);
    float mg = meangx[b] + 1e-6f;
    float4 v = *(const float4*)(x + i4);
    float o0 = (1.f+g4.x) * v.x * (sqrtf(s4.x)/mg) + b4.x + v.x;
    float o1 = (1.f+g4.y) * v.y * (sqrtf(s4.y)/mg) + b4.y + v.y;
    float o2 = (1.f+g4.z) * v.z * (sqrtf(s4.z)/mg) + b4.z + v.z;
    float o3 = (1.f+g4.w) * v.w * (sqrtf(s4.w)/mg) + b4.w + v.w;
    bf16 h0, l0, h1, l1, h2, l2, h3, l3;
    split_bf16(o0, h0, l0); split_bf16(o1, h1, l1);
    split_bf16(o2, h2, l2); split_bf16(o3, h3, l3);
    *(bf162*)(oh + i4)     = __halves2bfloat162(h0, h1);
    *(bf162*)(oh + i4 + 2) = __halves2bfloat162(h2, h3);
    *(bf162*)(ol + i4)     = __halves2bfloat162(l0, l1);
    *(bf162*)(ol + i4 + 2) = __halves2bfloat162(l2, l3);
}

// ---------------- LayerNorm + (elu+1) ----------------
__global__ __launch_bounds__(256) void ln_elu(float* __restrict__ x,
                                              const float* __restrict__ w,
                                              const float* __restrict__ b) {
    float* xr = x + (long)blockIdx.x * EE;
    int tid = threadIdx.x;
    float4 v = *(const float4*)(xr + tid*4);
    float s  = v.x + v.y + v.z + v.w;
    float sq = v.x*v.x + v.y*v.y + v.z*v.z + v.w*v.w;
    blockReduce2(s, sq);
    float mean = s / (float)EE;
    float var = sq / (float)EE - mean*mean;
    float rstd = rsqrtf(var + 1e-5f);
    float4 wv = *(const float4*)(w + tid*4);
    float4 bv = *(const float4*)(b + tid*4);
    float y;
    y = (v.x-mean)*rstd*wv.x + bv.x; v.x = (y > 0.f) ? y + 1.f : expf(y);
    y = (v.y-mean)*rstd*wv.y + bv.y; v.y = (y > 0.f) ? y + 1.f : expf(y);
    y = (v.z-mean)*rstd*wv.z + bv.z; v.z = (y > 0.f) ? y + 1.f : expf(y);
    y = (v.w-mean)*rstd*wv.w + bv.w; v.w = (y > 0.f) ? y + 1.f : expf(y);
    *(float4*)(xr + tid*4) = v;
}

// ---------------- linear attention ----------------
__global__ __launch_bounds__(256) void kvsum_kernel(const float* __restrict__ k,
                                                    const float* __restrict__ v,
                                                    float* __restrict__ kv,
                                                    float* __restrict__ ksum) {
    int bh = blockIdx.x;
    int b = bh >> 4, h = bh & 15;
    int tid = threadIdx.x;
    __shared__ float ks[16][68], vs[16][68];
    int d0 = (tid >> 4) * 4, e0 = (tid & 15) * 4;
    float acc[4][4] = {};
    float accks[4] = {};
    long base = ((long)b * SS + (long)blockIdx.y * 256) * EE + h * DD;
    int ltok = tid >> 4, lc = (tid & 15) * 4;
    for (int t0 = 0; t0 < 256; t0 += 16) {
        *(float4*)&ks[ltok][lc] = *(const float4*)(k + base + (long)(t0+ltok)*EE + lc);
        *(float4*)&vs[ltok][lc] = *(const float4*)(v + base + (long)(t0+ltok)*EE + lc);
        __syncthreads();
        #pragma unroll
        for (int t = 0; t < 16; t++) {
            float a[4], bb[4];
            #pragma unroll
            for (int i = 0; i < 4; i++) a[i] = ks[t][d0+i];
            #pragma unroll
            for (int j = 0; j < 4; j++) bb[j] = vs[t][e0+j];
            #pragma unroll
            for (int i = 0; i < 4; i++)
                #pragma unroll
                for (int j = 0; j < 4; j++) acc[i][j] += a[i]*bb[j];
            if (e0 == 0) {
                #pragma unroll
                for (int i = 0; i < 4; i++) accks[i] += a[i];
            }
        }
        __syncthreads();
    }
    long kvbase = (long)bh * DD * DD;
    #pragma unroll
    for (int i = 0; i < 4; i++)
        #pragma unroll
        for (int j = 0; j < 4; j++)
            atomicAdd(&kv[kvbase + (d0+i)*DD + e0+j], acc[i][j]);
    if (e0 == 0)
        #pragma unroll
        for (int i = 0; i < 4; i++) atomicAdd(&ksum[bh*DD + d0+i], accks[i]);
}

// attn = (q @ kv) / (q . ksum + 1e-8), writes bf16 hi/lo directly
__global__ __launch_bounds__(256) void attn_apply_kernel(const float* __restrict__ q,
                                                         const float* __restrict__ kv,
                                                         const float* __restrict__ ksum,
                                                         bf16* __restrict__ oh,
                                                         bf16* __restrict__ ol) {
    int bh = blockIdx.x, sblk = blockIdx.y;
    int b = bh >> 4, h = bh & 15;
    int tid = threadIdx.x;
    __shared__ float qs[64][68];
    __shared__ float kvs[64][64];
    __shared__ float kss[64];
    long kvbase = (long)bh * DD * DD;
    #pragma unroll
    for (int r = 0; r < 4; r++) {
        int idx = (r*256 + tid) * 4;
        *(float4*)&kvs[idx >> 6][idx & 63] = *(const float4*)(kv + kvbase + idx);
    }
    if (tid < 64) kss[tid] = ksum[bh*DD + tid];
    long qbase = ((long)b * SS + (long)sblk * 64) * EE + h * DD;
    int ltok = tid >> 4, lc = (tid & 15) * 4;
    #pragma unroll
    for (int r = 0; r < 4; r++)
        *(float4*)&qs[ltok + r*16][lc] =
            *(const float4*)(q + qbase + (long)(ltok + r*16)*EE + lc);
    __syncthreads();
    int tok = tid >> 2, e0 = (tid & 3) * 16;
    float num[16] = {};
    float den = 0.f;
    #pragma unroll 8
    for (int d = 0; d < 64; d++) {
        float qd = qs[tok][d];
        den += qd * kss[d];
        #pragma unroll
        for (int j = 0; j < 16; j++) num[j] += qd * kvs[d][e0+j];
    }
    float r = 1.f / (den + 1e-8f);
    long obase = ((long)b * SS + (long)sblk * 64 + tok) * EE + h * DD + e0;
    #pragma unroll
    for (int j = 0; j < 16; j += 2) {
        bf16 h0, l0, h1, l1;
        split_bf16(num[j]   * r, h0, l0);
        split_bf16(num[j+1] * r, h1, l1);
        *(bf162*)(oh + obase + j) = __halves2bfloat162(h0, h1);
        *(bf162*)(ol + obase + j) = __halves2bfloat162(l0, l1);
    }
}

// ---------------- residual / transpose kernels ----------------
__global__ void make_working(const float* __restrict__ qimg,
                             const float* __restrict__ attn_out,
                             const float* __restrict__ ascal,
                             float* __restrict__ work) {
    __shared__ float t[32][33];
    int sx = blockIdx.x * 32, cy = blockIdx.y * 32, b = blockIdx.z;
    int x = threadIdx.x;
    for (int r = threadIdx.y; r < 32; r += 8)
        t[r][x] = qimg[((long)b*EE + cy + r)*SS + sx + x];
    __syncthreads();
    for (int r = threadIdx.y; r < 32; r += 8) {
        long o = ((long)b*SS + sx + r)*EE + cy + x;
        work[o] = t[x][r] + attn_out[o] * ascal[cy + x];
    }
}

__global__ void final_kernel(const float* __restrict__ qimg,
                             const float* __restrict__ work,
                             const float* __restrict__ ffn,
                             const float* __restrict__ fscal,
                             const float* __restrict__ finscal,
                             float* __restrict__ out) {
    __shared__ float t[32][33];
    int sx = blockIdx.x * 32, cy = blockIdx.y * 32, b = blockIdx.z;
    int x = threadIdx.x;
    for (int r = threadIdx.y; r < 32; r += 8) {
        long o = ((long)b*SS + sx + r)*EE + cy + x;
        t[r][x] = (work[o] + ffn[o] * fscal[cy + x]) * finscal[cy + x];
    }
    __syncthreads();
    for (int r = threadIdx.y; r < 32; r += 8) {
        long o = ((long)b*EE + cy + r)*SS + sx + x;
        out[o] = qimg[o] + t[x][r];
    }
}

// ---------------- host launcher ----------------
extern "C" void kernel_launch(void* const* d_in, const int* in_sizes, int n_in,
                              void* d_out, int out_size) {
    const float* qimg   = (const float*)d_in[0];
    const float* kimg   = (const float*)d_in[1];
    const float* vimg   = (const float*)d_in[2];
    const float* grn1_g = (const float*)d_in[3];
    const float* grn1_b = (const float*)d_in[4];
    const float* q_w    = (const float*)d_in[5];
    const float* q_b    = (const float*)d_in[6];
    const float* k_w    = (const float*)d_in[7];
    const float* k_b    = (const float*)d_in[8];
    const float* v_w    = (const float*)d_in[9];
    const float* v_b    = (const float*)d_in[10];
    const float* o_w    = (const float*)d_in[11];
    const float* o_b    = (const float*)d_in[12];
    const float* lnq_w  = (const float*)d_in[13];
    const float* lnq_b  = (const float*)d_in[14];
    const float* lnk_w  = (const float*)d_in[15];
    const float* lnk_b  = (const float*)d_in[16];
    const float* ascal  = (const float*)d_in[17];
    const float* grn2_g = (const float*)d_in[18];
    const float* grn2_b = (const float*)d_in[19];
    const float* w1     = (const float*)d_in[20];
    const float* b1     = (const float*)d_in[21];
    const float* w2     = (const float*)d_in[22];
    const float* b2     = (const float*)d_in[23];
    const float* fscal  = (const float*)d_in[24];
    const float* finscal= (const float*)d_in[25];

    float *adad, *qb, *kb, *vb, *ffno, *work, *kv, *ksum, *sumsq, *meang;
    bf16 *xh, *xl, *wh, *wl, *hh, *hl;
    cudaGetSymbolAddress((void**)&adad, g_adad);
    cudaGetSymbolAddress((void**)&qb,   g_q);
    cudaGetSymbolAddress((void**)&kb,   g_k);
    cudaGetSymbolAddress((void**)&vb,   g_v);
    cudaGetSymbolAddress((void**)&ffno, g_ffno);
    cudaGetSymbolAddress((void**)&work, g_work);
    cudaGetSymbolAddress((void**)&xh,   g_xh);
    cudaGetSymbolAddress((void**)&xl,   g_xl);
    cudaGetSymbolAddress((void**)&wh,   g_wh);
    cudaGetSymbolAddress((void**)&wl,   g_wl);
    cudaGetSymbolAddress((void**)&hh,   g_hh);
    cudaGetSymbolAddress((void**)&hl,   g_hl);
    cudaGetSymbolAddress((void**)&kv,   g_kv);
    cudaGetSymbolAddress((void**)&ksum, g_ksum);
    cudaGetSymbolAddress((void**)&sumsq,g_sumsq);
    cudaGetSymbolAddress((void**)&meang,g_meangx);

    cudaFuncSetAttribute(gemm_hmma<0>, cudaFuncAttributeMaxDynamicSharedMemorySize, GSMEM);
    cudaFuncSetAttribute(gemm_hmma<1>, cudaFuncAttributeMaxDynamicSharedMemorySize, GSMEM);

    const long ES = (long)EE * SS;
    dim3 tgrid(SS/32, EE/32, BB);
    dim3 tblk(32, 8);

    // GRN1 on query image (apply fused with transpose + bf16 split)
    grn_sumsq_cm<<<BB*EE, 256>>>(qimg, sumsq);
    grn_mean<<<BB, 256>>>(sumsq, meang);
    grn1_T<<<tgrid, tblk>>>(qimg, sumsq, meang, grn1_g, grn1_b, xh, xl);

    // Q projection
    cvt_split<<<EE*EE/1024, 256>>>(q_w, wh, wl);
    gemm_hmma<0><<<dim3(EE/128, BNS/128), 256, GSMEM>>>(xh, xl, wh, wl, q_b,
        qb, nullptr, nullptr, BNS, EE, EE);
    // K projection
    cvt_T<<<tgrid, tblk>>>(kimg, xh, xl);
    cvt_split<<<EE*EE/1024, 256>>>(k_w, wh, wl);
    gemm_hmma<0><<<dim3(EE/128, BNS/128), 256, GSMEM>>>(xh, xl, wh, wl, k_b,
        kb, nullptr, nullptr, BNS, EE, EE);
    // V projection
    cvt_T<<<tgrid, tblk>>>(vimg, xh, xl);
    cvt_split<<<EE*EE/1024, 256>>>(v_w, wh, wl);
    gemm_hmma<0><<<dim3(EE/128, BNS/128), 256, GSMEM>>>(xh, xl, wh, wl, v_b,
        vb, nullptr, nullptr, BNS, EE, EE);

    // LayerNorm + elu+1 (in place)
    ln_elu<<<BNS, 256>>>(qb, lnq_w, lnq_b);
    ln_elu<<<BNS, 256>>>(kb, lnk_w, lnk_b);

    // linear attention (output straight to bf16 hi/lo)
    zero_f<<<(BB*HH*DD*DD + 255)/256, 256>>>(kv, BB*HH*DD*DD);
    zero_f<<<(BB*HH*DD + 255)/256, 256>>>(ksum, BB*HH*DD);
    kvsum_kernel<<<dim3(BB*HH, 16), 256>>>(kb, vb, kv, ksum);
    attn_apply_kernel<<<dim3(BB*HH, SS/64), 256>>>(qb, kv, ksum, xh, xl);

    // O projection -> adad (token-major fp32)
    cvt_split<<<EE*EE/1024, 256>>>(o_w, wh, wl);
    gemm_hmma<0><<<dim3(EE/128, BNS/128), 256, GSMEM>>>(xh, xl, wh, wl, o_b,
        adad, nullptr, nullptr, BNS, EE, EE);

    // working = qimg^T + oproj * attn_scalar (token-major)
    make_working<<<tgrid, tblk>>>(qimg, adad, ascal, work);

    // GRN2 on working (apply writes bf16 hi/lo directly)
    zero_f<<<(BB*EE + 255)/256, 256>>>(sumsq, BB*EE);
    grn2_sumsq<<<dim3(EE/256, SS/256, BB), 256>>>(work, sumsq);
    grn_mean<<<BB, 256>>>(sumsq, meang);
    grn2_apply<<<(int)(BB*ES/1024), 256>>>(work, sumsq, meang, grn2_g, grn2_b, xh, xl);

    // FFN1: silu epilogue -> bf16 hi/lo hidden
    cvt_split<<<E4*EE/1024, 256>>>(w1, wh, wl);
    gemm_hmma<1><<<dim3(E4/128, BNS/128), 256, GSMEM>>>(xh, xl, wh, wl, b1,
        nullptr, hh, hl, BNS, E4, EE);

    // FFN2
    cvt_split<<<EE*E4/1024, 256>>>(w2, wh, wl);
    gemm_hmma<0><<<dim3(EE/128, BNS/128), 256, GSMEM>>>(hh, hl, wh, wl, b2,
        ffno, nullptr, nullptr, BNS, EE, E4);

    // final residual (transpose back to channel-major)
    final_kernel<<<tgrid, tblk>>>(qimg, work, ffno, fscal, finscal, (float*)d_out);
}

// round 6
// speedup vs baseline: 1.0959x; 1.0079x over previous
#include <cuda_runtime.h>
#include <cuda_bf16.h>
#include <math.h>
#include <stdint.h>

// Problem constants
#define BB 2
#define EE 1024
#define HH 16
#define DD 64
#define SS 4096            // 64*64 spatial tokens per batch
#define BNS (BB*SS)        // 8192 total tokens
#define E4 (4*EE)          // 4096 ffn hidden

typedef __nv_bfloat16 bf16;
typedef __nv_bfloat162 bf162;

// ---------------- device scratch ----------------
__device__ float g_adad[(long)BNS*EE];     // o-proj out
__device__ float g_q   [(long)BNS*EE];
__device__ float g_k   [(long)BNS*EE];
__device__ float g_v   [(long)BNS*EE];
__device__ float g_ffno[(long)BNS*EE];     // ffn2 out
__device__ float g_work[(long)BNS*EE];
__device__ bf16  g_xh  [(long)BNS*EE];
__device__ bf16  g_xl  [(long)BNS*EE];
__device__ bf16  g_wh  [(long)E4*EE];
__device__ bf16  g_wl  [(long)E4*EE];
__device__ bf16  g_hh  [(long)BNS*E4];
__device__ bf16  g_hl  [(long)BNS*E4];
__device__ float g_kv  [BB*HH*DD*DD];
__device__ float g_ksum[BB*HH*DD];
__device__ float g_sumsq[BB*EE];
__device__ float g_meangx[BB];

// ================= helpers =================
__device__ __forceinline__ uint32_t smem_u32(const void* p) {
    uint32_t a;
    asm("{ .reg .u64 t; cvta.to.shared.u64 t, %1; cvt.u32.u64 %0, t; }" : "=r"(a) : "l"(p));
    return a;
}
__device__ __forceinline__ void cp16(uint32_t dst, const void* src) {
    asm volatile("cp.async.cg.shared.global [%0], [%1], 16;" :: "r"(dst), "l"(src));
}
__device__ __forceinline__ uint32_t lds32(uint32_t a) {
    uint32_t v;
    asm volatile("ld.shared.u32 %0, [%1];" : "=r"(v) : "r"(a));
    return v;
}
__device__ __forceinline__ void mma16816(float* c, const uint32_t* a, const uint32_t* b) {
    asm volatile(
        "mma.sync.aligned.m16n8k16.row.col.f32.bf16.bf16.f32 "
        "{%0,%1,%2,%3}, {%4,%5,%6,%7}, {%8,%9}, {%0,%1,%2,%3};"
        : "+f"(c[0]), "+f"(c[1]), "+f"(c[2]), "+f"(c[3])
        : "r"(a[0]), "r"(a[1]), "r"(a[2]), "r"(a[3]), "r"(b[0]), "r"(b[1]));
}
__device__ __forceinline__ void split_bf16(float v, bf16& h, bf16& l) {
    h = __float2bfloat16(v);
    l = __float2bfloat16(v - __bfloat162float(h));
}

// ================= GEMM: C[M,N] = (Ah+Al)(Wh+Wl)^T + bias (3-pass bf16) =====
// Block 128x128, KT=32, 4 warps (2 M x 2 N), warp tile 64x64, scalar LDS frags.
#define TPITCH 80
#define TBYTES (128*TPITCH)          // 10240
#define STAGEB (4*TBYTES)            // 40960
#define GSMEM  (2*STAGEB)            // 81920

template<int EPI>
__global__ __launch_bounds__(128, 2) void gemm_hmma(
    const bf16* __restrict__ Ah, const bf16* __restrict__ Al,
    const bf16* __restrict__ Wh, const bf16* __restrict__ Wl,
    const float* __restrict__ bias,
    float* __restrict__ C, bf16* __restrict__ CH, bf16* __restrict__ CL,
    int M, int N, int K)
{
    extern __shared__ char sm[];
    const uint32_t sbase = smem_u32(sm);
    const int tid = threadIdx.x;
    const int lane = tid & 31, wid = tid >> 5;
    const int warp_m = wid >> 1, warp_n = wid & 1;
    const int m0 = blockIdx.y * 128, n0 = blockIdx.x * 128;
    const int lrow = lane >> 2, lpair = lane & 3;

    float acc[4][8][4];
    #pragma unroll
    for (int i = 0; i < 4; i++)
        #pragma unroll
        for (int j = 0; j < 8; j++)
            #pragma unroll
            for (int t = 0; t < 4; t++) acc[i][j][t] = 0.f;

    const int nk = K >> 5;

    // stage = Ah | Al | Wh | Wl, each 128 rows x 64B (+16B pad per row)
    auto load_stage = [&](int buf, int kc) {
        const long kq = (long)kc * 32;
        uint32_t sb = sbase + buf * STAGEB;
        #pragma unroll
        for (int i = 0; i < 4; i++) {
            int p = tid + i * 128;
            int row = p >> 2, ch = p & 3;
            long goff = (long)(m0 + row) * K + kq + ch * 8;
            uint32_t d = sb + row * TPITCH + ch * 16;
            cp16(d,            Ah + goff);
            cp16(d + TBYTES,   Al + goff);
            long boff = (long)(n0 + row) * K + kq + ch * 8;
            cp16(d + 2*TBYTES, Wh + boff);
            cp16(d + 3*TBYTES, Wl + boff);
        }
        asm volatile("cp.async.commit_group;");
    };

    load_stage(0, 0);
    if (nk > 1) load_stage(1, 1);

    for (int kc = 0; kc < nk; kc++) {
        const int buf = kc & 1;
        if (kc + 2 < nk) asm volatile("cp.async.wait_group 1;");
        else             asm volatile("cp.async.wait_group 0;");
        __syncthreads();

        const uint32_t aHb = sbase + buf * STAGEB;
        const uint32_t aLb = aHb + TBYTES;
        const uint32_t bHb = aHb + 2*TBYTES;
        const uint32_t bLb = aHb + 3*TBYTES;

        #pragma unroll
        for (int s = 0; s < 2; s++) {
            const uint32_t koff = (s * 8 + lpair) * 4;
            uint32_t aH[4][4], bH[8][2];
            #pragma unroll
            for (int mt = 0; mt < 4; mt++) {
                uint32_t r = (warp_m * 64 + mt * 16 + lrow) * TPITCH;
                aH[mt][0] = lds32(aHb + r + koff);
                aH[mt][1] = lds32(aHb + r + 8*TPITCH + koff);
                aH[mt][2] = lds32(aHb + r + koff + 16);
                aH[mt][3] = lds32(aHb + r + 8*TPITCH + koff + 16);
            }
            #pragma unroll
            for (int nt = 0; nt < 8; nt++) {
                uint32_t r = (warp_n * 64 + nt * 8 + lrow) * TPITCH;
                bH[nt][0] = lds32(bHb + r + koff);
                bH[nt][1] = lds32(bHb + r + koff + 16);
            }
            // pass 1: Ah x Bh
            #pragma unroll
            for (int mt = 0; mt < 4; mt++)
                #pragma unroll
                for (int nt = 0; nt < 8; nt++)
                    mma16816(acc[mt][nt], aH[mt], bH[nt]);
            // pass 2: Al x Bh
            {
                uint32_t aL[4][4];
                #pragma unroll
                for (int mt = 0; mt < 4; mt++) {
                    uint32_t r = (warp_m * 64 + mt * 16 + lrow) * TPITCH;
                    aL[mt][0] = lds32(aLb + r + koff);
                    aL[mt][1] = lds32(aLb + r + 8*TPITCH + koff);
                    aL[mt][2] = lds32(aLb + r + koff + 16);
                    aL[mt][3] = lds32(aLb + r + 8*TPITCH + koff + 16);
                }
                #pragma unroll
                for (int mt = 0; mt < 4; mt++)
                    #pragma unroll
                    for (int nt = 0; nt < 8; nt++)
                        mma16816(acc[mt][nt], aL[mt], bH[nt]);
            }
            // pass 3: Ah x Bl
            {
                uint32_t bL[8][2];
                #pragma unroll
                for (int nt = 0; nt < 8; nt++) {
                    uint32_t r = (warp_n * 64 + nt * 8 + lrow) * TPITCH;
                    bL[nt][0] = lds32(bLb + r + koff);
                    bL[nt][1] = lds32(bLb + r + koff + 16);
                }
                #pragma unroll
                for (int mt = 0; mt < 4; mt++)
                    #pragma unroll
                    for (int nt = 0; nt < 8; nt++)
                        mma16816(acc[mt][nt], aH[mt], bL[nt]);
            }
        }
        __syncthreads();
        if (kc + 2 < nk) load_stage(buf, kc + 2);
    }

    // ---- epilogue ----
    #pragma unroll
    for (int mt = 0; mt < 4; mt++) {
        #pragma unroll
        for (int nt = 0; nt < 8; nt++) {
            long row = m0 + warp_m * 64 + mt * 16 + lrow;
            int col = n0 + warp_n * 64 + nt * 8 + lpair * 2;
            float b0 = bias[col], b1 = bias[col + 1];
            #pragma unroll
            for (int half = 0; half < 2; half++) {
                long r = row + half * 8;
                float v0 = acc[mt][nt][half*2 + 0] + b0;
                float v1 = acc[mt][nt][half*2 + 1] + b1;
                if (EPI == 0) {
                    *(float2*)(C + r * N + col) = make_float2(v0, v1);
                } else {
                    v0 = v0 / (1.f + expf(-v0));
                    v1 = v1 / (1.f + expf(-v1));
                    bf16 h0, l0, h1, l1;
                    split_bf16(v0, h0, l0);
                    split_bf16(v1, h1, l1);
                    *(bf162*)(CH + r * N + col) = __halves2bfloat162(h0, h1);
                    *(bf162*)(CL + r * N + col) = __halves2bfloat162(l0, l1);
                }
            }
        }
    }
}

// ================= converters =================
__global__ __launch_bounds__(256) void cvt_split(const float* __restrict__ x,
                                                 bf16* __restrict__ oh,
                                                 bf16* __restrict__ ol) {
    long i = ((long)blockIdx.x * 256 + threadIdx.x) * 4;
    float4 v = *(const float4*)(x + i);
    bf16 h0, l0, h1, l1, h2, l2, h3, l3;
    split_bf16(v.x, h0, l0); split_bf16(v.y, h1, l1);
    split_bf16(v.z, h2, l2); split_bf16(v.w, h3, l3);
    *(bf162*)(oh + i)     = __halves2bfloat162(h0, h1);
    *(bf162*)(oh + i + 2) = __halves2bfloat162(h2, h3);
    *(bf162*)(ol + i)     = __halves2bfloat162(l0, l1);
    *(bf162*)(ol + i + 2) = __halves2bfloat162(l2, l3);
}

// transpose [B,E,S] fp32 -> [B,S,E] bf16 hi/lo
__global__ void cvt_T(const float* __restrict__ x, bf16* __restrict__ oh,
                      bf16* __restrict__ ol) {
    __shared__ float t[32][33];
    int sx = blockIdx.x * 32, cy = blockIdx.y * 32, b = blockIdx.z;
    int lx = threadIdx.x;
    for (int r = threadIdx.y; r < 32; r += 8)
        t[r][lx] = x[((long)b * EE + cy + r) * SS + sx + lx];
    __syncthreads();
    for (int r = threadIdx.y; r < 32; r += 8) {
        float v = t[lx][r];
        long o = ((long)b * SS + sx + r) * EE + cy + lx;
        bf16 h, l;
        split_bf16(v, h, l);
        oh[o] = h; ol[o] = l;
    }
}

// GRN1 apply fused with transpose + bf16 split
__global__ void grn1_T(const float* __restrict__ x,
                       const float* __restrict__ sumsq,
                       const float* __restrict__ meangx,
                       const float* __restrict__ gamma,
                       const float* __restrict__ beta,
                       bf16* __restrict__ oh, bf16* __restrict__ ol) {
    __shared__ float t[32][33];
    int sx = blockIdx.x * 32, cy = blockIdx.y * 32, b = blockIdx.z;
    int lx = threadIdx.x;
    for (int r = threadIdx.y; r < 32; r += 8)
        t[r][lx] = x[((long)b * EE + cy + r) * SS + sx + lx];
    __syncthreads();
    int c = cy + lx;
    float nx = sqrtf(sumsq[b*EE + c]) / (meangx[b] + 1e-6f);
    float g1 = 1.f + gamma[c], be = beta[c];
    for (int r = threadIdx.y; r < 32; r += 8) {
        float v = t[lx][r];
        float o = g1 * v * nx + be + v;
        long oi = ((long)b * SS + sx + r) * EE + c;
        bf16 h, l;
        split_bf16(o, h, l);
        oh[oi] = h; ol[oi] = l;
    }
}

// ---------------- small helpers ----------------
__inline__ __device__ void blockReduce2(float& a, float& b) {
    #pragma unroll
    for (int off = 16; off > 0; off >>= 1) {
        a += __shfl_down_sync(0xffffffffu, a, off);
        b += __shfl_down_sync(0xffffffffu, b, off);
    }
    __shared__ float sa[8], sb[8];
    int w = threadIdx.x >> 5, l = threadIdx.x & 31;
    if (l == 0) { sa[w] = a; sb[w] = b; }
    __syncthreads();
    if (w == 0) {
        a = (l < 8) ? sa[l] : 0.f;
        b = (l < 8) ? sb[l] : 0.f;
        #pragma unroll
        for (int off = 4; off > 0; off >>= 1) {
            a += __shfl_down_sync(0xffu, a, off);
            b += __shfl_down_sync(0xffu, b, off);
        }
        if (l == 0) { sa[0] = a; sb[0] = b; }
    }
    __syncthreads();
    a = sa[0]; b = sb[0];
}

__global__ void zero_f(float* __restrict__ p, int n) {
    int i = blockIdx.x * blockDim.x + threadIdx.x;
    if (i < n) p[i] = 0.f;
}

// ---------------- GRN reductions ----------------
__global__ __launch_bounds__(256) void grn_sumsq_cm(const float* __restrict__ x,
                                                    float* __restrict__ sumsq) {
    const float* xr = x + (long)blockIdx.x * SS;
    float acc = 0.f, dummy = 0.f;
    for (int i = threadIdx.x * 4; i < SS; i += 1024) {
        float4 v = *(const float4*)(xr + i);
        acc += v.x*v.x + v.y*v.y + v.z*v.z + v.w*v.w;
    }
    blockReduce2(acc, dummy);
    if (threadIdx.x == 0) sumsq[blockIdx.x] = acc;
}

__global__ __launch_bounds__(256) void grn_mean(const float* __restrict__ sumsq,
                                                float* __restrict__ meangx) {
    int b = blockIdx.x;
    float s = 0.f, dummy = 0.f;
    for (int c = threadIdx.x; c < EE; c += 256) s += sqrtf(sumsq[b*EE + c]);
    blockReduce2(s, dummy);
    if (threadIdx.x == 0) meangx[b] = s / (float)EE;
}

__global__ __launch_bounds__(256) void grn2_sumsq(const float* __restrict__ w,
                                                  float* __restrict__ sumsq) {
    int c = blockIdx.x * 256 + threadIdx.x;
    int b = blockIdx.z;
    long base = ((long)b * SS + (long)blockIdx.y * 256) * EE + c;
    float acc = 0.f;
    #pragma unroll 4
    for (int r = 0; r < 256; r++) {
        float v = w[base + (long)r * EE];
        acc += v * v;
    }
    atomicAdd(&sumsq[b*EE + c], acc);
}

// GRN2 apply, token-major, writes bf16 hi/lo directly
__global__ __launch_bounds__(256) void grn2_apply(const float* __restrict__ x,
                                                  const float* __restrict__ sumsq,
                                                  const float* __restrict__ meangx,
                                                  const float* __restrict__ gamma,
                                                  const float* __restrict__ beta,
                                                  bf16* __restrict__ oh,
                                                  bf16* __restrict__ ol) {
    long i4 = ((long)blockIdx.x * 256 + threadIdx.x) * 4;
    int c0 = (int)(i4 & 1023);
    int b = (int)(i4 >> 22);
    float4 g4 = *(const float4*)(gamma + c0);
    float4 b4 = *(const float4*)(beta + c0);
    float4 s4 = *(const float4*)(sumsq + b*EE + c0);
    float mg = meangx[b] + 1e-6f;
    float4 v = *(const float4*)(x + i4);
    float o0 = (1.f+g4.x) * v.x * (sqrtf(s4.x)/mg) + b4.x + v.x;
    float o1 = (1.f+g4.y) * v.y * (sqrtf(s4.y)/mg) + b4.y + v.y;
    float o2 = (1.f+g4.z) * v.z * (sqrtf(s4.z)/mg) + b4.z + v.z;
    float o3 = (1.f+g4.w) * v.w * (sqrtf(s4.w)/mg) + b4.w + v.w;
    bf16 h0, l0, h1, l1, h2, l2, h3, l3;
    split_bf16(o0, h0, l0); split_bf16(o1, h1, l1);
    split_bf16(o2, h2, l2); split_bf16(o3, h3, l3);
    *(bf162*)(oh + i4)     = __halves2bfloat162(h0, h1);
    *(bf162*)(oh + i4 + 2) = __halves2bfloat162(h2, h3);
    *(bf162*)(ol + i4)     = __halves2bfloat162(l0, l1);
    *(bf162*)(ol + i4 + 2) = __halves2bfloat162(l2, l3);
}

// ---------------- LayerNorm + (elu+1) ----------------
__global__ __launch_bounds__(256) void ln_elu(float* __restrict__ x,
                                              const float* __restrict__ w,
                                              const float* __restrict__ b) {
    float* xr = x + (long)blockIdx.x * EE;
    int tid = threadIdx.x;
    float4 v = *(const float4*)(xr + tid*4);
    float s  = v.x + v.y + v.z + v.w;
    float sq = v.x*v.x + v.y*v.y + v.z*v.z + v.w*v.w;
    blockReduce2(s, sq);
    float mean = s / (float)EE;
    float var = sq / (float)EE - mean*mean;
    float rstd = rsqrtf(var + 1e-5f);
    float4 wv = *(const float4*)(w + tid*4);
    float4 bv = *(const float4*)(b + tid*4);
    float y;
    y = (v.x-mean)*rstd*wv.x + bv.x; v.x = (y > 0.f) ? y + 1.f : expf(y);
    y = (v.y-mean)*rstd*wv.y + bv.y; v.y = (y > 0.f) ? y + 1.f : expf(y);
    y = (v.z-mean)*rstd*wv.z + bv.z; v.z = (y > 0.f) ? y + 1.f : expf(y);
    y = (v.w-mean)*rstd*wv.w + bv.w; v.w = (y > 0.f) ? y + 1.f : expf(y);
    *(float4*)(xr + tid*4) = v;
}

// ---------------- linear attention ----------------
__global__ __launch_bounds__(256) void kvsum_kernel(const float* __restrict__ k,
                                                    const float* __restrict__ v,
                                                    float* __restrict__ kv,
                                                    float* __restrict__ ksum) {
    int bh = blockIdx.x;
    int b = bh >> 4, h = bh & 15;
    int tid = threadIdx.x;
    __shared__ float ks[16][68], vs[16][68];
    int d0 = (tid >> 4) * 4, e0 = (tid & 15) * 4;
    float acc[4][4] = {};
    float accks[4] = {};
    long base = ((long)b * SS + (long)blockIdx.y * 256) * EE + h * DD;
    int ltok = tid >> 4, lc = (tid & 15) * 4;
    for (int t0 = 0; t0 < 256; t0 += 16) {
        *(float4*)&ks[ltok][lc] = *(const float4*)(k + base + (long)(t0+ltok)*EE + lc);
        *(float4*)&vs[ltok][lc] = *(const float4*)(v + base + (long)(t0+ltok)*EE + lc);
        __syncthreads();
        #pragma unroll
        for (int t = 0; t < 16; t++) {
            float a[4], bb[4];
            #pragma unroll
            for (int i = 0; i < 4; i++) a[i] = ks[t][d0+i];
            #pragma unroll
            for (int j = 0; j < 4; j++) bb[j] = vs[t][e0+j];
            #pragma unroll
            for (int i = 0; i < 4; i++)
                #pragma unroll
                for (int j = 0; j < 4; j++) acc[i][j] += a[i]*bb[j];
            if (e0 == 0) {
                #pragma unroll
                for (int i = 0; i < 4; i++) accks[i] += a[i];
            }
        }
        __syncthreads();
    }
    long kvbase = (long)bh * DD * DD;
    #pragma unroll
    for (int i = 0; i < 4; i++)
        #pragma unroll
        for (int j = 0; j < 4; j++)
            atomicAdd(&kv[kvbase + (d0+i)*DD + e0+j], acc[i][j]);
    if (e0 == 0)
        #pragma unroll
        for (int i = 0; i < 4; i++) atomicAdd(&ksum[bh*DD + d0+i], accks[i]);
}

// attn = (q @ kv) / (q . ksum + 1e-8), writes bf16 hi/lo directly
__global__ __launch_bounds__(256) void attn_apply_kernel(const float* __restrict__ q,
                                                         const float* __restrict__ kv,
                                                         const float* __restrict__ ksum,
                                                         bf16* __restrict__ oh,
                                                         bf16* __restrict__ ol) {
    int bh = blockIdx.x, sblk = blockIdx.y;
    int b = bh >> 4, h = bh & 15;
    int tid = threadIdx.x;
    __shared__ float qs[64][68];
    __shared__ float kvs[64][64];
    __shared__ float kss[64];
    long kvbase = (long)bh * DD * DD;
    #pragma unroll
    for (int r = 0; r < 4; r++) {
        int idx = (r*256 + tid) * 4;
        *(float4*)&kvs[idx >> 6][idx & 63] = *(const float4*)(kv + kvbase + idx);
    }
    if (tid < 64) kss[tid] = ksum[bh*DD + tid];
    long qbase = ((long)b * SS + (long)sblk * 64) * EE + h * DD;
    int ltok = tid >> 4, lc = (tid & 15) * 4;
    #pragma unroll
    for (int r = 0; r < 4; r++)
        *(float4*)&qs[ltok + r*16][lc] =
            *(const float4*)(q + qbase + (long)(ltok + r*16)*EE + lc);
    __syncthreads();
    int tok = tid >> 2, e0 = (tid & 3) * 16;
    float num[16] = {};
    float den = 0.f;
    #pragma unroll 8
    for (int d = 0; d < 64; d++) {
        float qd = qs[tok][d];
        den += qd * kss[d];
        #pragma unroll
        for (int j = 0; j < 16; j++) num[j] += qd * kvs[d][e0+j];
    }
    float r = 1.f / (den + 1e-8f);
    long obase = ((long)b * SS + (long)sblk * 64 + tok) * EE + h * DD + e0;
    #pragma unroll
    for (int j = 0; j < 16; j += 2) {
        bf16 h0, l0, h1, l1;
        split_bf16(num[j]   * r, h0, l0);
        split_bf16(num[j+1] * r, h1, l1);
        *(bf162*)(oh + obase + j) = __halves2bfloat162(h0, h1);
        *(bf162*)(ol + obase + j) = __halves2bfloat162(l0, l1);
    }
}

// ---------------- residual / transpose kernels ----------------
__global__ void make_working(const float* __restrict__ qimg,
                             const float* __restrict__ attn_out,
                             const float* __restrict__ ascal,
                             float* __restrict__ work) {
    __shared__ float t[32][33];
    int sx = blockIdx.x * 32, cy = blockIdx.y * 32, b = blockIdx.z;
    int x = threadIdx.x;
    for (int r = threadIdx.y; r < 32; r += 8)
        t[r][x] = qimg[((long)b*EE + cy + r)*SS + sx + x];
    __syncthreads();
    for (int r = threadIdx.y; r < 32; r += 8) {
        long o = ((long)b*SS + sx + r)*EE + cy + x;
        work[o] = t[x][r] + attn_out[o] * ascal[cy + x];
    }
}

__global__ void final_kernel(const float* __restrict__ qimg,
                             const float* __restrict__ work,
                             const float* __restrict__ ffn,
                             const float* __restrict__ fscal,
                             const float* __restrict__ finscal,
                             float* __restrict__ out) {
    __shared__ float t[32][33];
    int sx = blockIdx.x * 32, cy = blockIdx.y * 32, b = blockIdx.z;
    int x = threadIdx.x;
    for (int r = threadIdx.y; r < 32; r += 8) {
        long o = ((long)b*SS + sx + r)*EE + cy + x;
        t[r][x] = (work[o] + ffn[o] * fscal[cy + x]) * finscal[cy + x];
    }
    __syncthreads();
    for (int r = threadIdx.y; r < 32; r += 8) {
        long o = ((long)b*EE + cy + r)*SS + sx + x;
        out[o] = qimg[o] + t[x][r];
    }
}

// ---------------- host launcher ----------------
extern "C" void kernel_launch(void* const* d_in, const int* in_sizes, int n_in,
                              void* d_out, int out_size) {
    const float* qimg   = (const float*)d_in[0];
    const float* kimg   = (const float*)d_in[1];
    const float* vimg   = (const float*)d_in[2];
    const float* grn1_g = (const float*)d_in[3];
    const float* grn1_b = (const float*)d_in[4];
    const float* q_w    = (const float*)d_in[5];
    const float* q_b    = (const float*)d_in[6];
    const float* k_w    = (const float*)d_in[7];
    const float* k_b    = (const float*)d_in[8];
    const float* v_w    = (const float*)d_in[9];
    const float* v_b    = (const float*)d_in[10];
    const float* o_w    = (const float*)d_in[11];
    const float* o_b    = (const float*)d_in[12];
    const float* lnq_w  = (const float*)d_in[13];
    const float* lnq_b  = (const float*)d_in[14];
    const float* lnk_w  = (const float*)d_in[15];
    const float* lnk_b  = (const float*)d_in[16];
    const float* ascal  = (const float*)d_in[17];
    const float* grn2_g = (const float*)d_in[18];
    const float* grn2_b = (const float*)d_in[19];
    const float* w1     = (const float*)d_in[20];
    const float* b1     = (const float*)d_in[21];
    const float* w2     = (const float*)d_in[22];
    const float* b2     = (const float*)d_in[23];
    const float* fscal  = (const float*)d_in[24];
    const float* finscal= (const float*)d_in[25];

    float *adad, *qb, *kb, *vb, *ffno, *work, *kv, *ksum, *sumsq, *meang;
    bf16 *xh, *xl, *wh, *wl, *hh, *hl;
    cudaGetSymbolAddress((void**)&adad, g_adad);
    cudaGetSymbolAddress((void**)&qb,   g_q);
    cudaGetSymbolAddress((void**)&kb,   g_k);
    cudaGetSymbolAddress((void**)&vb,   g_v);
    cudaGetSymbolAddress((void**)&ffno, g_ffno);
    cudaGetSymbolAddress((void**)&work, g_work);
    cudaGetSymbolAddress((void**)&xh,   g_xh);
    cudaGetSymbolAddress((void**)&xl,   g_xl);
    cudaGetSymbolAddress((void**)&wh,   g_wh);
    cudaGetSymbolAddress((void**)&wl,   g_wl);
    cudaGetSymbolAddress((void**)&hh,   g_hh);
    cudaGetSymbolAddress((void**)&hl,   g_hl);
    cudaGetSymbolAddress((void**)&kv,   g_kv);
    cudaGetSymbolAddress((void**)&ksum, g_ksum);
    cudaGetSymbolAddress((void**)&sumsq,g_sumsq);
    cudaGetSymbolAddress((void**)&meang,g_meangx);

    cudaFuncSetAttribute(gemm_hmma<0>, cudaFuncAttributeMaxDynamicSharedMemorySize, GSMEM);
    cudaFuncSetAttribute(gemm_hmma<1>, cudaFuncAttributeMaxDynamicSharedMemorySize, GSMEM);

    const long ES = (long)EE * SS;
    dim3 tgrid(SS/32, EE/32, BB);
    dim3 tblk(32, 8);

    // GRN1 on query image (apply fused with transpose + bf16 split)
    grn_sumsq_cm<<<BB*EE, 256>>>(qimg, sumsq);
    grn_mean<<<BB, 256>>>(sumsq, meang);
    grn1_T<<<tgrid, tblk>>>(qimg, sumsq, meang, grn1_g, grn1_b, xh, xl);

    // Q projection
    cvt_split<<<EE*EE/1024, 256>>>(q_w, wh, wl);
    gemm_hmma<0><<<dim3(EE/128, BNS/128), 128, GSMEM>>>(xh, xl, wh, wl, q_b,
        qb, nullptr, nullptr, BNS, EE, EE);
    // K projection
    cvt_T<<<tgrid, tblk>>>(kimg, xh, xl);
    cvt_split<<<EE*EE/1024, 256>>>(k_w, wh, wl);
    gemm_hmma<0><<<dim3(EE/128, BNS/128), 128, GSMEM>>>(xh, xl, wh, wl, k_b,
        kb, nullptr, nullptr, BNS, EE, EE);
    // V projection
    cvt_T<<<tgrid, tblk>>>(vimg, xh, xl);
    cvt_split<<<EE*EE/1024, 256>>>(v_w, wh, wl);
    gemm_hmma<0><<<dim3(EE/128, BNS/128), 128, GSMEM>>>(xh, xl, wh, wl, v_b,
        vb, nullptr, nullptr, BNS, EE, EE);

    // LayerNorm + elu+1 (in place)
    ln_elu<<<BNS, 256>>>(qb, lnq_w, lnq_b);
    ln_elu<<<BNS, 256>>>(kb, lnk_w, lnk_b);

    // linear attention (output straight to bf16 hi/lo)
    zero_f<<<(BB*HH*DD*DD + 255)/256, 256>>>(kv, BB*HH*DD*DD);
    zero_f<<<(BB*HH*DD + 255)/256, 256>>>(ksum, BB*HH*DD);
    kvsum_kernel<<<dim3(BB*HH, 16), 256>>>(kb, vb, kv, ksum);
    attn_apply_kernel<<<dim3(BB*HH, SS/64), 256>>>(qb, kv, ksum, xh, xl);

    // O projection -> adad (token-major fp32)
    cvt_split<<<EE*EE/1024, 256>>>(o_w, wh, wl);
    gemm_hmma<0><<<dim3(EE/128, BNS/128), 128, GSMEM>>>(xh, xl, wh, wl, o_b,
        adad, nullptr, nullptr, BNS, EE, EE);

    // working = qimg^T + oproj * attn_scalar (token-major)
    make_working<<<tgrid, tblk>>>(qimg, adad, ascal, work);

    // GRN2 on working (apply writes bf16 hi/lo directly)
    zero_f<<<(BB*EE + 255)/256, 256>>>(sumsq, BB*EE);
    grn2_sumsq<<<dim3(EE/256, SS/256, BB), 256>>>(work, sumsq);
    grn_mean<<<BB, 256>>>(sumsq, meang);
    grn2_apply<<<(int)(BB*ES/1024), 256>>>(work, sumsq, meang, grn2_g, grn2_b, xh, xl);

    // FFN1: silu epilogue -> bf16 hi/lo hidden
    cvt_split<<<E4*EE/1024, 256>>>(w1, wh, wl);
    gemm_hmma<1><<<dim3(E4/128, BNS/128), 128, GSMEM>>>(xh, xl, wh, wl, b1,
        nullptr, hh, hl, BNS, E4, EE);

    // FFN2
    cvt_split<<<EE*E4/1024, 256>>>(w2, wh, wl);
    gemm_hmma<0><<<dim3(EE/128, BNS/128), 128, GSMEM>>>(hh, hl, wh, wl, b2,
        ffno, nullptr, nullptr, BNS, EE, E4);

    // final residual (transpose back to channel-major)
    final_kernel<<<tgrid, tblk>>>(qimg, work, ffno, fscal, finscal, (float*)d_out);
}

// round 7
// speedup vs baseline: 2.1066x; 1.9223x over previous
#include <cuda_runtime.h>
#include <cuda_fp16.h>
#include <math.h>
#include <stdint.h>

// Problem constants
#define BB 2
#define EE 1024
#define HH 16
#define DD 64
#define SS 4096            // 64*64 spatial tokens per batch
#define BNS (BB*SS)        // 8192 total tokens
#define E4 (4*EE)          // 4096 ffn hidden

typedef __half h16;
typedef __half2 h162;

// ---------------- device scratch ----------------
__device__ float g_adad[(long)BNS*EE];     // o-proj out
__device__ float g_q   [(long)BNS*EE];
__device__ float g_k   [(long)BNS*EE];
__device__ float g_v   [(long)BNS*EE];
__device__ float g_ffno[(long)BNS*EE];     // ffn2 out
__device__ float g_work[(long)BNS*EE];
__device__ h16   g_x   [(long)BNS*EE];     // fp16 activations
__device__ h16   g_w   [(long)E4*EE];      // fp16 weights (max 4096x1024)
__device__ h16   g_h   [(long)BNS*E4];     // fp16 ffn hidden
__device__ float g_kv  [BB*HH*DD*DD];
__device__ float g_ksum[BB*HH*DD];
__device__ float g_sumsq[BB*EE];
__device__ float g_meangx[BB];

// ================= helpers =================
__device__ __forceinline__ uint32_t smem_u32(const void* p) {
    uint32_t a;
    asm("{ .reg .u64 t; cvta.to.shared.u64 t, %1; cvt.u32.u64 %0, t; }" : "=r"(a) : "l"(p));
    return a;
}
__device__ __forceinline__ void cp16(uint32_t dst, const void* src) {
    asm volatile("cp.async.cg.shared.global [%0], [%1], 16;" :: "r"(dst), "l"(src));
}
__device__ __forceinline__ uint32_t lds32(uint32_t a) {
    uint32_t v;
    asm volatile("ld.shared.u32 %0, [%1];" : "=r"(v) : "r"(a));
    return v;
}
__device__ __forceinline__ void mma16816(float* c, const uint32_t* a, const uint32_t* b) {
    asm volatile(
        "mma.sync.aligned.m16n8k16.row.col.f32.f16.f16.f32 "
        "{%0,%1,%2,%3}, {%4,%5,%6,%7}, {%8,%9}, {%0,%1,%2,%3};"
        : "+f"(c[0]), "+f"(c[1]), "+f"(c[2]), "+f"(c[3])
        : "r"(a[0]), "r"(a[1]), "r"(a[2]), "r"(a[3]), "r"(b[0]), "r"(b[1]));
}

// ================= GEMM: C[M,N] = A W^T + bias (fp16 single-pass) =====
// Block 128x128, KT=32, 4 warps (2 M x 2 N), warp tile 64x64.
// 3-stage cp.async pipeline; smem stage = A(128x64B) + B(128x64B), pitch 80B.
#define TPITCH 80
#define TBYTES (128*TPITCH)          // 10240
#define STAGEB (2*TBYTES)            // 20480
#define NSTAGE 3
#define GSMEM  (NSTAGE*STAGEB)       // 61440

template<int EPI>
__global__ __launch_bounds__(128, 2) void gemm_hmma(
    const h16* __restrict__ A, const h16* __restrict__ W,
    const float* __restrict__ bias,
    float* __restrict__ C, h16* __restrict__ CH,
    int M, int N, int K)
{
    extern __shared__ char sm[];
    const uint32_t sbase = smem_u32(sm);
    const int tid = threadIdx.x;
    const int lane = tid & 31, wid = tid >> 5;
    const int warp_m = wid >> 1, warp_n = wid & 1;
    const int m0 = blockIdx.y * 128, n0 = blockIdx.x * 128;
    const int lrow = lane >> 2, lpair = lane & 3;

    float acc[4][8][4];
    #pragma unroll
    for (int i = 0; i < 4; i++)
        #pragma unroll
        for (int j = 0; j < 8; j++)
            #pragma unroll
            for (int t = 0; t < 4; t++) acc[i][j][t] = 0.f;

    const int nk = K >> 5;          // always >= 32 here

    auto load_stage = [&](int buf, int kc) {
        const long kq = (long)kc * 32;
        uint32_t sb = sbase + buf * STAGEB;
        #pragma unroll
        for (int i = 0; i < 4; i++) {
            int p = tid + i * 128;
            int row = p >> 2, ch = p & 3;
            uint32_t d = sb + row * TPITCH + ch * 16;
            cp16(d,          A + (long)(m0 + row) * K + kq + ch * 8);
            cp16(d + TBYTES, W + (long)(n0 + row) * K + kq + ch * 8);
        }
        asm volatile("cp.async.commit_group;");
    };

    load_stage(0, 0);
    load_stage(1, 1);
    load_stage(2, 2);

    for (int kc = 0; kc < nk; kc++) {
        const int buf = kc % 3;
        const int ahead = nk - 1 - kc;
        if (ahead >= 2)      asm volatile("cp.async.wait_group 2;");
        else if (ahead == 1) asm volatile("cp.async.wait_group 1;");
        else                 asm volatile("cp.async.wait_group 0;");
        __syncthreads();

        const uint32_t aB = sbase + buf * STAGEB;
        const uint32_t bB = aB + TBYTES;

        #pragma unroll
        for (int s = 0; s < 2; s++) {
            const uint32_t koff = (s * 8 + lpair) * 4;
            uint32_t aF[4][4], bF[8][2];
            #pragma unroll
            for (int mt = 0; mt < 4; mt++) {
                uint32_t r = (warp_m * 64 + mt * 16 + lrow) * TPITCH;
                aF[mt][0] = lds32(aB + r + koff);
                aF[mt][1] = lds32(aB + r + 8*TPITCH + koff);
                aF[mt][2] = lds32(aB + r + koff + 16);
                aF[mt][3] = lds32(aB + r + 8*TPITCH + koff + 16);
            }
            #pragma unroll
            for (int nt = 0; nt < 8; nt++) {
                uint32_t r = (warp_n * 64 + nt * 8 + lrow) * TPITCH;
                bF[nt][0] = lds32(bB + r + koff);
                bF[nt][1] = lds32(bB + r + koff + 16);
            }
            #pragma unroll
            for (int mt = 0; mt < 4; mt++)
                #pragma unroll
                for (int nt = 0; nt < 8; nt++)
                    mma16816(acc[mt][nt], aF[mt], bF[nt]);
        }
        __syncthreads();
        if (kc + 3 < nk) load_stage(buf, kc + 3);
    }

    // ---- epilogue ----
    #pragma unroll
    for (int mt = 0; mt < 4; mt++) {
        #pragma unroll
        for (int nt = 0; nt < 8; nt++) {
            long row = m0 + warp_m * 64 + mt * 16 + lrow;
            int col = n0 + warp_n * 64 + nt * 8 + lpair * 2;
            float b0 = bias[col], b1 = bias[col + 1];
            #pragma unroll
            for (int half = 0; half < 2; half++) {
                long r = row + half * 8;
                float v0 = acc[mt][nt][half*2 + 0] + b0;
                float v1 = acc[mt][nt][half*2 + 1] + b1;
                if (EPI == 0) {
                    *(float2*)(C + r * N + col) = make_float2(v0, v1);
                } else {
                    v0 = v0 / (1.f + expf(-v0));
                    v1 = v1 / (1.f + expf(-v1));
                    *(h162*)(CH + r * N + col) =
                        __floats2half2_rn(v0, v1);
                }
            }
        }
    }
}

// ================= converters =================
__global__ __launch_bounds__(256) void cvt_h(const float* __restrict__ x,
                                             h16* __restrict__ o) {
    long i = ((long)blockIdx.x * 256 + threadIdx.x) * 4;
    float4 v = *(const float4*)(x + i);
    *(h162*)(o + i)     = __floats2half2_rn(v.x, v.y);
    *(h162*)(o + i + 2) = __floats2half2_rn(v.z, v.w);
}

// transpose [B,E,S] fp32 -> [B,S,E] fp16
__global__ void cvt_T(const float* __restrict__ x, h16* __restrict__ o) {
    __shared__ float t[32][33];
    int sx = blockIdx.x * 32, cy = blockIdx.y * 32, b = blockIdx.z;
    int lx = threadIdx.x;
    for (int r = threadIdx.y; r < 32; r += 8)
        t[r][lx] = x[((long)b * EE + cy + r) * SS + sx + lx];
    __syncthreads();
    for (int r = threadIdx.y; r < 32; r += 8) {
        long oi = ((long)b * SS + sx + r) * EE + cy + lx;
        o[oi] = __float2half(t[lx][r]);
    }
}

// GRN1 apply fused with transpose + fp16 convert
__global__ void grn1_T(const float* __restrict__ x,
                       const float* __restrict__ sumsq,
                       const float* __restrict__ meangx,
                       const float* __restrict__ gamma,
                       const float* __restrict__ beta,
                       h16* __restrict__ o) {
    __shared__ float t[32][33];
    int sx = blockIdx.x * 32, cy = blockIdx.y * 32, b = blockIdx.z;
    int lx = threadIdx.x;
    for (int r = threadIdx.y; r < 32; r += 8)
        t[r][lx] = x[((long)b * EE + cy + r) * SS + sx + lx];
    __syncthreads();
    int c = cy + lx;
    float nx = sqrtf(sumsq[b*EE + c]) / (meangx[b] + 1e-6f);
    float g1 = 1.f + gamma[c], be = beta[c];
    for (int r = threadIdx.y; r < 32; r += 8) {
        float v = t[lx][r];
        long oi = ((long)b * SS + sx + r) * EE + c;
        o[oi] = __float2half(g1 * v * nx + be + v);
    }
}

// ---------------- small helpers ----------------
__inline__ __device__ void blockReduce2(float& a, float& b) {
    #pragma unroll
    for (int off = 16; off > 0; off >>= 1) {
        a += __shfl_down_sync(0xffffffffu, a, off);
        b += __shfl_down_sync(0xffffffffu, b, off);
    }
    __shared__ float sa[8], sb[8];
    int w = threadIdx.x >> 5, l = threadIdx.x & 31;
    if (l == 0) { sa[w] = a; sb[w] = b; }
    __syncthreads();
    if (w == 0) {
        a = (l < 8) ? sa[l] : 0.f;
        b = (l < 8) ? sb[l] : 0.f;
        #pragma unroll
        for (int off = 4; off > 0; off >>= 1) {
            a += __shfl_down_sync(0xffu, a, off);
            b += __shfl_down_sync(0xffu, b, off);
        }
        if (l == 0) { sa[0] = a; sb[0] = b; }
    }
    __syncthreads();
    a = sa[0]; b = sb[0];
}

__global__ void zero_f(float* __restrict__ p, int n) {
    int i = blockIdx.x * blockDim.x + threadIdx.x;
    if (i < n) p[i] = 0.f;
}

// ---------------- GRN reductions ----------------
__global__ __launch_bounds__(256) void grn_sumsq_cm(const float* __restrict__ x,
                                                    float* __restrict__ sumsq) {
    const float* xr = x + (long)blockIdx.x * SS;
    float acc = 0.f, dummy = 0.f;
    for (int i = threadIdx.x * 4; i < SS; i += 1024) {
        float4 v = *(const float4*)(xr + i);
        acc += v.x*v.x + v.y*v.y + v.z*v.z + v.w*v.w;
    }
    blockReduce2(acc, dummy);
    if (threadIdx.x == 0) sumsq[blockIdx.x] = acc;
}

__global__ __launch_bounds__(256) void grn_mean(const float* __restrict__ sumsq,
                                                float* __restrict__ meangx) {
    int b = blockIdx.x;
    float s = 0.f, dummy = 0.f;
    for (int c = threadIdx.x; c < EE; c += 256) s += sqrtf(sumsq[b*EE + c]);
    blockReduce2(s, dummy);
    if (threadIdx.x == 0) meangx[b] = s / (float)EE;
}

__global__ __launch_bounds__(256) void grn2_sumsq(const float* __restrict__ w,
                                                  float* __restrict__ sumsq) {
    int c = blockIdx.x * 256 + threadIdx.x;
    int b = blockIdx.z;
    long base = ((long)b * SS + (long)blockIdx.y * 256) * EE + c;
    float acc = 0.f;
    #pragma unroll 4
    for (int r = 0; r < 256; r++) {
        float v = w[base + (long)r * EE];
        acc += v * v;
    }
    atomicAdd(&sumsq[b*EE + c], acc);
}

// GRN2 apply, token-major, writes fp16 directly
__global__ __launch_bounds__(256) void grn2_apply(const float* __restrict__ x,
                                                  const float* __restrict__ sumsq,
                                                  const float* __restrict__ meangx,
                                                  const float* __restrict__ gamma,
                                                  const float* __restrict__ beta,
                                                  h16* __restrict__ o) {
    long i4 = ((long)blockIdx.x * 256 + threadIdx.x) * 4;
    int c0 = (int)(i4 & 1023);
    int b = (int)(i4 >> 22);
    float4 g4 = *(const float4*)(gamma + c0);
    float4 b4 = *(const float4*)(beta + c0);
    float4 s4 = *(const float4*)(sumsq + b*EE + c0);
    float mg = meangx[b] + 1e-6f;
    float4 v = *(const float4*)(x + i4);
    float o0 = (1.f+g4.x) * v.x * (sqrtf(s4.x)/mg) + b4.x + v.x;
    float o1 = (1.f+g4.y) * v.y * (sqrtf(s4.y)/mg) + b4.y + v.y;
    float o2 = (1.f+g4.z) * v.z * (sqrtf(s4.z)/mg) + b4.z + v.z;
    float o3 = (1.f+g4.w) * v.w * (sqrtf(s4.w)/mg) + b4.w + v.w;
    *(h162*)(o + i4)     = __floats2half2_rn(o0, o1);
    *(h162*)(o + i4 + 2) = __floats2half2_rn(o2, o3);
}

// ---------------- LayerNorm + (elu+1) ----------------
__global__ __launch_bounds__(256) void ln_elu(float* __restrict__ x,
                                              const float* __restrict__ w,
                                              const float* __restrict__ b) {
    float* xr = x + (long)blockIdx.x * EE;
    int tid = threadIdx.x;
    float4 v = *(const float4*)(xr + tid*4);
    float s  = v.x + v.y + v.z + v.w;
    float sq = v.x*v.x + v.y*v.y + v.z*v.z + v.w*v.w;
    blockReduce2(s, sq);
    float mean = s / (float)EE;
    float var = sq / (float)EE - mean*mean;
    float rstd = rsqrtf(var + 1e-5f);
    float4 wv = *(const float4*)(w + tid*4);
    float4 bv = *(const float4*)(b + tid*4);
    float y;
    y = (v.x-mean)*rstd*wv.x + bv.x; v.x = (y > 0.f) ? y + 1.f : expf(y);
    y = (v.y-mean)*rstd*wv.y + bv.y; v.y = (y > 0.f) ? y + 1.f : expf(y);
    y = (v.z-mean)*rstd*wv.z + bv.z; v.z = (y > 0.f) ? y + 1.f : expf(y);
    y = (v.w-mean)*rstd*wv.w + bv.w; v.w = (y > 0.f) ? y + 1.f : expf(y);
    *(float4*)(xr + tid*4) = v;
}

// ---------------- linear attention ----------------
__global__ __launch_bounds__(256) void kvsum_kernel(const float* __restrict__ k,
                                                    const float* __restrict__ v,
                                                    float* __restrict__ kv,
                                                    float* __restrict__ ksum) {
    int bh = blockIdx.x;
    int b = bh >> 4, h = bh & 15;
    int tid = threadIdx.x;
    __shared__ float ks[16][68], vs[16][68];
    int d0 = (tid >> 4) * 4, e0 = (tid & 15) * 4;
    float acc[4][4] = {};
    float accks[4] = {};
    long base = ((long)b * SS + (long)blockIdx.y * 256) * EE + h * DD;
    int ltok = tid >> 4, lc = (tid & 15) * 4;
    for (int t0 = 0; t0 < 256; t0 += 16) {
        *(float4*)&ks[ltok][lc] = *(const float4*)(k + base + (long)(t0+ltok)*EE + lc);
        *(float4*)&vs[ltok][lc] = *(const float4*)(v + base + (long)(t0+ltok)*EE + lc);
        __syncthreads();
        #pragma unroll
        for (int t = 0; t < 16; t++) {
            float a[4], bb[4];
            #pragma unroll
            for (int i = 0; i < 4; i++) a[i] = ks[t][d0+i];
            #pragma unroll
            for (int j = 0; j < 4; j++) bb[j] = vs[t][e0+j];
            #pragma unroll
            for (int i = 0; i < 4; i++)
                #pragma unroll
                for (int j = 0; j < 4; j++) acc[i][j] += a[i]*bb[j];
            if (e0 == 0) {
                #pragma unroll
                for (int i = 0; i < 4; i++) accks[i] += a[i];
            }
        }
        __syncthreads();
    }
    long kvbase = (long)bh * DD * DD;
    #pragma unroll
    for (int i = 0; i < 4; i++)
        #pragma unroll
        for (int j = 0; j < 4; j++)
            atomicAdd(&kv[kvbase + (d0+i)*DD + e0+j], acc[i][j]);
    if (e0 == 0)
        #pragma unroll
        for (int i = 0; i < 4; i++) atomicAdd(&ksum[bh*DD + d0+i], accks[i]);
}

// attn = (q @ kv) / (q . ksum + 1e-8), writes fp16 directly
__global__ __launch_bounds__(256) void attn_apply_kernel(const float* __restrict__ q,
                                                         const float* __restrict__ kv,
                                                         const float* __restrict__ ksum,
                                                         h16* __restrict__ o) {
    int bh = blockIdx.x, sblk = blockIdx.y;
    int b = bh >> 4, h = bh & 15;
    int tid = threadIdx.x;
    __shared__ float qs[64][68];
    __shared__ float kvs[64][64];
    __shared__ float kss[64];
    long kvbase = (long)bh * DD * DD;
    #pragma unroll
    for (int r = 0; r < 4; r++) {
        int idx = (r*256 + tid) * 4;
        *(float4*)&kvs[idx >> 6][idx & 63] = *(const float4*)(kv + kvbase + idx);
    }
    if (tid < 64) kss[tid] = ksum[bh*DD + tid];
    long qbase = ((long)b * SS + (long)sblk * 64) * EE + h * DD;
    int ltok = tid >> 4, lc = (tid & 15) * 4;
    #pragma unroll
    for (int r = 0; r < 4; r++)
        *(float4*)&qs[ltok + r*16][lc] =
            *(const float4*)(q + qbase + (long)(ltok + r*16)*EE + lc);
    __syncthreads();
    int tok = tid >> 2, e0 = (tid & 3) * 16;
    float num[16] = {};
    float den = 0.f;
    #pragma unroll 8
    for (int d = 0; d < 64; d++) {
        float qd = qs[tok][d];
        den += qd * kss[d];
        #pragma unroll
        for (int j = 0; j < 16; j++) num[j] += qd * kvs[d][e0+j];
    }
    float r = 1.f / (den + 1e-8f);
    long obase = ((long)b * SS + (long)sblk * 64 + tok) * EE + h * DD + e0;
    #pragma unroll
    for (int j = 0; j < 16; j += 2)
        *(h162*)(o + obase + j) = __floats2half2_rn(num[j] * r, num[j+1] * r);
}

// ---------------- residual / transpose kernels ----------------
__global__ void make_working(const float* __restrict__ qimg,
                             const float* __restrict__ attn_out,
                             const float* __restrict__ ascal,
                             float* __restrict__ work) {
    __shared__ float t[32][33];
    int sx = blockIdx.x * 32, cy = blockIdx.y * 32, b = blockIdx.z;
    int x = threadIdx.x;
    for (int r = threadIdx.y; r < 32; r += 8)
        t[r][x] = qimg[((long)b*EE + cy + r)*SS + sx + x];
    __syncthreads();
    for (int r = threadIdx.y; r < 32; r += 8) {
        long o = ((long)b*SS + sx + r)*EE + cy + x;
        work[o] = t[x][r] + attn_out[o] * ascal[cy + x];
    }
}

__global__ void final_kernel(const float* __restrict__ qimg,
                             const float* __restrict__ work,
                             const float* __restrict__ ffn,
                             const float* __restrict__ fscal,
                             const float* __restrict__ finscal,
                             float* __restrict__ out) {
    __shared__ float t[32][33];
    int sx = blockIdx.x * 32, cy = blockIdx.y * 32, b = blockIdx.z;
    int x = threadIdx.x;
    for (int r = threadIdx.y; r < 32; r += 8) {
        long o = ((long)b*SS + sx + r)*EE + cy + x;
        t[r][x] = (work[o] + ffn[o] * fscal[cy + x]) * finscal[cy + x];
    }
    __syncthreads();
    for (int r = threadIdx.y; r < 32; r += 8) {
        long o = ((long)b*EE + cy + r)*SS + sx + x;
        out[o] = qimg[o] + t[x][r];
    }
}

// ---------------- host launcher ----------------
extern "C" void kernel_launch(void* const* d_in, const int* in_sizes, int n_in,
                              void* d_out, int out_size) {
    const float* qimg   = (const float*)d_in[0];
    const float* kimg   = (const float*)d_in[1];
    const float* vimg   = (const float*)d_in[2];
    const float* grn1_g = (const float*)d_in[3];
    const float* grn1_b = (const float*)d_in[4];
    const float* q_w    = (const float*)d_in[5];
    const float* q_b    = (const float*)d_in[6];
    const float* k_w    = (const float*)d_in[7];
    const float* k_b    = (const float*)d_in[8];
    const float* v_w    = (const float*)d_in[9];
    const float* v_b    = (const float*)d_in[10];
    const float* o_w    = (const float*)d_in[11];
    const float* o_b    = (const float*)d_in[12];
    const float* lnq_w  = (const float*)d_in[13];
    const float* lnq_b  = (const float*)d_in[14];
    const float* lnk_w  = (const float*)d_in[15];
    const float* lnk_b  = (const float*)d_in[16];
    const float* ascal  = (const float*)d_in[17];
    const float* grn2_g = (const float*)d_in[18];
    const float* grn2_b = (const float*)d_in[19];
    const float* w1     = (const float*)d_in[20];
    const float* b1     = (const float*)d_in[21];
    const float* w2     = (const float*)d_in[22];
    const float* b2     = (const float*)d_in[23];
    const float* fscal  = (const float*)d_in[24];
    const float* finscal= (const float*)d_in[25];

    float *adad, *qb, *kb, *vb, *ffno, *work, *kv, *ksum, *sumsq, *meang;
    h16 *xh, *wh, *hh;
    cudaGetSymbolAddress((void**)&adad, g_adad);
    cudaGetSymbolAddress((void**)&qb,   g_q);
    cudaGetSymbolAddress((void**)&kb,   g_k);
    cudaGetSymbolAddress((void**)&vb,   g_v);
    cudaGetSymbolAddress((void**)&ffno, g_ffno);
    cudaGetSymbolAddress((void**)&work, g_work);
    cudaGetSymbolAddress((void**)&xh,   g_x);
    cudaGetSymbolAddress((void**)&wh,   g_w);
    cudaGetSymbolAddress((void**)&hh,   g_h);
    cudaGetSymbolAddress((void**)&kv,   g_kv);
    cudaGetSymbolAddress((void**)&ksum, g_ksum);
    cudaGetSymbolAddress((void**)&sumsq,g_sumsq);
    cudaGetSymbolAddress((void**)&meang,g_meangx);

    cudaFuncSetAttribute(gemm_hmma<0>, cudaFuncAttributeMaxDynamicSharedMemorySize, GSMEM);
    cudaFuncSetAttribute(gemm_hmma<1>, cudaFuncAttributeMaxDynamicSharedMemorySize, GSMEM);

    const long ES = (long)EE * SS;
    dim3 tgrid(SS/32, EE/32, BB);
    dim3 tblk(32, 8);

    // GRN1 on query image (apply fused with transpose + fp16 convert)
    grn_sumsq_cm<<<BB*EE, 256>>>(qimg, sumsq);
    grn_mean<<<BB, 256>>>(sumsq, meang);
    grn1_T<<<tgrid, tblk>>>(qimg, sumsq, meang, grn1_g, grn1_b, xh);

    // Q projection
    cvt_h<<<EE*EE/1024, 256>>>(q_w, wh);
    gemm_hmma<0><<<dim3(EE/128, BNS/128), 128, GSMEM>>>(xh, wh, q_b,
        qb, nullptr, BNS, EE, EE);
    // K projection
    cvt_T<<<tgrid, tblk>>>(kimg, xh);
    cvt_h<<<EE*EE/1024, 256>>>(k_w, wh);
    gemm_hmma<0><<<dim3(EE/128, BNS/128), 128, GSMEM>>>(xh, wh, k_b,
        kb, nullptr, BNS, EE, EE);
    // V projection
    cvt_T<<<tgrid, tblk>>>(vimg, xh);
    cvt_h<<<EE*EE/1024, 256>>>(v_w, wh);
    gemm_hmma<0><<<dim3(EE/128, BNS/128), 128, GSMEM>>>(xh, wh, v_b,
        vb, nullptr, BNS, EE, EE);

    // LayerNorm + elu+1 (in place)
    ln_elu<<<BNS, 256>>>(qb, lnq_w, lnq_b);
    ln_elu<<<BNS, 256>>>(kb, lnk_w, lnk_b);

    // linear attention (output straight to fp16)
    zero_f<<<(BB*HH*DD*DD + 255)/256, 256>>>(kv, BB*HH*DD*DD);
    zero_f<<<(BB*HH*DD + 255)/256, 256>>>(ksum, BB*HH*DD);
    kvsum_kernel<<<dim3(BB*HH, 16), 256>>>(kb, vb, kv, ksum);
    attn_apply_kernel<<<dim3(BB*HH, SS/64), 256>>>(qb, kv, ksum, xh);

    // O projection -> adad (token-major fp32)
    cvt_h<<<EE*EE/1024, 256>>>(o_w, wh);
    gemm_hmma<0><<<dim3(EE/128, BNS/128), 128, GSMEM>>>(xh, wh, o_b,
        adad, nullptr, BNS, EE, EE);

    // working = qimg^T + oproj * attn_scalar (token-major)
    make_working<<<tgrid, tblk>>>(qimg, adad, ascal, work);

    // GRN2 on working (apply writes fp16 directly)
    zero_f<<<(BB*EE + 255)/256, 256>>>(sumsq, BB*EE);
    grn2_sumsq<<<dim3(EE/256, SS/256, BB), 256>>>(work, sumsq);
    grn_mean<<<BB, 256>>>(sumsq, meang);
    grn2_apply<<<(int)(BB*ES/1024), 256>>>(work, sumsq, meang, grn2_g, grn2_b, xh);

    // FFN1: silu epilogue -> fp16 hidden
    cvt_h<<<E4*EE/1024, 256>>>(w1, wh);
    gemm_hmma<1><<<dim3(E4/128, BNS/128), 128, GSMEM>>>(xh, wh, b1,
        nullptr, hh, BNS, E4, EE);

    // FFN2
    cvt_h<<<EE*E4/1024, 256>>>(w2, wh);
    gemm_hmma<0><<<dim3(EE/128, BNS/128), 128, GSMEM>>>(hh, wh, b2,
        ffno, nullptr, BNS, EE, E4);

    // final residual (transpose back to channel-major)
    final_kernel<<<tgrid, tblk>>>(qimg, work, ffno, fscal, finscal, (float*)d_out);
}

// round 8
// speedup vs baseline: 2.1675x; 1.0289x over previous
#include <cuda_runtime.h>
#include <cuda_fp16.h>
#include <math.h>
#include <stdint.h>

// Problem constants
#define BB 2
#define EE 1024
#define HH 16
#define DD 64
#define SS 4096            // 64*64 spatial tokens per batch
#define BNS (BB*SS)        // 8192 total tokens
#define E4 (4*EE)          // 4096 ffn hidden

typedef __half h16;
typedef __half2 h162;

// ---------------- device scratch ----------------
__device__ float g_work[(long)BNS*EE];     // fp32 working residual
__device__ h16   g_x   [(long)BNS*EE];     // fp16 GEMM A staging
__device__ h16   g_w   [(long)E4*EE];      // fp16 weights (max 4096x1024)
__device__ h16   g_h   [(long)BNS*E4];     // fp16: q|k|v slices, later ffn hidden
__device__ h16   g_o1  [(long)BNS*EE];     // fp16 o-proj out
__device__ h16   g_o2  [(long)BNS*EE];     // fp16 ffn2 out
__device__ float g_kv  [BB*HH*DD*DD];
__device__ float g_ksum[BB*HH*DD];
__device__ float g_sumsq[BB*EE];
__device__ float g_meangx[BB];

// ================= helpers =================
__device__ __forceinline__ uint32_t smem_u32(const void* p) {
    uint32_t a;
    asm("{ .reg .u64 t; cvta.to.shared.u64 t, %1; cvt.u32.u64 %0, t; }" : "=r"(a) : "l"(p));
    return a;
}
__device__ __forceinline__ void cp16(uint32_t dst, const void* src) {
    asm volatile("cp.async.cg.shared.global [%0], [%1], 16;" :: "r"(dst), "l"(src));
}
__device__ __forceinline__ uint32_t lds32(uint32_t a) {
    uint32_t v;
    asm volatile("ld.shared.u32 %0, [%1];" : "=r"(v) : "r"(a));
    return v;
}
__device__ __forceinline__ void mma16816(float* c, const uint32_t* a, const uint32_t* b) {
    asm volatile(
        "mma.sync.aligned.m16n8k16.row.col.f32.f16.f16.f32 "
        "{%0,%1,%2,%3}, {%4,%5,%6,%7}, {%8,%9}, {%0,%1,%2,%3};"
        : "+f"(c[0]), "+f"(c[1]), "+f"(c[2]), "+f"(c[3])
        : "r"(a[0]), "r"(a[1]), "r"(a[2]), "r"(a[3]), "r"(b[0]), "r"(b[1]));
}

// ================= GEMM: C[M,N] = A W^T + bias (fp16) =====
// Block 128x128, KT=32, 4 warps (2 M x 2 N), warp tile 64x64, 3-stage cp.async.
// EPI 0: fp32 out. EPI 1: silu -> fp16. EPI 2: fp16 out.
#define TPITCH 80
#define TBYTES (128*TPITCH)          // 10240
#define STAGEB (2*TBYTES)            // 20480
#define NSTAGE 3
#define GSMEM  (NSTAGE*STAGEB)       // 61440

template<int EPI>
__global__ __launch_bounds__(128, 2) void gemm_hmma(
    const h16* __restrict__ A, const h16* __restrict__ W,
    const float* __restrict__ bias,
    float* __restrict__ C, h16* __restrict__ CH,
    int M, int N, int K)
{
    extern __shared__ char sm[];
    const uint32_t sbase = smem_u32(sm);
    const int tid = threadIdx.x;
    const int lane = tid & 31, wid = tid >> 5;
    const int warp_m = wid >> 1, warp_n = wid & 1;
    const int m0 = blockIdx.y * 128, n0 = blockIdx.x * 128;
    const int lrow = lane >> 2, lpair = lane & 3;

    float acc[4][8][4];
    #pragma unroll
    for (int i = 0; i < 4; i++)
        #pragma unroll
        for (int j = 0; j < 8; j++)
            #pragma unroll
            for (int t = 0; t < 4; t++) acc[i][j][t] = 0.f;

    const int nk = K >> 5;

    auto load_stage = [&](int buf, int kc) {
        const long kq = (long)kc * 32;
        uint32_t sb = sbase + buf * STAGEB;
        #pragma unroll
        for (int i = 0; i < 4; i++) {
            int p = tid + i * 128;
            int row = p >> 2, ch = p & 3;
            uint32_t d = sb + row * TPITCH + ch * 16;
            cp16(d,          A + (long)(m0 + row) * K + kq + ch * 8);
            cp16(d + TBYTES, W + (long)(n0 + row) * K + kq + ch * 8);
        }
        asm volatile("cp.async.commit_group;");
    };

    load_stage(0, 0);
    load_stage(1, 1);
    load_stage(2, 2);

    for (int kc = 0; kc < nk; kc++) {
        const int buf = kc % 3;
        const int ahead = nk - 1 - kc;
        if (ahead >= 2)      asm volatile("cp.async.wait_group 2;");
        else if (ahead == 1) asm volatile("cp.async.wait_group 1;");
        else                 asm volatile("cp.async.wait_group 0;");
        __syncthreads();

        const uint32_t aB = sbase + buf * STAGEB;
        const uint32_t bB = aB + TBYTES;

        #pragma unroll
        for (int s = 0; s < 2; s++) {
            const uint32_t koff = (s * 8 + lpair) * 4;
            uint32_t aF[4][4], bF[8][2];
            #pragma unroll
            for (int mt = 0; mt < 4; mt++) {
                uint32_t r = (warp_m * 64 + mt * 16 + lrow) * TPITCH;
                aF[mt][0] = lds32(aB + r + koff);
                aF[mt][1] = lds32(aB + r + 8*TPITCH + koff);
                aF[mt][2] = lds32(aB + r + koff + 16);
                aF[mt][3] = lds32(aB + r + 8*TPITCH + koff + 16);
            }
            #pragma unroll
            for (int nt = 0; nt < 8; nt++) {
                uint32_t r = (warp_n * 64 + nt * 8 + lrow) * TPITCH;
                bF[nt][0] = lds32(bB + r + koff);
                bF[nt][1] = lds32(bB + r + koff + 16);
            }
            #pragma unroll
            for (int mt = 0; mt < 4; mt++)
                #pragma unroll
                for (int nt = 0; nt < 8; nt++)
                    mma16816(acc[mt][nt], aF[mt], bF[nt]);
        }
        __syncthreads();
        if (kc + 3 < nk) load_stage(buf, kc + 3);
    }

    // ---- epilogue ----
    #pragma unroll
    for (int mt = 0; mt < 4; mt++) {
        #pragma unroll
        for (int nt = 0; nt < 8; nt++) {
            long row = m0 + warp_m * 64 + mt * 16 + lrow;
            int col = n0 + warp_n * 64 + nt * 8 + lpair * 2;
            float b0 = bias[col], b1 = bias[col + 1];
            #pragma unroll
            for (int half = 0; half < 2; half++) {
                long r = row + half * 8;
                float v0 = acc[mt][nt][half*2 + 0] + b0;
                float v1 = acc[mt][nt][half*2 + 1] + b1;
                if (EPI == 0) {
                    *(float2*)(C + r * N + col) = make_float2(v0, v1);
                } else if (EPI == 1) {
                    v0 = v0 / (1.f + expf(-v0));
                    v1 = v1 / (1.f + expf(-v1));
                    *(h162*)(CH + r * N + col) = __floats2half2_rn(v0, v1);
                } else {
                    *(h162*)(CH + r * N + col) = __floats2half2_rn(v0, v1);
                }
            }
        }
    }
}

// ================= converters =================
__global__ __launch_bounds__(256) void cvt_h(const float* __restrict__ x,
                                             h16* __restrict__ o) {
    long i = ((long)blockIdx.x * 256 + threadIdx.x) * 4;
    float4 v = *(const float4*)(x + i);
    *(h162*)(o + i)     = __floats2half2_rn(v.x, v.y);
    *(h162*)(o + i + 2) = __floats2half2_rn(v.z, v.w);
}

// transpose [B,E,S] fp32 -> [B,S,E] fp16
__global__ void cvt_T(const float* __restrict__ x, h16* __restrict__ o) {
    __shared__ float t[32][33];
    int sx = blockIdx.x * 32, cy = blockIdx.y * 32, b = blockIdx.z;
    int lx = threadIdx.x;
    for (int r = threadIdx.y; r < 32; r += 8)
        t[r][lx] = x[((long)b * EE + cy + r) * SS + sx + lx];
    __syncthreads();
    for (int r = threadIdx.y; r < 32; r += 8) {
        long oi = ((long)b * SS + sx + r) * EE + cy + lx;
        o[oi] = __float2half(t[lx][r]);
    }
}

// GRN1 apply fused with transpose + fp16 convert
__global__ void grn1_T(const float* __restrict__ x,
                       const float* __restrict__ sumsq,
                       const float* __restrict__ meangx,
                       const float* __restrict__ gamma,
                       const float* __restrict__ beta,
                       h16* __restrict__ o) {
    __shared__ float t[32][33];
    int sx = blockIdx.x * 32, cy = blockIdx.y * 32, b = blockIdx.z;
    int lx = threadIdx.x;
    for (int r = threadIdx.y; r < 32; r += 8)
        t[r][lx] = x[((long)b * EE + cy + r) * SS + sx + lx];
    __syncthreads();
    int c = cy + lx;
    float nx = sqrtf(sumsq[b*EE + c]) / (meangx[b] + 1e-6f);
    float g1 = 1.f + gamma[c], be = beta[c];
    for (int r = threadIdx.y; r < 32; r += 8) {
        float v = t[lx][r];
        long oi = ((long)b * SS + sx + r) * EE + c;
        o[oi] = __float2half(g1 * v * nx + be + v);
    }
}

// ---------------- small helpers ----------------
__inline__ __device__ void blockReduce2(float& a, float& b) {
    #pragma unroll
    for (int off = 16; off > 0; off >>= 1) {
        a += __shfl_down_sync(0xffffffffu, a, off);
        b += __shfl_down_sync(0xffffffffu, b, off);
    }
    __shared__ float sa[8], sb[8];
    int w = threadIdx.x >> 5, l = threadIdx.x & 31;
    if (l == 0) { sa[w] = a; sb[w] = b; }
    __syncthreads();
    if (w == 0) {
        a = (l < 8) ? sa[l] : 0.f;
        b = (l < 8) ? sb[l] : 0.f;
        #pragma unroll
        for (int off = 4; off > 0; off >>= 1) {
            a += __shfl_down_sync(0xffu, a, off);
            b += __shfl_down_sync(0xffu, b, off);
        }
        if (l == 0) { sa[0] = a; sb[0] = b; }
    }
    __syncthreads();
    a = sa[0]; b = sb[0];
}

__global__ void zero_f(float* __restrict__ p, int n) {
    int i = blockIdx.x * blockDim.x + threadIdx.x;
    if (i < n) p[i] = 0.f;
}

// ---------------- GRN reductions ----------------
__global__ __launch_bounds__(256) void grn_sumsq_cm(const float* __restrict__ x,
                                                    float* __restrict__ sumsq) {
    const float* xr = x + (long)blockIdx.x * SS;
    float acc = 0.f, dummy = 0.f;
    for (int i = threadIdx.x * 4; i < SS; i += 1024) {
        float4 v = *(const float4*)(xr + i);
        acc += v.x*v.x + v.y*v.y + v.z*v.z + v.w*v.w;
    }
    blockReduce2(acc, dummy);
    if (threadIdx.x == 0) sumsq[blockIdx.x] = acc;
}

__global__ __launch_bounds__(256) void grn_mean(const float* __restrict__ sumsq,
                                                float* __restrict__ meangx) {
    int b = blockIdx.x;
    float s = 0.f, dummy = 0.f;
    for (int c = threadIdx.x; c < EE; c += 256) s += sqrtf(sumsq[b*EE + c]);
    blockReduce2(s, dummy);
    if (threadIdx.x == 0) meangx[b] = s / (float)EE;
}

// GRN2 apply, token-major fp32 in, writes fp16 directly
__global__ __launch_bounds__(256) void grn2_apply(const float* __restrict__ x,
                                                  const float* __restrict__ sumsq,
                                                  const float* __restrict__ meangx,
                                                  const float* __restrict__ gamma,
                                                  const float* __restrict__ beta,
                                                  h16* __restrict__ o) {
    long i4 = ((long)blockIdx.x * 256 + threadIdx.x) * 4;
    int c0 = (int)(i4 & 1023);
    int b = (int)(i4 >> 22);
    float4 g4 = *(const float4*)(gamma + c0);
    float4 b4 = *(const float4*)(beta + c0);
    float4 s4 = *(const float4*)(sumsq + b*EE + c0);
    float mg = meangx[b] + 1e-6f;
    float4 v = *(const float4*)(x + i4);
    float o0 = (1.f+g4.x) * v.x * (sqrtf(s4.x)/mg) + b4.x + v.x;
    float o1 = (1.f+g4.y) * v.y * (sqrtf(s4.y)/mg) + b4.y + v.y;
    float o2 = (1.f+g4.z) * v.z * (sqrtf(s4.z)/mg) + b4.z + v.z;
    float o3 = (1.f+g4.w) * v.w * (sqrtf(s4.w)/mg) + b4.w + v.w;
    *(h162*)(o + i4)     = __floats2half2_rn(o0, o1);
    *(h162*)(o + i4 + 2) = __floats2half2_rn(o2, o3);
}

// ---------------- LayerNorm + (elu+1), fp16 in/out ----------------
__global__ __launch_bounds__(256) void ln_elu_h(h16* __restrict__ x,
                                                const float* __restrict__ w,
                                                const float* __restrict__ b) {
    h162* xr = (h162*)(x + (long)blockIdx.x * EE);
    int tid = threadIdx.x;
    h162 p0 = xr[tid*2], p1 = xr[tid*2 + 1];
    float v0 = __half2float(p0.x), v1 = __half2float(p0.y);
    float v2 = __half2float(p1.x), v3 = __half2float(p1.y);
    float s  = v0 + v1 + v2 + v3;
    float sq = v0*v0 + v1*v1 + v2*v2 + v3*v3;
    blockReduce2(s, sq);
    float mean = s / (float)EE;
    float var = sq / (float)EE - mean*mean;
    float rstd = rsqrtf(var + 1e-5f);
    float4 wv = *(const float4*)(w + tid*4);
    float4 bv = *(const float4*)(b + tid*4);
    float y;
    y = (v0-mean)*rstd*wv.x + bv.x; v0 = (y > 0.f) ? y + 1.f : expf(y);
    y = (v1-mean)*rstd*wv.y + bv.y; v1 = (y > 0.f) ? y + 1.f : expf(y);
    y = (v2-mean)*rstd*wv.z + bv.z; v2 = (y > 0.f) ? y + 1.f : expf(y);
    y = (v3-mean)*rstd*wv.w + bv.w; v3 = (y > 0.f) ? y + 1.f : expf(y);
    xr[tid*2]     = __floats2half2_rn(v0, v1);
    xr[tid*2 + 1] = __floats2half2_rn(v2, v3);
}

// ---------------- linear attention (fp16 inputs) ----------------
__global__ __launch_bounds__(256) void kvsum_kernel(const h16* __restrict__ k,
                                                    const h16* __restrict__ v,
                                                    float* __restrict__ kv,
                                                    float* __restrict__ ksum) {
    int bh = blockIdx.x;
    int b = bh >> 4, h = bh & 15;
    int tid = threadIdx.x;
    __shared__ float ks[16][68], vs[16][68];
    int d0 = (tid >> 4) * 4, e0 = (tid & 15) * 4;
    float acc[4][4] = {};
    float accks[4] = {};
    long base = ((long)b * SS + (long)blockIdx.y * 256) * EE + h * DD;
    int ltok = tid >> 4, lc = (tid & 15) * 4;
    for (int t0 = 0; t0 < 256; t0 += 16) {
        long gi = base + (long)(t0+ltok)*EE + lc;
        h162 ka = *(const h162*)(k + gi), kb2 = *(const h162*)(k + gi + 2);
        h162 va = *(const h162*)(v + gi), vb2 = *(const h162*)(v + gi + 2);
        ks[ltok][lc+0] = __half2float(ka.x); ks[ltok][lc+1] = __half2float(ka.y);
        ks[ltok][lc+2] = __half2float(kb2.x); ks[ltok][lc+3] = __half2float(kb2.y);
        vs[ltok][lc+0] = __half2float(va.x); vs[ltok][lc+1] = __half2float(va.y);
        vs[ltok][lc+2] = __half2float(vb2.x); vs[ltok][lc+3] = __half2float(vb2.y);
        __syncthreads();
        #pragma unroll
        for (int t = 0; t < 16; t++) {
            float a[4], bb[4];
            #pragma unroll
            for (int i = 0; i < 4; i++) a[i] = ks[t][d0+i];
            #pragma unroll
            for (int j = 0; j < 4; j++) bb[j] = vs[t][e0+j];
            #pragma unroll
            for (int i = 0; i < 4; i++)
                #pragma unroll
                for (int j = 0; j < 4; j++) acc[i][j] += a[i]*bb[j];
            if (e0 == 0) {
                #pragma unroll
                for (int i = 0; i < 4; i++) accks[i] += a[i];
            }
        }
        __syncthreads();
    }
    long kvbase = (long)bh * DD * DD;
    #pragma unroll
    for (int i = 0; i < 4; i++)
        #pragma unroll
        for (int j = 0; j < 4; j++)
            atomicAdd(&kv[kvbase + (d0+i)*DD + e0+j], acc[i][j]);
    if (e0 == 0)
        #pragma unroll
        for (int i = 0; i < 4; i++) atomicAdd(&ksum[bh*DD + d0+i], accks[i]);
}

// attn = (q @ kv) / (q . ksum + 1e-8), fp16 in, fp16 out
__global__ __launch_bounds__(256) void attn_apply_kernel(const h16* __restrict__ q,
                                                         const float* __restrict__ kv,
                                                         const float* __restrict__ ksum,
                                                         h16* __restrict__ o) {
    int bh = blockIdx.x, sblk = blockIdx.y;
    int b = bh >> 4, h = bh & 15;
    int tid = threadIdx.x;
    __shared__ float qs[64][68];
    __shared__ float kvs[64][64];
    __shared__ float kss[64];
    long kvbase = (long)bh * DD * DD;
    #pragma unroll
    for (int r = 0; r < 4; r++) {
        int idx = (r*256 + tid) * 4;
        *(float4*)&kvs[idx >> 6][idx & 63] = *(const float4*)(kv + kvbase + idx);
    }
    if (tid < 64) kss[tid] = ksum[bh*DD + tid];
    long qbase = ((long)b * SS + (long)sblk * 64) * EE + h * DD;
    int ltok = tid >> 4, lc = (tid & 15) * 4;
    #pragma unroll
    for (int r = 0; r < 4; r++) {
        long gi = qbase + (long)(ltok + r*16)*EE + lc;
        h162 qa = *(const h162*)(q + gi), qb2 = *(const h162*)(q + gi + 2);
        qs[ltok + r*16][lc+0] = __half2float(qa.x);
        qs[ltok + r*16][lc+1] = __half2float(qa.y);
        qs[ltok + r*16][lc+2] = __half2float(qb2.x);
        qs[ltok + r*16][lc+3] = __half2float(qb2.y);
    }
    __syncthreads();
    int tok = tid >> 2, e0 = (tid & 3) * 16;
    float num[16] = {};
    float den = 0.f;
    #pragma unroll 8
    for (int d = 0; d < 64; d++) {
        float qd = qs[tok][d];
        den += qd * kss[d];
        #pragma unroll
        for (int j = 0; j < 16; j++) num[j] += qd * kvs[d][e0+j];
    }
    float r = 1.f / (den + 1e-8f);
    long obase = ((long)b * SS + (long)sblk * 64 + tok) * EE + h * DD + e0;
    #pragma unroll
    for (int j = 0; j < 16; j += 2)
        *(h162*)(o + obase + j) = __floats2half2_rn(num[j] * r, num[j+1] * r);
}

// ---------------- residual / transpose kernels ----------------
// working = qimg^T + oproj*ascal (fp32) + fused GRN2 sumsq accumulation
__global__ void make_working(const float* __restrict__ qimg,
                             const h16* __restrict__ attn_out,
                             const float* __restrict__ ascal,
                             float* __restrict__ work,
                             float* __restrict__ sumsq) {
    __shared__ float t[32][33];
    __shared__ float red[8][32];
    int sx = blockIdx.x * 32, cy = blockIdx.y * 32, b = blockIdx.z;
    int x = threadIdx.x, ty = threadIdx.y;
    for (int r = ty; r < 32; r += 8)
        t[r][x] = qimg[((long)b*EE + cy + r)*SS + sx + x];
    __syncthreads();
    float asc = ascal[cy + x];
    float acc = 0.f;
    for (int r = ty; r < 32; r += 8) {
        long o = ((long)b*SS + sx + r)*EE + cy + x;
        float wv = t[x][r] + __half2float(attn_out[o]) * asc;
        work[o] = wv;
        acc += wv * wv;
    }
    red[ty][x] = acc;
    __syncthreads();
    if (ty == 0) {
        float s = 0.f;
        #pragma unroll
        for (int i = 0; i < 8; i++) s += red[i][x];
        atomicAdd(&sumsq[b*EE + cy + x], s);
    }
}

__global__ void final_kernel(const float* __restrict__ qimg,
                             const float* __restrict__ work,
                             const h16* __restrict__ ffn,
                             const float* __restrict__ fscal,
                             const float* __restrict__ finscal,
                             float* __restrict__ out) {
    __shared__ float t[32][33];
    int sx = blockIdx.x * 32, cy = blockIdx.y * 32, b = blockIdx.z;
    int x = threadIdx.x;
    float fs = fscal[cy + x], fin = finscal[cy + x];
    for (int r = threadIdx.y; r < 32; r += 8) {
        long o = ((long)b*SS + sx + r)*EE + cy + x;
        t[r][x] = (work[o] + __half2float(ffn[o]) * fs) * fin;
    }
    __syncthreads();
    for (int r = threadIdx.y; r < 32; r += 8) {
        long o = ((long)b*EE + cy + r)*SS + sx + x;
        out[o] = qimg[o] + t[x][r];
    }
}

// ---------------- host launcher ----------------
extern "C" void kernel_launch(void* const* d_in, const int* in_sizes, int n_in,
                              void* d_out, int out_size) {
    const float* qimg   = (const float*)d_in[0];
    const float* kimg   = (const float*)d_in[1];
    const float* vimg   = (const float*)d_in[2];
    const float* grn1_g = (const float*)d_in[3];
    const float* grn1_b = (const float*)d_in[4];
    const float* q_w    = (const float*)d_in[5];
    const float* q_b    = (const float*)d_in[6];
    const float* k_w    = (const float*)d_in[7];
    const float* k_b    = (const float*)d_in[8];
    const float* v_w    = (const float*)d_in[9];
    const float* v_b    = (const float*)d_in[10];
    const float* o_w    = (const float*)d_in[11];
    const float* o_b    = (const float*)d_in[12];
    const float* lnq_w  = (const float*)d_in[13];
    const float* lnq_b  = (const float*)d_in[14];
    const float* lnk_w  = (const float*)d_in[15];
    const float* lnk_b  = (const float*)d_in[16];
    const float* ascal  = (const float*)d_in[17];
    const float* grn2_g = (const float*)d_in[18];
    const float* grn2_b = (const float*)d_in[19];
    const float* w1     = (const float*)d_in[20];
    const float* b1     = (const float*)d_in[21];
    const float* w2     = (const float*)d_in[22];
    const float* b2     = (const float*)d_in[23];
    const float* fscal  = (const float*)d_in[24];
    const float* finscal= (const float*)d_in[25];

    float *work, *kv, *ksum, *sumsq, *meang;
    h16 *xh, *wh, *hh, *o1, *o2;
    cudaGetSymbolAddress((void**)&work, g_work);
    cudaGetSymbolAddress((void**)&xh,   g_x);
    cudaGetSymbolAddress((void**)&wh,   g_w);
    cudaGetSymbolAddress((void**)&hh,   g_h);
    cudaGetSymbolAddress((void**)&o1,   g_o1);
    cudaGetSymbolAddress((void**)&o2,   g_o2);
    cudaGetSymbolAddress((void**)&kv,   g_kv);
    cudaGetSymbolAddress((void**)&ksum, g_ksum);
    cudaGetSymbolAddress((void**)&sumsq,g_sumsq);
    cudaGetSymbolAddress((void**)&meang,g_meangx);

    h16* qh = hh;                         // q/k/v alias ffn hidden (dead by then)
    h16* kh = hh + (long)BNS*EE;
    h16* vh = hh + 2L*BNS*EE;

    cudaFuncSetAttribute(gemm_hmma<0>, cudaFuncAttributeMaxDynamicSharedMemorySize, GSMEM);
    cudaFuncSetAttribute(gemm_hmma<1>, cudaFuncAttributeMaxDynamicSharedMemorySize, GSMEM);
    cudaFuncSetAttribute(gemm_hmma<2>, cudaFuncAttributeMaxDynamicSharedMemorySize, GSMEM);

    const long ES = (long)EE * SS;
    dim3 tgrid(SS/32, EE/32, BB);
    dim3 tblk(32, 8);
    dim3 pgrid(EE/128, BNS/128);

    // GRN1 on query image (apply fused with transpose + fp16 convert)
    grn_sumsq_cm<<<BB*EE, 256>>>(qimg, sumsq);
    grn_mean<<<BB, 256>>>(sumsq, meang);
    grn1_T<<<tgrid, tblk>>>(qimg, sumsq, meang, grn1_g, grn1_b, xh);

    // Q projection -> fp16
    cvt_h<<<EE*EE/1024, 256>>>(q_w, wh);
    gemm_hmma<2><<<pgrid, 128, GSMEM>>>(xh, wh, q_b, nullptr, qh, BNS, EE, EE);
    // K projection
    cvt_T<<<tgrid, tblk>>>(kimg, xh);
    cvt_h<<<EE*EE/1024, 256>>>(k_w, wh);
    gemm_hmma<2><<<pgrid, 128, GSMEM>>>(xh, wh, k_b, nullptr, kh, BNS, EE, EE);
    // V projection
    cvt_T<<<tgrid, tblk>>>(vimg, xh);
    cvt_h<<<EE*EE/1024, 256>>>(v_w, wh);
    gemm_hmma<2><<<pgrid, 128, GSMEM>>>(xh, wh, v_b, nullptr, vh, BNS, EE, EE);

    // LayerNorm + elu+1 (in place, fp16)
    ln_elu_h<<<BNS, 256>>>(qh, lnq_w, lnq_b);
    ln_elu_h<<<BNS, 256>>>(kh, lnk_w, lnk_b);

    // linear attention (fp16 in, fp16 out)
    zero_f<<<(BB*HH*DD*DD + 255)/256, 256>>>(kv, BB*HH*DD*DD);
    zero_f<<<(BB*HH*DD + 255)/256, 256>>>(ksum, BB*HH*DD);
    kvsum_kernel<<<dim3(BB*HH, 16), 256>>>(kh, vh, kv, ksum);
    attn_apply_kernel<<<dim3(BB*HH, SS/64), 256>>>(qh, kv, ksum, xh);

    // O projection -> fp16 o1
    cvt_h<<<EE*EE/1024, 256>>>(o_w, wh);
    gemm_hmma<2><<<pgrid, 128, GSMEM>>>(xh, wh, o_b, nullptr, o1, BNS, EE, EE);

    // working = qimg^T + oproj * ascal (+ fused GRN2 sumsq)
    zero_f<<<(BB*EE + 255)/256, 256>>>(sumsq, BB*EE);
    make_working<<<tgrid, tblk>>>(qimg, o1, ascal, work, sumsq);
    grn_mean<<<BB, 256>>>(sumsq, meang);
    grn2_apply<<<(int)(BB*ES/1024), 256>>>(work, sumsq, meang, grn2_g, grn2_b, xh);

    // FFN1: silu epilogue -> fp16 hidden
    cvt_h<<<E4*EE/1024, 256>>>(w1, wh);
    gemm_hmma<1><<<dim3(E4/128, BNS/128), 128, GSMEM>>>(xh, wh, b1,
        nullptr, hh, BNS, E4, EE);

    // FFN2 -> fp16 o2
    cvt_h<<<EE*E4/1024, 256>>>(w2, wh);
    gemm_hmma<2><<<pgrid, 128, GSMEM>>>(hh, wh, b2, nullptr, o2, BNS, EE, E4);

    // final residual (transpose back to channel-major)
    final_kernel<<<tgrid, tblk>>>(qimg, work, o2, fscal, finscal, (float*)d_out);
}

// round 9
// speedup vs baseline: 2.3590x; 1.0884x over previous
#include <cuda_runtime.h>
#include <cuda_fp16.h>
#include <math.h>
#include <stdint.h>

// Problem constants
#define BB 2
#define EE 1024
#define HH 16
#define DD 64
#define SS 4096            // 64*64 spatial tokens per batch
#define BNS (BB*SS)        // 8192 total tokens
#define E4 (4*EE)          // 4096 ffn hidden

typedef __half h16;
typedef __half2 h162;

#define M1 (1L<<20)        // 1M elements (EE*EE)

// ---------------- device scratch ----------------
__device__ float g_work[(long)BNS*EE];        // fp32 working residual
__device__ h16   g_x   [(long)BNS*EE];        // fp16 GEMM A staging
__device__ h16   g_w   [12*M1];               // all 6 weights fp16: q|k|v|o|w1|w2
__device__ h16   g_h   [(long)BNS*E4];        // fp16: q|k|v slices, later ffn hidden
__device__ h16   g_o1  [(long)BNS*EE];        // fp16 o-proj out
__device__ h16   g_o2  [(long)BNS*EE];        // fp16 ffn2 out
__device__ float g_kv  [BB*HH*DD*DD + BB*HH*DD];  // kv | ksum
__device__ float g_sumsq[BB*EE];
__device__ float g_meangx[BB];

// ================= helpers =================
__device__ __forceinline__ uint32_t smem_u32(const void* p) {
    uint32_t a;
    asm("{ .reg .u64 t; cvta.to.shared.u64 t, %1; cvt.u32.u64 %0, t; }" : "=r"(a) : "l"(p));
    return a;
}
__device__ __forceinline__ void cp16(uint32_t dst, const void* src) {
    asm volatile("cp.async.cg.shared.global [%0], [%1], 16;" :: "r"(dst), "l"(src));
}
__device__ __forceinline__ uint32_t lds32(uint32_t a) {
    uint32_t v;
    asm volatile("ld.shared.u32 %0, [%1];" : "=r"(v) : "r"(a));
    return v;
}
__device__ __forceinline__ void mma16816(float* c, const uint32_t* a, const uint32_t* b) {
    asm volatile(
        "mma.sync.aligned.m16n8k16.row.col.f32.f16.f16.f32 "
        "{%0,%1,%2,%3}, {%4,%5,%6,%7}, {%8,%9}, {%0,%1,%2,%3};"
        : "+f"(c[0]), "+f"(c[1]), "+f"(c[2]), "+f"(c[3])
        : "r"(a[0]), "r"(a[1]), "r"(a[2]), "r"(a[3]), "r"(b[0]), "r"(b[1]));
}

// ================= GEMM: C[M,N] = A W^T + bias (fp16) =====
// Block 128x128, KT=64, 4 warps (2 M x 2 N), warp tile 64x64, 2-stage cp.async.
// EPI 0: fp32 out. EPI 1: silu -> fp16. EPI 2: fp16 out.
#define TPITCH 144
#define TBYTES (128*TPITCH)          // 18432
#define STAGEB (2*TBYTES)            // 36864
#define GSMEM  (2*STAGEB)            // 73728

template<int EPI>
__global__ __launch_bounds__(128, 2) void gemm_hmma(
    const h16* __restrict__ A, const h16* __restrict__ W,
    const float* __restrict__ bias,
    float* __restrict__ C, h16* __restrict__ CH,
    int M, int N, int K)
{
    extern __shared__ char sm[];
    const uint32_t sbase = smem_u32(sm);
    const int tid = threadIdx.x;
    const int lane = tid & 31, wid = tid >> 5;
    const int warp_m = wid >> 1, warp_n = wid & 1;
    const int m0 = blockIdx.y * 128, n0 = blockIdx.x * 128;
    const int lrow = lane >> 2, lpair = lane & 3;

    float acc[4][8][4];
    #pragma unroll
    for (int i = 0; i < 4; i++)
        #pragma unroll
        for (int j = 0; j < 8; j++)
            #pragma unroll
            for (int t = 0; t < 4; t++) acc[i][j][t] = 0.f;

    const int nk = K >> 6;

    auto load_stage = [&](int buf, int kc) {
        const long kq = (long)kc * 64;
        uint32_t sb = sbase + buf * STAGEB;
        #pragma unroll
        for (int i = 0; i < 8; i++) {
            int p = tid + i * 128;
            int row = p >> 3, ch = p & 7;
            uint32_t d = sb + row * TPITCH + ch * 16;
            cp16(d,          A + (long)(m0 + row) * K + kq + ch * 8);
            cp16(d + TBYTES, W + (long)(n0 + row) * K + kq + ch * 8);
        }
        asm volatile("cp.async.commit_group;");
    };

    load_stage(0, 0);
    if (nk > 1) load_stage(1, 1);

    for (int kc = 0; kc < nk; kc++) {
        const int buf = kc & 1;
        if (kc + 1 < nk) asm volatile("cp.async.wait_group 1;");
        else             asm volatile("cp.async.wait_group 0;");
        __syncthreads();

        const uint32_t aB = sbase + buf * STAGEB;
        const uint32_t bB = aB + TBYTES;

        #pragma unroll
        for (int s = 0; s < 4; s++) {
            const uint32_t koff = (s * 8 + lpair) * 4;
            uint32_t aF[4][4], bF[8][2];
            #pragma unroll
            for (int mt = 0; mt < 4; mt++) {
                uint32_t r = (warp_m * 64 + mt * 16 + lrow) * TPITCH;
                aF[mt][0] = lds32(aB + r + koff);
                aF[mt][1] = lds32(aB + r + 8*TPITCH + koff);
                aF[mt][2] = lds32(aB + r + koff + 16);
                aF[mt][3] = lds32(aB + r + 8*TPITCH + koff + 16);
            }
            #pragma unroll
            for (int nt = 0; nt < 8; nt++) {
                uint32_t r = (warp_n * 64 + nt * 8 + lrow) * TPITCH;
                bF[nt][0] = lds32(bB + r + koff);
                bF[nt][1] = lds32(bB + r + koff + 16);
            }
            #pragma unroll
            for (int mt = 0; mt < 4; mt++)
                #pragma unroll
                for (int nt = 0; nt < 8; nt++)
                    mma16816(acc[mt][nt], aF[mt], bF[nt]);
        }
        __syncthreads();
        if (kc + 2 < nk) load_stage(buf, kc + 2);
    }

    // ---- epilogue ----
    #pragma unroll
    for (int mt = 0; mt < 4; mt++) {
        #pragma unroll
        for (int nt = 0; nt < 8; nt++) {
            long row = m0 + warp_m * 64 + mt * 16 + lrow;
            int col = n0 + warp_n * 64 + nt * 8 + lpair * 2;
            float b0 = bias[col], b1 = bias[col + 1];
            #pragma unroll
            for (int half = 0; half < 2; half++) {
                long r = row + half * 8;
                float v0 = acc[mt][nt][half*2 + 0] + b0;
                float v1 = acc[mt][nt][half*2 + 1] + b1;
                if (EPI == 0) {
                    *(float2*)(C + r * N + col) = make_float2(v0, v1);
                } else if (EPI == 1) {
                    v0 = v0 / (1.f + expf(-v0));
                    v1 = v1 / (1.f + expf(-v1));
                    *(h162*)(CH + r * N + col) = __floats2half2_rn(v0, v1);
                } else {
                    *(h162*)(CH + r * N + col) = __floats2half2_rn(v0, v1);
                }
            }
        }
    }
}

// ================= converters =================
// all 6 weight matrices -> fp16 in one grid-stride launch
// layout in out: q[0,1M) k[1M,2M) v[2M,3M) o[3M,4M) w1[4M,8M) w2[8M,12M)
__global__ __launch_bounds__(256) void cvt_weights(
    const float* __restrict__ qw, const float* __restrict__ kw,
    const float* __restrict__ vw, const float* __restrict__ ow,
    const float* __restrict__ w1, const float* __restrict__ w2,
    h16* __restrict__ out)
{
    const long total = 12 * M1;
    const long stride = (long)gridDim.x * blockDim.x * 4;
    for (long i = ((long)blockIdx.x * blockDim.x + threadIdx.x) * 4; i < total;
         i += stride) {
        const float* src;
        long off;
        if (i < 4*M1) {
            int seg = (int)(i >> 20);
            src = (seg == 0) ? qw : (seg == 1) ? kw : (seg == 2) ? vw : ow;
            off = i & (M1 - 1);
        } else if (i < 8*M1) { src = w1; off = i - 4*M1; }
        else                 { src = w2; off = i - 8*M1; }
        float4 v = *(const float4*)(src + off);
        *(h162*)(out + i)     = __floats2half2_rn(v.x, v.y);
        *(h162*)(out + i + 2) = __floats2half2_rn(v.z, v.w);
    }
}

// transpose [B,E,S] fp32 -> [B,S,E] fp16
__global__ void cvt_T(const float* __restrict__ x, h16* __restrict__ o) {
    __shared__ float t[32][33];
    int sx = blockIdx.x * 32, cy = blockIdx.y * 32, b = blockIdx.z;
    int lx = threadIdx.x;
    for (int r = threadIdx.y; r < 32; r += 8)
        t[r][lx] = x[((long)b * EE + cy + r) * SS + sx + lx];
    __syncthreads();
    for (int r = threadIdx.y; r < 32; r += 8) {
        long oi = ((long)b * SS + sx + r) * EE + cy + lx;
        o[oi] = __float2half(t[lx][r]);
    }
}

// GRN1 apply fused with transpose + fp16 convert
__global__ void grn1_T(const float* __restrict__ x,
                       const float* __restrict__ sumsq,
                       const float* __restrict__ meangx,
                       const float* __restrict__ gamma,
                       const float* __restrict__ beta,
                       h16* __restrict__ o) {
    __shared__ float t[32][33];
    int sx = blockIdx.x * 32, cy = blockIdx.y * 32, b = blockIdx.z;
    int lx = threadIdx.x;
    for (int r = threadIdx.y; r < 32; r += 8)
        t[r][lx] = x[((long)b * EE + cy + r) * SS + sx + lx];
    __syncthreads();
    int c = cy + lx;
    float nx = sqrtf(sumsq[b*EE + c]) / (meangx[b] + 1e-6f);
    float g1 = 1.f + gamma[c], be = beta[c];
    for (int r = threadIdx.y; r < 32; r += 8) {
        float v = t[lx][r];
        long oi = ((long)b * SS + sx + r) * EE + c;
        o[oi] = __float2half(g1 * v * nx + be + v);
    }
}

// ---------------- small helpers ----------------
__inline__ __device__ void blockReduce2(float& a, float& b) {
    #pragma unroll
    for (int off = 16; off > 0; off >>= 1) {
        a += __shfl_down_sync(0xffffffffu, a, off);
        b += __shfl_down_sync(0xffffffffu, b, off);
    }
    __shared__ float sa[8], sb[8];
    int w = threadIdx.x >> 5, l = threadIdx.x & 31;
    if (l == 0) { sa[w] = a; sb[w] = b; }
    __syncthreads();
    if (w == 0) {
        a = (l < 8) ? sa[l] : 0.f;
        b = (l < 8) ? sb[l] : 0.f;
        #pragma unroll
        for (int off = 4; off > 0; off >>= 1) {
            a += __shfl_down_sync(0xffu, a, off);
            b += __shfl_down_sync(0xffu, b, off);
        }
        if (l == 0) { sa[0] = a; sb[0] = b; }
    }
    __syncthreads();
    a = sa[0]; b = sb[0];
}

__global__ void zero_f(float* __restrict__ p, int n) {
    int i = blockIdx.x * blockDim.x + threadIdx.x;
    if (i < n) p[i] = 0.f;
}

// ---------------- GRN reductions ----------------
__global__ __launch_bounds__(256) void grn_sumsq_cm(const float* __restrict__ x,
                                                    float* __restrict__ sumsq) {
    const float* xr = x + (long)blockIdx.x * SS;
    float acc = 0.f, dummy = 0.f;
    for (int i = threadIdx.x * 4; i < SS; i += 1024) {
        float4 v = *(const float4*)(xr + i);
        acc += v.x*v.x + v.y*v.y + v.z*v.z + v.w*v.w;
    }
    blockReduce2(acc, dummy);
    if (threadIdx.x == 0) sumsq[blockIdx.x] = acc;
}

__global__ __launch_bounds__(256) void grn_mean(const float* __restrict__ sumsq,
                                                float* __restrict__ meangx) {
    int b = blockIdx.x;
    float s = 0.f, dummy = 0.f;
    for (int c = threadIdx.x; c < EE; c += 256) s += sqrtf(sumsq[b*EE + c]);
    blockReduce2(s, dummy);
    if (threadIdx.x == 0) meangx[b] = s / (float)EE;
}

// GRN2 apply, token-major fp32 in, writes fp16 directly
__global__ __launch_bounds__(256) void grn2_apply(const float* __restrict__ x,
                                                  const float* __restrict__ sumsq,
                                                  const float* __restrict__ meangx,
                                                  const float* __restrict__ gamma,
                                                  const float* __restrict__ beta,
                                                  h16* __restrict__ o) {
    long i4 = ((long)blockIdx.x * 256 + threadIdx.x) * 4;
    int c0 = (int)(i4 & 1023);
    int b = (int)(i4 >> 22);
    float4 g4 = *(const float4*)(gamma + c0);
    float4 b4 = *(const float4*)(beta + c0);
    float4 s4 = *(const float4*)(sumsq + b*EE + c0);
    float mg = meangx[b] + 1e-6f;
    float4 v = *(const float4*)(x + i4);
    float o0 = (1.f+g4.x) * v.x * (sqrtf(s4.x)/mg) + b4.x + v.x;
    float o1 = (1.f+g4.y) * v.y * (sqrtf(s4.y)/mg) + b4.y + v.y;
    float o2 = (1.f+g4.z) * v.z * (sqrtf(s4.z)/mg) + b4.z + v.z;
    float o3 = (1.f+g4.w) * v.w * (sqrtf(s4.w)/mg) + b4.w + v.w;
    *(h162*)(o + i4)     = __floats2half2_rn(o0, o1);
    *(h162*)(o + i4 + 2) = __floats2half2_rn(o2, o3);
}

// ---------------- LayerNorm + (elu+1), fp16 in/out, q & k in one launch ----
__global__ __launch_bounds__(256) void ln_elu_h2(h16* __restrict__ q,
                                                 h16* __restrict__ k,
                                                 const float* __restrict__ wq,
                                                 const float* __restrict__ bq,
                                                 const float* __restrict__ wk,
                                                 const float* __restrict__ bk) {
    int row = blockIdx.x;
    h16* xp;
    const float *w, *b;
    if (row < BNS) { xp = q + (long)row * EE; w = wq; b = bq; }
    else           { xp = k + (long)(row - BNS) * EE; w = wk; b = bk; }
    h162* xr = (h162*)xp;
    int tid = threadIdx.x;
    h162 p0 = xr[tid*2], p1 = xr[tid*2 + 1];
    float v0 = __half2float(p0.x), v1 = __half2float(p0.y);
    float v2 = __half2float(p1.x), v3 = __half2float(p1.y);
    float s  = v0 + v1 + v2 + v3;
    float sq = v0*v0 + v1*v1 + v2*v2 + v3*v3;
    blockReduce2(s, sq);
    float mean = s / (float)EE;
    float var = sq / (float)EE - mean*mean;
    float rstd = rsqrtf(var + 1e-5f);
    float4 wv = *(const float4*)(w + tid*4);
    float4 bv = *(const float4*)(b + tid*4);
    float y;
    y = (v0-mean)*rstd*wv.x + bv.x; v0 = (y > 0.f) ? y + 1.f : expf(y);
    y = (v1-mean)*rstd*wv.y + bv.y; v1 = (y > 0.f) ? y + 1.f : expf(y);
    y = (v2-mean)*rstd*wv.z + bv.z; v2 = (y > 0.f) ? y + 1.f : expf(y);
    y = (v3-mean)*rstd*wv.w + bv.w; v3 = (y > 0.f) ? y + 1.f : expf(y);
    xr[tid*2]     = __floats2half2_rn(v0, v1);
    xr[tid*2 + 1] = __floats2half2_rn(v2, v3);
}

// ---------------- linear attention (fp16 inputs) ----------------
__global__ __launch_bounds__(256) void kvsum_kernel(const h16* __restrict__ k,
                                                    const h16* __restrict__ v,
                                                    float* __restrict__ kv,
                                                    float* __restrict__ ksum) {
    int bh = blockIdx.x;
    int b = bh >> 4, h = bh & 15;
    int tid = threadIdx.x;
    __shared__ float ks[16][68], vs[16][68];
    int d0 = (tid >> 4) * 4, e0 = (tid & 15) * 4;
    float acc[4][4] = {};
    float accks[4] = {};
    long base = ((long)b * SS + (long)blockIdx.y * 256) * EE + h * DD;
    int ltok = tid >> 4, lc = (tid & 15) * 4;
    for (int t0 = 0; t0 < 256; t0 += 16) {
        long gi = base + (long)(t0+ltok)*EE + lc;
        h162 ka = *(const h162*)(k + gi), kb2 = *(const h162*)(k + gi + 2);
        h162 va = *(const h162*)(v + gi), vb2 = *(const h162*)(v + gi + 2);
        ks[ltok][lc+0] = __half2float(ka.x); ks[ltok][lc+1] = __half2float(ka.y);
        ks[ltok][lc+2] = __half2float(kb2.x); ks[ltok][lc+3] = __half2float(kb2.y);
        vs[ltok][lc+0] = __half2float(va.x); vs[ltok][lc+1] = __half2float(va.y);
        vs[ltok][lc+2] = __half2float(vb2.x); vs[ltok][lc+3] = __half2float(vb2.y);
        __syncthreads();
        #pragma unroll
        for (int t = 0; t < 16; t++) {
            float a[4], bb[4];
            #pragma unroll
            for (int i = 0; i < 4; i++) a[i] = ks[t][d0+i];
            #pragma unroll
            for (int j = 0; j < 4; j++) bb[j] = vs[t][e0+j];
            #pragma unroll
            for (int i = 0; i < 4; i++)
                #pragma unroll
                for (int j = 0; j < 4; j++) acc[i][j] += a[i]*bb[j];
            if (e0 == 0) {
                #pragma unroll
                for (int i = 0; i < 4; i++) accks[i] += a[i];
            }
        }
        __syncthreads();
    }
    long kvbase = (long)bh * DD * DD;
    #pragma unroll
    for (int i = 0; i < 4; i++)
        #pragma unroll
        for (int j = 0; j < 4; j++)
            atomicAdd(&kv[kvbase + (d0+i)*DD + e0+j], acc[i][j]);
    if (e0 == 0)
        #pragma unroll
        for (int i = 0; i < 4; i++) atomicAdd(&ksum[bh*DD + d0+i], accks[i]);
}

// attn = (q @ kv) / (q . ksum + 1e-8), fp16 in, fp16 out
__global__ __launch_bounds__(256) void attn_apply_kernel(const h16* __restrict__ q,
                                                         const float* __restrict__ kv,
                                                         const float* __restrict__ ksum,
                                                         h16* __restrict__ o) {
    int bh = blockIdx.x, sblk = blockIdx.y;
    int b = bh >> 4, h = bh & 15;
    int tid = threadIdx.x;
    __shared__ float qs[64][68];
    __shared__ float kvs[64][64];
    __shared__ float kss[64];
    long kvbase = (long)bh * DD * DD;
    #pragma unroll
    for (int r = 0; r < 4; r++) {
        int idx = (r*256 + tid) * 4;
        *(float4*)&kvs[idx >> 6][idx & 63] = *(const float4*)(kv + kvbase + idx);
    }
    if (tid < 64) kss[tid] = ksum[bh*DD + tid];
    long qbase = ((long)b * SS + (long)sblk * 64) * EE + h * DD;
    int ltok = tid >> 4, lc = (tid & 15) * 4;
    #pragma unroll
    for (int r = 0; r < 4; r++) {
        long gi = qbase + (long)(ltok + r*16)*EE + lc;
        h162 qa = *(const h162*)(q + gi), qb2 = *(const h162*)(q + gi + 2);
        qs[ltok + r*16][lc+0] = __half2float(qa.x);
        qs[ltok + r*16][lc+1] = __half2float(qa.y);
        qs[ltok + r*16][lc+2] = __half2float(qb2.x);
        qs[ltok + r*16][lc+3] = __half2float(qb2.y);
    }
    __syncthreads();
    int tok = tid >> 2, e0 = (tid & 3) * 16;
    float num[16] = {};
    float den = 0.f;
    #pragma unroll 8
    for (int d = 0; d < 64; d++) {
        float qd = qs[tok][d];
        den += qd * kss[d];
        #pragma unroll
        for (int j = 0; j < 16; j++) num[j] += qd * kvs[d][e0+j];
    }
    float r = 1.f / (den + 1e-8f);
    long obase = ((long)b * SS + (long)sblk * 64 + tok) * EE + h * DD + e0;
    #pragma unroll
    for (int j = 0; j < 16; j += 2)
        *(h162*)(o + obase + j) = __floats2half2_rn(num[j] * r, num[j+1] * r);
}

// ---------------- residual / transpose kernels ----------------
// working = qimg^T + oproj*ascal (fp32) + fused GRN2 sumsq accumulation
__global__ void make_working(const float* __restrict__ qimg,
                             const h16* __restrict__ attn_out,
                             const float* __restrict__ ascal,
                             float* __restrict__ work,
                             float* __restrict__ sumsq) {
    __shared__ float t[32][33];
    __shared__ float red[8][32];
    int sx = blockIdx.x * 32, cy = blockIdx.y * 32, b = blockIdx.z;
    int x = threadIdx.x, ty = threadIdx.y;
    for (int r = ty; r < 32; r += 8)
        t[r][x] = qimg[((long)b*EE + cy + r)*SS + sx + x];
    __syncthreads();
    float asc = ascal[cy + x];
    float acc = 0.f;
    for (int r = ty; r < 32; r += 8) {
        long o = ((long)b*SS + sx + r)*EE + cy + x;
        float wv = t[x][r] + __half2float(attn_out[o]) * asc;
        work[o] = wv;
        acc += wv * wv;
    }
    red[ty][x] = acc;
    __syncthreads();
    if (ty == 0) {
        float s = 0.f;
        #pragma unroll
        for (int i = 0; i < 8; i++) s += red[i][x];
        atomicAdd(&sumsq[b*EE + cy + x], s);
    }
}

__global__ void final_kernel(const float* __restrict__ qimg,
                             const float* __restrict__ work,
                             const h16* __restrict__ ffn,
                             const float* __restrict__ fscal,
                             const float* __restrict__ finscal,
                             float* __restrict__ out) {
    __shared__ float t[32][33];
    int sx = blockIdx.x * 32, cy = blockIdx.y * 32, b = blockIdx.z;
    int x = threadIdx.x;
    float fs = fscal[cy + x], fin = finscal[cy + x];
    for (int r = threadIdx.y; r < 32; r += 8) {
        long o = ((long)b*SS + sx + r)*EE + cy + x;
        t[r][x] = (work[o] + __half2float(ffn[o]) * fs) * fin;
    }
    __syncthreads();
    for (int r = threadIdx.y; r < 32; r += 8) {
        long o = ((long)b*EE + cy + r)*SS + sx + x;
        out[o] = qimg[o] + t[x][r];
    }
}

// ---------------- host launcher ----------------
extern "C" void kernel_launch(void* const* d_in, const int* in_sizes, int n_in,
                              void* d_out, int out_size) {
    const float* qimg   = (const float*)d_in[0];
    const float* kimg   = (const float*)d_in[1];
    const float* vimg   = (const float*)d_in[2];
    const float* grn1_g = (const float*)d_in[3];
    const float* grn1_b = (const float*)d_in[4];
    const float* q_w    = (const float*)d_in[5];
    const float* q_b    = (const float*)d_in[6];
    const float* k_w    = (const float*)d_in[7];
    const float* k_b    = (const float*)d_in[8];
    const float* v_w    = (const float*)d_in[9];
    const float* v_b    = (const float*)d_in[10];
    const float* o_w    = (const float*)d_in[11];
    const float* o_b    = (const float*)d_in[12];
    const float* lnq_w  = (const float*)d_in[13];
    const float* lnq_b  = (const float*)d_in[14];
    const float* lnk_w  = (const float*)d_in[15];
    const float* lnk_b  = (const float*)d_in[16];
    const float* ascal  = (const float*)d_in[17];
    const float* grn2_g = (const float*)d_in[18];
    const float* grn2_b = (const float*)d_in[19];
    const float* w1     = (const float*)d_in[20];
    const float* b1     = (const float*)d_in[21];
    const float* w2     = (const float*)d_in[22];
    const float* b2     = (const float*)d_in[23];
    const float* fscal  = (const float*)d_in[24];
    const float* finscal= (const float*)d_in[25];

    float *work, *kv, *sumsq, *meang;
    h16 *xh, *wh, *hh, *o1, *o2;
    cudaGetSymbolAddress((void**)&work, g_work);
    cudaGetSymbolAddress((void**)&xh,   g_x);
    cudaGetSymbolAddress((void**)&wh,   g_w);
    cudaGetSymbolAddress((void**)&hh,   g_h);
    cudaGetSymbolAddress((void**)&o1,   g_o1);
    cudaGetSymbolAddress((void**)&o2,   g_o2);
    cudaGetSymbolAddress((void**)&kv,   g_kv);
    cudaGetSymbolAddress((void**)&sumsq,g_sumsq);
    cudaGetSymbolAddress((void**)&meang,g_meangx);
    float* ksum = kv + BB*HH*DD*DD;

    h16* qh = hh;                         // q/k/v alias ffn hidden (dead by then)
    h16* kh = hh + (long)BNS*EE;
    h16* vh = hh + 2L*BNS*EE;
    // weight slots inside g_w
    h16 *w_q = wh, *w_k = wh + M1, *w_v = wh + 2*M1, *w_o = wh + 3*M1;
    h16 *w_1 = wh + 4*M1, *w_2 = wh + 8*M1;

    cudaFuncSetAttribute(gemm_hmma<0>, cudaFuncAttributeMaxDynamicSharedMemorySize, GSMEM);
    cudaFuncSetAttribute(gemm_hmma<1>, cudaFuncAttributeMaxDynamicSharedMemorySize, GSMEM);
    cudaFuncSetAttribute(gemm_hmma<2>, cudaFuncAttributeMaxDynamicSharedMemorySize, GSMEM);

    const long ES = (long)EE * SS;
    dim3 tgrid(SS/32, EE/32, BB);
    dim3 tblk(32, 8);
    dim3 pgrid(EE/128, BNS/128);

    // All weight conversions in one launch (independent of everything else)
    cvt_weights<<<1184, 256>>>(q_w, k_w, v_w, o_w, w1, w2, wh);

    // GRN1 on query image (apply fused with transpose + fp16 convert)
    grn_sumsq_cm<<<BB*EE, 256>>>(qimg, sumsq);
    grn_mean<<<BB, 256>>>(sumsq, meang);
    grn1_T<<<tgrid, tblk>>>(qimg, sumsq, meang, grn1_g, grn1_b, xh);

    // Q projection -> fp16
    gemm_hmma<2><<<pgrid, 128, GSMEM>>>(xh, w_q, q_b, nullptr, qh, BNS, EE, EE);
    // K projection
    cvt_T<<<tgrid, tblk>>>(kimg, xh);
    gemm_hmma<2><<<pgrid, 128, GSMEM>>>(xh, w_k, k_b, nullptr, kh, BNS, EE, EE);
    // V projection
    cvt_T<<<tgrid, tblk>>>(vimg, xh);
    gemm_hmma<2><<<pgrid, 128, GSMEM>>>(xh, w_v, v_b, nullptr, vh, BNS, EE, EE);

    // LayerNorm + elu+1 on q and k (one launch, in place, fp16)
    ln_elu_h2<<<2*BNS, 256>>>(qh, kh, lnq_w, lnq_b, lnk_w, lnk_b);

    // linear attention (fp16 in, fp16 out)
    zero_f<<<(BB*HH*DD*DD + BB*HH*DD + 255)/256, 256>>>(kv, BB*HH*DD*DD + BB*HH*DD);
    kvsum_kernel<<<dim3(BB*HH, 16), 256>>>(kh, vh, kv, ksum);
    attn_apply_kernel<<<dim3(BB*HH, SS/64), 256>>>(qh, kv, ksum, xh);

    // O projection -> fp16 o1
    gemm_hmma<2><<<pgrid, 128, GSMEM>>>(xh, w_o, o_b, nullptr, o1, BNS, EE, EE);

    // working = qimg^T + oproj * ascal (+ fused GRN2 sumsq)
    zero_f<<<(BB*EE + 255)/256, 256>>>(sumsq, BB*EE);
    make_working<<<tgrid, tblk>>>(qimg, o1, ascal, work, sumsq);
    grn_mean<<<BB, 256>>>(sumsq, meang);
    grn2_apply<<<(int)(BB*ES/1024), 256>>>(work, sumsq, meang, grn2_g, grn2_b, xh);

    // FFN1: silu epilogue -> fp16 hidden
    gemm_hmma<1><<<dim3(E4/128, BNS/128), 128, GSMEM>>>(xh, w_1, b1,
        nullptr, hh, BNS, E4, EE);

    // FFN2 -> fp16 o2
    gemm_hmma<2><<<pgrid, 128, GSMEM>>>(hh, w_2, b2, nullptr, o2, BNS, EE, E4);

    // final residual (transpose back to channel-major)
    final_kernel<<<tgrid, tblk>>>(qimg, work, o2, fscal, finscal, (float*)d_out);
}

// round 10
// speedup vs baseline: 2.5129x; 1.0652x over previous
#include <cuda_runtime.h>
#include <cuda_fp16.h>
#include <math.h>
#include <stdint.h>

// Problem constants
#define BB 2
#define EE 1024
#define HH 16
#define DD 64
#define SS 4096            // 64*64 spatial tokens per batch
#define BNS (BB*SS)        // 8192 total tokens
#define E4 (4*EE)          // 4096 ffn hidden

typedef __half h16;
typedef __half2 h162;

#define M1 (1L<<20)        // 1M elements (EE*EE)

// ---------------- device scratch ----------------
__device__ h16   g_work[(long)BNS*EE];        // fp16 working residual
__device__ h16   g_x   [(long)BNS*EE];        // fp16 GEMM A staging
__device__ h16   g_w   [12*M1];               // all 6 weights fp16: q|k|v|o|w1|w2
__device__ h16   g_h   [(long)BNS*E4];        // fp16: q|k|v slices, later ffn hidden
__device__ h16   g_o1  [(long)BNS*EE];        // fp16 o-proj out
__device__ h16   g_o2  [(long)BNS*EE];        // fp16 ffn2 out
__device__ float g_kv  [BB*HH*DD*DD + BB*HH*DD];  // kv | ksum
__device__ float g_sumsq[BB*EE];
__device__ float g_meangx[BB];

// ================= helpers =================
__device__ __forceinline__ uint32_t smem_u32(const void* p) {
    uint32_t a;
    asm("{ .reg .u64 t; cvta.to.shared.u64 t, %1; cvt.u32.u64 %0, t; }" : "=r"(a) : "l"(p));
    return a;
}
__device__ __forceinline__ void cp16(uint32_t dst, const void* src) {
    asm volatile("cp.async.cg.shared.global [%0], [%1], 16;" :: "r"(dst), "l"(src));
}
__device__ __forceinline__ uint32_t lds32(uint32_t a) {
    uint32_t v;
    asm volatile("ld.shared.u32 %0, [%1];" : "=r"(v) : "r"(a));
    return v;
}
__device__ __forceinline__ void mma16816(float* c, const uint32_t* a, const uint32_t* b) {
    asm volatile(
        "mma.sync.aligned.m16n8k16.row.col.f32.f16.f16.f32 "
        "{%0,%1,%2,%3}, {%4,%5,%6,%7}, {%8,%9}, {%0,%1,%2,%3};"
        : "+f"(c[0]), "+f"(c[1]), "+f"(c[2]), "+f"(c[3])
        : "r"(a[0]), "r"(a[1]), "r"(a[2]), "r"(a[3]), "r"(b[0]), "r"(b[1]));
}

// ================= GEMM: C[M,N] = A W^T + bias (fp16) =====
// Block 128x128, KT=64, 4 warps (2 M x 2 N), warp tile 64x64, 2-stage cp.async.
// EPI 0: fp32 out. EPI 1: silu -> fp16. EPI 2: fp16 out.
#define TPITCH 144
#define TBYTES (128*TPITCH)          // 18432
#define STAGEB (2*TBYTES)            // 36864
#define GSMEM  (2*STAGEB)            // 73728

template<int EPI>
__global__ __launch_bounds__(128, 2) void gemm_hmma(
    const h16* __restrict__ A, const h16* __restrict__ W,
    const float* __restrict__ bias,
    float* __restrict__ C, h16* __restrict__ CH,
    int M, int N, int K)
{
    extern __shared__ char sm[];
    const uint32_t sbase = smem_u32(sm);
    const int tid = threadIdx.x;
    const int lane = tid & 31, wid = tid >> 5;
    const int warp_m = wid >> 1, warp_n = wid & 1;
    const int m0 = blockIdx.y * 128, n0 = blockIdx.x * 128;
    const int lrow = lane >> 2, lpair = lane & 3;

    float acc[4][8][4];
    #pragma unroll
    for (int i = 0; i < 4; i++)
        #pragma unroll
        for (int j = 0; j < 8; j++)
            #pragma unroll
            for (int t = 0; t < 4; t++) acc[i][j][t] = 0.f;

    const int nk = K >> 6;

    auto load_stage = [&](int buf, int kc) {
        const long kq = (long)kc * 64;
        uint32_t sb = sbase + buf * STAGEB;
        #pragma unroll
        for (int i = 0; i < 8; i++) {
            int p = tid + i * 128;
            int row = p >> 3, ch = p & 7;
            uint32_t d = sb + row * TPITCH + ch * 16;
            cp16(d,          A + (long)(m0 + row) * K + kq + ch * 8);
            cp16(d + TBYTES, W + (long)(n0 + row) * K + kq + ch * 8);
        }
        asm volatile("cp.async.commit_group;");
    };

    load_stage(0, 0);
    if (nk > 1) load_stage(1, 1);

    for (int kc = 0; kc < nk; kc++) {
        const int buf = kc & 1;
        if (kc + 1 < nk) asm volatile("cp.async.wait_group 1;");
        else             asm volatile("cp.async.wait_group 0;");
        __syncthreads();

        const uint32_t aB = sbase + buf * STAGEB;
        const uint32_t bB = aB + TBYTES;

        #pragma unroll
        for (int s = 0; s < 4; s++) {
            const uint32_t koff = (s * 8 + lpair) * 4;
            uint32_t aF[4][4], bF[8][2];
            #pragma unroll
            for (int mt = 0; mt < 4; mt++) {
                uint32_t r = (warp_m * 64 + mt * 16 + lrow) * TPITCH;
                aF[mt][0] = lds32(aB + r + koff);
                aF[mt][1] = lds32(aB + r + 8*TPITCH + koff);
                aF[mt][2] = lds32(aB + r + koff + 16);
                aF[mt][3] = lds32(aB + r + 8*TPITCH + koff + 16);
            }
            #pragma unroll
            for (int nt = 0; nt < 8; nt++) {
                uint32_t r = (warp_n * 64 + nt * 8 + lrow) * TPITCH;
                bF[nt][0] = lds32(bB + r + koff);
                bF[nt][1] = lds32(bB + r + koff + 16);
            }
            #pragma unroll
            for (int mt = 0; mt < 4; mt++)
                #pragma unroll
                for (int nt = 0; nt < 8; nt++)
                    mma16816(acc[mt][nt], aF[mt], bF[nt]);
        }
        __syncthreads();
        if (kc + 2 < nk) load_stage(buf, kc + 2);
    }

    // ---- epilogue ----
    #pragma unroll
    for (int mt = 0; mt < 4; mt++) {
        #pragma unroll
        for (int nt = 0; nt < 8; nt++) {
            long row = m0 + warp_m * 64 + mt * 16 + lrow;
            int col = n0 + warp_n * 64 + nt * 8 + lpair * 2;
            float b0 = bias[col], b1 = bias[col + 1];
            #pragma unroll
            for (int half = 0; half < 2; half++) {
                long r = row + half * 8;
                float v0 = acc[mt][nt][half*2 + 0] + b0;
                float v1 = acc[mt][nt][half*2 + 1] + b1;
                if (EPI == 0) {
                    *(float2*)(C + r * N + col) = make_float2(v0, v1);
                } else if (EPI == 1) {
                    v0 = v0 / (1.f + expf(-v0));
                    v1 = v1 / (1.f + expf(-v1));
                    *(h162*)(CH + r * N + col) = __floats2half2_rn(v0, v1);
                } else {
                    *(h162*)(CH + r * N + col) = __floats2half2_rn(v0, v1);
                }
            }
        }
    }
}

// ================= converters =================
// all 6 weight matrices -> fp16 in one grid-stride launch
__global__ __launch_bounds__(256) void cvt_weights(
    const float* __restrict__ qw, const float* __restrict__ kw,
    const float* __restrict__ vw, const float* __restrict__ ow,
    const float* __restrict__ w1, const float* __restrict__ w2,
    h16* __restrict__ out)
{
    const long total = 12 * M1;
    const long stride = (long)gridDim.x * blockDim.x * 4;
    for (long i = ((long)blockIdx.x * blockDim.x + threadIdx.x) * 4; i < total;
         i += stride) {
        const float* src;
        long off;
        if (i < 4*M1) {
            int seg = (int)(i >> 20);
            src = (seg == 0) ? qw : (seg == 1) ? kw : (seg == 2) ? vw : ow;
            off = i & (M1 - 1);
        } else if (i < 8*M1) { src = w1; off = i - 4*M1; }
        else                 { src = w2; off = i - 8*M1; }
        float4 v = *(const float4*)(src + off);
        *(h162*)(out + i)     = __floats2half2_rn(v.x, v.y);
        *(h162*)(out + i + 2) = __floats2half2_rn(v.z, v.w);
    }
}

// transpose [B,E,S] fp32 -> [B,S,E] fp16  (64x64 tile, float4 both sides)
__global__ __launch_bounds__(256) void cvt_T(const float* __restrict__ x,
                                             h16* __restrict__ o) {
    __shared__ float t[64][65];
    int sx = blockIdx.x * 64, cy = blockIdx.y * 64, b = blockIdx.z;
    int tid = threadIdx.x;
    int row = tid >> 4, col4 = (tid & 15) * 4;
    #pragma unroll
    for (int r = 0; r < 64; r += 16) {
        float4 v = *(const float4*)(x + ((long)b*EE + cy + row + r)*SS + sx + col4);
        t[row+r][col4+0] = v.x; t[row+r][col4+1] = v.y;
        t[row+r][col4+2] = v.z; t[row+r][col4+3] = v.w;
    }
    __syncthreads();
    #pragma unroll
    for (int r = 0; r < 64; r += 16) {
        int s = row + r;
        long oi = ((long)b*SS + sx + s)*EE + cy + col4;
        *(h162*)(o + oi)     = __floats2half2_rn(t[col4+0][s], t[col4+1][s]);
        *(h162*)(o + oi + 2) = __floats2half2_rn(t[col4+2][s], t[col4+3][s]);
    }
}

// GRN1 apply fused with transpose + fp16 convert (64x64 tile)
__global__ __launch_bounds__(256) void grn1_T(const float* __restrict__ x,
                       const float* __restrict__ sumsq,
                       const float* __restrict__ meangx,
                       const float* __restrict__ gamma,
                       const float* __restrict__ beta,
                       h16* __restrict__ o) {
    __shared__ float t[64][65];
    int sx = blockIdx.x * 64, cy = blockIdx.y * 64, b = blockIdx.z;
    int tid = threadIdx.x;
    int row = tid >> 4, col4 = (tid & 15) * 4;
    #pragma unroll
    for (int r = 0; r < 64; r += 16) {
        float4 v = *(const float4*)(x + ((long)b*EE + cy + row + r)*SS + sx + col4);
        t[row+r][col4+0] = v.x; t[row+r][col4+1] = v.y;
        t[row+r][col4+2] = v.z; t[row+r][col4+3] = v.w;
    }
    __syncthreads();
    float4 sq = *(const float4*)(sumsq + b*EE + cy + col4);
    float4 g4 = *(const float4*)(gamma + cy + col4);
    float4 b4 = *(const float4*)(beta + cy + col4);
    float mg = meangx[b] + 1e-6f;
    float nx0 = sqrtf(sq.x)/mg, nx1 = sqrtf(sq.y)/mg;
    float nx2 = sqrtf(sq.z)/mg, nx3 = sqrtf(sq.w)/mg;
    #pragma unroll
    for (int r = 0; r < 64; r += 16) {
        int s = row + r;
        float v0 = t[col4+0][s], v1 = t[col4+1][s];
        float v2 = t[col4+2][s], v3 = t[col4+3][s];
        float o0 = (1.f+g4.x)*v0*nx0 + b4.x + v0;
        float o1 = (1.f+g4.y)*v1*nx1 + b4.y + v1;
        float o2 = (1.f+g4.z)*v2*nx2 + b4.z + v2;
        float o3 = (1.f+g4.w)*v3*nx3 + b4.w + v3;
        long oi = ((long)b*SS + sx + s)*EE + cy + col4;
        *(h162*)(o + oi)     = __floats2half2_rn(o0, o1);
        *(h162*)(o + oi + 2) = __floats2half2_rn(o2, o3);
    }
}

// ---------------- small helpers ----------------
__inline__ __device__ void blockReduce2(float& a, float& b) {
    #pragma unroll
    for (int off = 16; off > 0; off >>= 1) {
        a += __shfl_down_sync(0xffffffffu, a, off);
        b += __shfl_down_sync(0xffffffffu, b, off);
    }
    __shared__ float sa[8], sb[8];
    int w = threadIdx.x >> 5, l = threadIdx.x & 31;
    if (l == 0) { sa[w] = a; sb[w] = b; }
    __syncthreads();
    if (w == 0) {
        a = (l < 8) ? sa[l] : 0.f;
        b = (l < 8) ? sb[l] : 0.f;
        #pragma unroll
        for (int off = 4; off > 0; off >>= 1) {
            a += __shfl_down_sync(0xffu, a, off);
            b += __shfl_down_sync(0xffu, b, off);
        }
        if (l == 0) { sa[0] = a; sb[0] = b; }
    }
    __syncthreads();
    a = sa[0]; b = sb[0];
}

__global__ void zero_f(float* __restrict__ p, int n) {
    int i = blockIdx.x * blockDim.x + threadIdx.x;
    if (i < n) p[i] = 0.f;
}

// ---------------- GRN reductions ----------------
__global__ __launch_bounds__(256) void grn_sumsq_cm(const float* __restrict__ x,
                                                    float* __restrict__ sumsq) {
    const float* xr = x + (long)blockIdx.x * SS;
    float acc = 0.f, dummy = 0.f;
    for (int i = threadIdx.x * 4; i < SS; i += 1024) {
        float4 v = *(const float4*)(xr + i);
        acc += v.x*v.x + v.y*v.y + v.z*v.z + v.w*v.w;
    }
    blockReduce2(acc, dummy);
    if (threadIdx.x == 0) sumsq[blockIdx.x] = acc;
}

__global__ __launch_bounds__(256) void grn_mean(const float* __restrict__ sumsq,
                                                float* __restrict__ meangx) {
    int b = blockIdx.x;
    float s = 0.f, dummy = 0.f;
    for (int c = threadIdx.x; c < EE; c += 256) s += sqrtf(sumsq[b*EE + c]);
    blockReduce2(s, dummy);
    if (threadIdx.x == 0) meangx[b] = s / (float)EE;
}

// GRN2 apply, token-major fp16 in, fp16 out
__global__ __launch_bounds__(256) void grn2_apply(const h16* __restrict__ x,
                                                  const float* __restrict__ sumsq,
                                                  const float* __restrict__ meangx,
                                                  const float* __restrict__ gamma,
                                                  const float* __restrict__ beta,
                                                  h16* __restrict__ o) {
    long i4 = ((long)blockIdx.x * 256 + threadIdx.x) * 4;
    int c0 = (int)(i4 & 1023);
    int b = (int)(i4 >> 22);
    float4 g4 = *(const float4*)(gamma + c0);
    float4 b4 = *(const float4*)(beta + c0);
    float4 s4 = *(const float4*)(sumsq + b*EE + c0);
    float mg = meangx[b] + 1e-6f;
    h162 xa = *(const h162*)(x + i4), xb = *(const h162*)(x + i4 + 2);
    float v0 = __half2float(xa.x), v1 = __half2float(xa.y);
    float v2 = __half2float(xb.x), v3 = __half2float(xb.y);
    float o0 = (1.f+g4.x) * v0 * (sqrtf(s4.x)/mg) + b4.x + v0;
    float o1 = (1.f+g4.y) * v1 * (sqrtf(s4.y)/mg) + b4.y + v1;
    float o2 = (1.f+g4.z) * v2 * (sqrtf(s4.z)/mg) + b4.z + v2;
    float o3 = (1.f+g4.w) * v3 * (sqrtf(s4.w)/mg) + b4.w + v3;
    *(h162*)(o + i4)     = __floats2half2_rn(o0, o1);
    *(h162*)(o + i4 + 2) = __floats2half2_rn(o2, o3);
}

// ---------------- LayerNorm + (elu+1), fp16 in/out, q & k in one launch ----
__global__ __launch_bounds__(256) void ln_elu_h2(h16* __restrict__ q,
                                                 h16* __restrict__ k,
                                                 const float* __restrict__ wq,
                                                 const float* __restrict__ bq,
                                                 const float* __restrict__ wk,
                                                 const float* __restrict__ bk) {
    int row = blockIdx.x;
    h16* xp;
    const float *w, *b;
    if (row < BNS) { xp = q + (long)row * EE; w = wq; b = bq; }
    else           { xp = k + (long)(row - BNS) * EE; w = wk; b = bk; }
    h162* xr = (h162*)xp;
    int tid = threadIdx.x;
    h162 p0 = xr[tid*2], p1 = xr[tid*2 + 1];
    float v0 = __half2float(p0.x), v1 = __half2float(p0.y);
    float v2 = __half2float(p1.x), v3 = __half2float(p1.y);
    float s  = v0 + v1 + v2 + v3;
    float sq = v0*v0 + v1*v1 + v2*v2 + v3*v3;
    blockReduce2(s, sq);
    float mean = s / (float)EE;
    float var = sq / (float)EE - mean*mean;
    float rstd = rsqrtf(var + 1e-5f);
    float4 wv = *(const float4*)(w + tid*4);
    float4 bv = *(const float4*)(b + tid*4);
    float y;
    y = (v0-mean)*rstd*wv.x + bv.x; v0 = (y > 0.f) ? y + 1.f : expf(y);
    y = (v1-mean)*rstd*wv.y + bv.y; v1 = (y > 0.f) ? y + 1.f : expf(y);
    y = (v2-mean)*rstd*wv.z + bv.z; v2 = (y > 0.f) ? y + 1.f : expf(y);
    y = (v3-mean)*rstd*wv.w + bv.w; v3 = (y > 0.f) ? y + 1.f : expf(y);
    xr[tid*2]     = __floats2half2_rn(v0, v1);
    xr[tid*2 + 1] = __floats2half2_rn(v2, v3);
}

// ---------------- linear attention (fp16 inputs) ----------------
__global__ __launch_bounds__(256) void kvsum_kernel(const h16* __restrict__ k,
                                                    const h16* __restrict__ v,
                                                    float* __restrict__ kv,
                                                    float* __restrict__ ksum) {
    int bh = blockIdx.x;
    int b = bh >> 4, h = bh & 15;
    int tid = threadIdx.x;
    __shared__ float ks[16][68], vs[16][68];
    int d0 = (tid >> 4) * 4, e0 = (tid & 15) * 4;
    float acc[4][4] = {};
    float accks[4] = {};
    long base = ((long)b * SS + (long)blockIdx.y * 256) * EE + h * DD;
    int ltok = tid >> 4, lc = (tid & 15) * 4;
    for (int t0 = 0; t0 < 256; t0 += 16) {
        long gi = base + (long)(t0+ltok)*EE + lc;
        h162 ka = *(const h162*)(k + gi), kb2 = *(const h162*)(k + gi + 2);
        h162 va = *(const h162*)(v + gi), vb2 = *(const h162*)(v + gi + 2);
        ks[ltok][lc+0] = __half2float(ka.x); ks[ltok][lc+1] = __half2float(ka.y);
        ks[ltok][lc+2] = __half2float(kb2.x); ks[ltok][lc+3] = __half2float(kb2.y);
        vs[ltok][lc+0] = __half2float(va.x); vs[ltok][lc+1] = __half2float(va.y);
        vs[ltok][lc+2] = __half2float(vb2.x); vs[ltok][lc+3] = __half2float(vb2.y);
        __syncthreads();
        #pragma unroll
        for (int t = 0; t < 16; t++) {
            float a[4], bb[4];
            #pragma unroll
            for (int i = 0; i < 4; i++) a[i] = ks[t][d0+i];
            #pragma unroll
            for (int j = 0; j < 4; j++) bb[j] = vs[t][e0+j];
            #pragma unroll
            for (int i = 0; i < 4; i++)
                #pragma unroll
                for (int j = 0; j < 4; j++) acc[i][j] += a[i]*bb[j];
            if (e0 == 0) {
                #pragma unroll
                for (int i = 0; i < 4; i++) accks[i] += a[i];
            }
        }
        __syncthreads();
    }
    long kvbase = (long)bh * DD * DD;
    #pragma unroll
    for (int i = 0; i < 4; i++)
        #pragma unroll
        for (int j = 0; j < 4; j++)
            atomicAdd(&kv[kvbase + (d0+i)*DD + e0+j], acc[i][j]);
    if (e0 == 0)
        #pragma unroll
        for (int i = 0; i < 4; i++) atomicAdd(&ksum[bh*DD + d0+i], accks[i]);
}

// attn = (q @ kv) / (q . ksum + 1e-8), fp16 in, fp16 out
__global__ __launch_bounds__(256) void attn_apply_kernel(const h16* __restrict__ q,
                                                         const float* __restrict__ kv,
                                                         const float* __restrict__ ksum,
                                                         h16* __restrict__ o) {
    int bh = blockIdx.x, sblk = blockIdx.y;
    int b = bh >> 4, h = bh & 15;
    int tid = threadIdx.x;
    __shared__ float qs[64][68];
    __shared__ float kvs[64][64];
    __shared__ float kss[64];
    long kvbase = (long)bh * DD * DD;
    #pragma unroll
    for (int r = 0; r < 4; r++) {
        int idx = (r*256 + tid) * 4;
        *(float4*)&kvs[idx >> 6][idx & 63] = *(const float4*)(kv + kvbase + idx);
    }
    if (tid < 64) kss[tid] = ksum[bh*DD + tid];
    long qbase = ((long)b * SS + (long)sblk * 64) * EE + h * DD;
    int ltok = tid >> 4, lc = (tid & 15) * 4;
    #pragma unroll
    for (int r = 0; r < 4; r++) {
        long gi = qbase + (long)(ltok + r*16)*EE + lc;
        h162 qa = *(const h162*)(q + gi), qb2 = *(const h162*)(q + gi + 2);
        qs[ltok + r*16][lc+0] = __half2float(qa.x);
        qs[ltok + r*16][lc+1] = __half2float(qa.y);
        qs[ltok + r*16][lc+2] = __half2float(qb2.x);
        qs[ltok + r*16][lc+3] = __half2float(qb2.y);
    }
    __syncthreads();
    int tok = tid >> 2, e0 = (tid & 3) * 16;
    float num[16] = {};
    float den = 0.f;
    #pragma unroll 8
    for (int d = 0; d < 64; d++) {
        float qd = qs[tok][d];
        den += qd * kss[d];
        #pragma unroll
        for (int j = 0; j < 16; j++) num[j] += qd * kvs[d][e0+j];
    }
    float r = 1.f / (den + 1e-8f);
    long obase = ((long)b * SS + (long)sblk * 64 + tok) * EE + h * DD + e0;
    #pragma unroll
    for (int j = 0; j < 16; j += 2)
        *(h162*)(o + obase + j) = __floats2half2_rn(num[j] * r, num[j+1] * r);
}

// ---------------- residual / transpose kernels (64x64 tiles) ----------------
// work(fp16) = qimg^T + oproj*ascal + fused GRN2 sumsq (from fp32 values)
__global__ __launch_bounds__(256) void make_working(const float* __restrict__ qimg,
                             const h16* __restrict__ attn_out,
                             const float* __restrict__ ascal,
                             h16* __restrict__ work,
                             float* __restrict__ sumsq) {
    __shared__ float t[64][65];
    __shared__ float ssq[64];
    int sx = blockIdx.x * 64, cy = blockIdx.y * 64, b = blockIdx.z;
    int tid = threadIdx.x;
    int row = tid >> 4, col4 = (tid & 15) * 4;
    #pragma unroll
    for (int r = 0; r < 64; r += 16) {
        float4 v = *(const float4*)(qimg + ((long)b*EE + cy + row + r)*SS + sx + col4);
        t[row+r][col4+0] = v.x; t[row+r][col4+1] = v.y;
        t[row+r][col4+2] = v.z; t[row+r][col4+3] = v.w;
    }
    if (tid < 64) ssq[tid] = 0.f;
    __syncthreads();
    float4 asc = *(const float4*)(ascal + cy + col4);
    float a0 = 0.f, a1 = 0.f, a2 = 0.f, a3 = 0.f;
    #pragma unroll
    for (int r = 0; r < 64; r += 16) {
        int s = row + r;
        long o = ((long)b*SS + sx + s)*EE + cy + col4;
        h162 at0 = *(const h162*)(attn_out + o);
        h162 at1 = *(const h162*)(attn_out + o + 2);
        float w0 = t[col4+0][s] + __half2float(at0.x) * asc.x;
        float w1 = t[col4+1][s] + __half2float(at0.y) * asc.y;
        float w2 = t[col4+2][s] + __half2float(at1.x) * asc.z;
        float w3 = t[col4+3][s] + __half2float(at1.y) * asc.w;
        *(h162*)(work + o)     = __floats2half2_rn(w0, w1);
        *(h162*)(work + o + 2) = __floats2half2_rn(w2, w3);
        a0 += w0*w0; a1 += w1*w1; a2 += w2*w2; a3 += w3*w3;
    }
    atomicAdd(&ssq[col4+0], a0);
    atomicAdd(&ssq[col4+1], a1);
    atomicAdd(&ssq[col4+2], a2);
    atomicAdd(&ssq[col4+3], a3);
    __syncthreads();
    if (tid < 64) atomicAdd(&sumsq[b*EE + cy + tid], ssq[tid]);
}

__global__ __launch_bounds__(256) void final_kernel(const float* __restrict__ qimg,
                             const h16* __restrict__ work,
                             const h16* __restrict__ ffn,
                             const float* __restrict__ fscal,
                             const float* __restrict__ finscal,
                             float* __restrict__ out) {
    __shared__ float t[64][65];
    int sx = blockIdx.x * 64, cy = blockIdx.y * 64, b = blockIdx.z;
    int tid = threadIdx.x;
    int row = tid >> 4, col4 = (tid & 15) * 4;
    float4 fs = *(const float4*)(fscal + cy + col4);
    float4 fin = *(const float4*)(finscal + cy + col4);
    #pragma unroll
    for (int r = 0; r < 64; r += 16) {
        int s = row + r;
        long o = ((long)b*SS + sx + s)*EE + cy + col4;
        h162 w0 = *(const h162*)(work + o), w1 = *(const h162*)(work + o + 2);
        h162 f0 = *(const h162*)(ffn + o),  f1 = *(const h162*)(ffn + o + 2);
        t[s][col4+0] = (__half2float(w0.x) + __half2float(f0.x)*fs.x)*fin.x;
        t[s][col4+1] = (__half2float(w0.y) + __half2float(f0.y)*fs.y)*fin.y;
        t[s][col4+2] = (__half2float(w1.x) + __half2float(f1.x)*fs.z)*fin.z;
        t[s][col4+3] = (__half2float(w1.y) + __half2float(f1.y)*fs.w)*fin.w;
    }
    __syncthreads();
    #pragma unroll
    for (int r = 0; r < 64; r += 16) {
        int c = row + r;
        long o = ((long)b*EE + cy + c)*SS + sx + col4;
        float4 qv = *(const float4*)(qimg + o);
        float4 ov;
        ov.x = qv.x + t[col4+0][c];
        ov.y = qv.y + t[col4+1][c];
        ov.z = qv.z + t[col4+2][c];
        ov.w = qv.w + t[col4+3][c];
        *(float4*)(out + o) = ov;
    }
}

// ---------------- host launcher ----------------
extern "C" void kernel_launch(void* const* d_in, const int* in_sizes, int n_in,
                              void* d_out, int out_size) {
    const float* qimg   = (const float*)d_in[0];
    const float* kimg   = (const float*)d_in[1];
    const float* vimg   = (const float*)d_in[2];
    const float* grn1_g = (const float*)d_in[3];
    const float* grn1_b = (const float*)d_in[4];
    const float* q_w    = (const float*)d_in[5];
    const float* q_b    = (const float*)d_in[6];
    const float* k_w    = (const float*)d_in[7];
    const float* k_b    = (const float*)d_in[8];
    const float* v_w    = (const float*)d_in[9];
    const float* v_b    = (const float*)d_in[10];
    const float* o_w    = (const float*)d_in[11];
    const float* o_b    = (const float*)d_in[12];
    const float* lnq_w  = (const float*)d_in[13];
    const float* lnq_b  = (const float*)d_in[14];
    const float* lnk_w  = (const float*)d_in[15];
    const float* lnk_b  = (const float*)d_in[16];
    const float* ascal  = (const float*)d_in[17];
    const float* grn2_g = (const float*)d_in[18];
    const float* grn2_b = (const float*)d_in[19];
    const float* w1     = (const float*)d_in[20];
    const float* b1     = (const float*)d_in[21];
    const float* w2     = (const float*)d_in[22];
    const float* b2     = (const float*)d_in[23];
    const float* fscal  = (const float*)d_in[24];
    const float* finscal= (const float*)d_in[25];

    float *kv, *sumsq, *meang;
    h16 *work, *xh, *wh, *hh, *o1, *o2;
    cudaGetSymbolAddress((void**)&work, g_work);
    cudaGetSymbolAddress((void**)&xh,   g_x);
    cudaGetSymbolAddress((void**)&wh,   g_w);
    cudaGetSymbolAddress((void**)&hh,   g_h);
    cudaGetSymbolAddress((void**)&o1,   g_o1);
    cudaGetSymbolAddress((void**)&o2,   g_o2);
    cudaGetSymbolAddress((void**)&kv,   g_kv);
    cudaGetSymbolAddress((void**)&sumsq,g_sumsq);
    cudaGetSymbolAddress((void**)&meang,g_meangx);
    float* ksum = kv + BB*HH*DD*DD;

    h16* qh = hh;                         // q/k/v alias ffn hidden (dead by then)
    h16* kh = hh + (long)BNS*EE;
    h16* vh = hh + 2L*BNS*EE;
    h16 *w_q = wh, *w_k = wh + M1, *w_v = wh + 2*M1, *w_o = wh + 3*M1;
    h16 *w_1 = wh + 4*M1, *w_2 = wh + 8*M1;

    cudaFuncSetAttribute(gemm_hmma<0>, cudaFuncAttributeMaxDynamicSharedMemorySize, GSMEM);
    cudaFuncSetAttribute(gemm_hmma<1>, cudaFuncAttributeMaxDynamicSharedMemorySize, GSMEM);
    cudaFuncSetAttribute(gemm_hmma<2>, cudaFuncAttributeMaxDynamicSharedMemorySize, GSMEM);

    const long ES = (long)EE * SS;
    dim3 tgrid(SS/64, EE/64, BB);
    dim3 pgrid(EE/128, BNS/128);

    // All weight conversions in one launch
    cvt_weights<<<1184, 256>>>(q_w, k_w, v_w, o_w, w1, w2, wh);

    // GRN1 on query image (apply fused with transpose + fp16 convert)
    grn_sumsq_cm<<<BB*EE, 256>>>(qimg, sumsq);
    grn_mean<<<BB, 256>>>(sumsq, meang);
    grn1_T<<<tgrid, 256>>>(qimg, sumsq, meang, grn1_g, grn1_b, xh);

    // Q projection -> fp16
    gemm_hmma<2><<<pgrid, 128, GSMEM>>>(xh, w_q, q_b, nullptr, qh, BNS, EE, EE);
    // K projection
    cvt_T<<<tgrid, 256>>>(kimg, xh);
    gemm_hmma<2><<<pgrid, 128, GSMEM>>>(xh, w_k, k_b, nullptr, kh, BNS, EE, EE);
    // V projection
    cvt_T<<<tgrid, 256>>>(vimg, xh);
    gemm_hmma<2><<<pgrid, 128, GSMEM>>>(xh, w_v, v_b, nullptr, vh, BNS, EE, EE);

    // LayerNorm + elu+1 on q and k (one launch, in place, fp16)
    ln_elu_h2<<<2*BNS, 256>>>(qh, kh, lnq_w, lnq_b, lnk_w, lnk_b);

    // linear attention (fp16 in, fp16 out)
    zero_f<<<(BB*HH*DD*DD + BB*HH*DD + 255)/256, 256>>>(kv, BB*HH*DD*DD + BB*HH*DD);
    kvsum_kernel<<<dim3(BB*HH, 16), 256>>>(kh, vh, kv, ksum);
    attn_apply_kernel<<<dim3(BB*HH, SS/64), 256>>>(qh, kv, ksum, xh);

    // O projection -> fp16 o1
    gemm_hmma<2><<<pgrid, 128, GSMEM>>>(xh, w_o, o_b, nullptr, o1, BNS, EE, EE);

    // working (fp16) = qimg^T + oproj * ascal (+ fused GRN2 sumsq)
    zero_f<<<(BB*EE + 255)/256, 256>>>(sumsq, BB*EE);
    make_working<<<tgrid, 256>>>(qimg, o1, ascal, work, sumsq);
    grn_mean<<<BB, 256>>>(sumsq, meang);
    grn2_apply<<<(int)(BB*ES/1024), 256>>>(work, sumsq, meang, grn2_g, grn2_b, xh);

    // FFN1: silu epilogue -> fp16 hidden
    gemm_hmma<1><<<dim3(E4/128, BNS/128), 128, GSMEM>>>(xh, w_1, b1,
        nullptr, hh, BNS, E4, EE);

    // FFN2 -> fp16 o2
    gemm_hmma<2><<<pgrid, 128, GSMEM>>>(hh, w_2, b2, nullptr, o2, BNS, EE, E4);

    // final residual (transpose back to channel-major)
    final_kernel<<<tgrid, 256>>>(qimg, work, o2, fscal, finscal, (float*)d_out);
}

// round 11
// speedup vs baseline: 2.5531x; 1.0160x over previous
#include <cuda_runtime.h>
#include <cuda_fp16.h>
#include <math.h>
#include <stdint.h>

// Problem constants
#define BB 2
#define EE 1024
#define HH 16
#define DD 64
#define SS 4096            // 64*64 spatial tokens per batch
#define BNS (BB*SS)        // 8192 total tokens
#define E4 (4*EE)          // 4096 ffn hidden

typedef __half h16;
typedef __half2 h162;

#define M1 (1L<<20)        // 1M elements (EE*EE)

// ---------------- device scratch ----------------
__device__ h16   g_work[(long)BNS*EE];        // fp16 working residual
__device__ h16   g_x   [(long)BNS*EE];        // fp16 staging (q-act / attn out / grn2 out)
__device__ h16   g_w   [12*M1];               // all 6 weights fp16: q|k|v|o|w1|w2
__device__ h16   g_h   [(long)BNS*E4];        // fp16: q|k|v slices, later ffn hidden
__device__ h16   g_o1  [(long)BNS*EE];        // fp16: k-act staging, later o-proj out
__device__ h16   g_o2  [(long)BNS*EE];        // fp16: v-act staging, later ffn2 out
__device__ float g_kv  [BB*HH*DD*DD + BB*HH*DD];  // kv | ksum
__device__ float g_sumsq[BB*EE];
__device__ float g_meangx[BB];

// ================= helpers =================
__device__ __forceinline__ uint32_t smem_u32(const void* p) {
    uint32_t a;
    asm("{ .reg .u64 t; cvta.to.shared.u64 t, %1; cvt.u32.u64 %0, t; }" : "=r"(a) : "l"(p));
    return a;
}
__device__ __forceinline__ void cp16(uint32_t dst, const void* src) {
    asm volatile("cp.async.cg.shared.global [%0], [%1], 16;" :: "r"(dst), "l"(src));
}
__device__ __forceinline__ uint32_t lds32(uint32_t a) {
    uint32_t v;
    asm volatile("ld.shared.u32 %0, [%1];" : "=r"(v) : "r"(a));
    return v;
}
__device__ __forceinline__ void mma16816(float* c, const uint32_t* a, const uint32_t* b) {
    asm volatile(
        "mma.sync.aligned.m16n8k16.row.col.f32.f16.f16.f32 "
        "{%0,%1,%2,%3}, {%4,%5,%6,%7}, {%8,%9}, {%0,%1,%2,%3};"
        : "+f"(c[0]), "+f"(c[1]), "+f"(c[2]), "+f"(c[3])
        : "r"(a[0]), "r"(a[1]), "r"(a[2]), "r"(a[3]), "r"(b[0]), "r"(b[1]));
}

// ================= GEMM: C[M,N] = A W^T + bias (fp16) =====
// CTA tile 128x64, KT=64, 4 warps (2 M x 2 N), warp tile 64x32.
// 2-stage cp.async; 3 CTAs/SM. grid.z batches independent GEMMs.
// EPI 1: silu -> fp16. EPI 2: fp16 out.
#define TPITCH 144
#define TBYTES_A (128*TPITCH)        // 18432
#define TBYTES_B (64*TPITCH)         // 9216
#define STAGEB (TBYTES_A + TBYTES_B) // 27648
#define GSMEM  (2*STAGEB)            // 55296

template<int EPI>
__global__ __launch_bounds__(128, 3) void gemm_hmma(
    const h16* __restrict__ A0, const h16* __restrict__ A1,
    const h16* __restrict__ A2,
    const h16* __restrict__ Wb, long wStride,
    const float* __restrict__ b0, const float* __restrict__ b1,
    const float* __restrict__ b2,
    h16* __restrict__ CHb, long cStride,
    int M, int N, int K)
{
    extern __shared__ char sm[];
    const uint32_t sbase = smem_u32(sm);
    const int tid = threadIdx.x;
    const int lane = tid & 31, wid = tid >> 5;
    const int warp_m = wid >> 1, warp_n = wid & 1;
    const int m0 = blockIdx.y * 128, n0 = blockIdx.x * 64;
    const int z = blockIdx.z;
    const int lrow = lane >> 2, lpair = lane & 3;

    const h16* A = (z == 0) ? A0 : (z == 1) ? A1 : A2;
    const float* bias = (z == 0) ? b0 : (z == 1) ? b1 : b2;
    const h16* W = Wb + (long)z * wStride;
    h16* CH = CHb + (long)z * cStride;

    float acc[4][4][4];
    #pragma unroll
    for (int i = 0; i < 4; i++)
        #pragma unroll
        for (int j = 0; j < 4; j++)
            #pragma unroll
            for (int t = 0; t < 4; t++) acc[i][j][t] = 0.f;

    const int nk = K >> 6;

    auto load_stage = [&](int buf, int kc) {
        const long kq = (long)kc * 64;
        uint32_t sb = sbase + buf * STAGEB;
        #pragma unroll
        for (int i = 0; i < 12; i++) {
            int p = tid + i * 128;
            int row = p >> 3, ch = p & 7;
            uint32_t d = sb + row * TPITCH + ch * 16;
            if (row < 128) cp16(d, A + (long)(m0 + row) * K + kq + ch * 8);
            else           cp16(d, W + (long)(n0 + row - 128) * K + kq + ch * 8);
        }
        asm volatile("cp.async.commit_group;");
    };

    load_stage(0, 0);
    if (nk > 1) load_stage(1, 1);

    for (int kc = 0; kc < nk; kc++) {
        const int buf = kc & 1;
        if (kc + 1 < nk) asm volatile("cp.async.wait_group 1;");
        else             asm volatile("cp.async.wait_group 0;");
        __syncthreads();

        const uint32_t aB = sbase + buf * STAGEB;
        const uint32_t bB = aB + TBYTES_A;

        #pragma unroll
        for (int s = 0; s < 4; s++) {
            const uint32_t koff = (s * 8 + lpair) * 4;
            uint32_t aF[4][4], bF[4][2];
            #pragma unroll
            for (int mt = 0; mt < 4; mt++) {
                uint32_t r = (warp_m * 64 + mt * 16 + lrow) * TPITCH;
                aF[mt][0] = lds32(aB + r + koff);
                aF[mt][1] = lds32(aB + r + 8*TPITCH + koff);
                aF[mt][2] = lds32(aB + r + koff + 16);
                aF[mt][3] = lds32(aB + r + 8*TPITCH + koff + 16);
            }
            #pragma unroll
            for (int nt = 0; nt < 4; nt++) {
                uint32_t r = (warp_n * 32 + nt * 8 + lrow) * TPITCH;
                bF[nt][0] = lds32(bB + r + koff);
                bF[nt][1] = lds32(bB + r + koff + 16);
            }
            #pragma unroll
            for (int mt = 0; mt < 4; mt++)
                #pragma unroll
                for (int nt = 0; nt < 4; nt++)
                    mma16816(acc[mt][nt], aF[mt], bF[nt]);
        }
        __syncthreads();
        if (kc + 2 < nk) load_stage(buf, kc + 2);
    }

    // ---- epilogue ----
    #pragma unroll
    for (int mt = 0; mt < 4; mt++) {
        #pragma unroll
        for (int nt = 0; nt < 4; nt++) {
            long row = m0 + warp_m * 64 + mt * 16 + lrow;
            int col = n0 + warp_n * 32 + nt * 8 + lpair * 2;
            float b0v = bias[col], b1v = bias[col + 1];
            #pragma unroll
            for (int half = 0; half < 2; half++) {
                long r = row + half * 8;
                float v0 = acc[mt][nt][half*2 + 0] + b0v;
                float v1 = acc[mt][nt][half*2 + 1] + b1v;
                if (EPI == 1) {
                    v0 = v0 / (1.f + expf(-v0));
                    v1 = v1 / (1.f + expf(-v1));
                }
                *(h162*)(CH + r * N + col) = __floats2half2_rn(v0, v1);
            }
        }
    }
}

// ================= converters =================
// all 6 weight matrices -> fp16 in one grid-stride launch
__global__ __launch_bounds__(256) void cvt_weights(
    const float* __restrict__ qw, const float* __restrict__ kw,
    const float* __restrict__ vw, const float* __restrict__ ow,
    const float* __restrict__ w1, const float* __restrict__ w2,
    h16* __restrict__ out)
{
    const long total = 12 * M1;
    const long stride = (long)gridDim.x * blockDim.x * 4;
    for (long i = ((long)blockIdx.x * blockDim.x + threadIdx.x) * 4; i < total;
         i += stride) {
        const float* src;
        long off;
        if (i < 4*M1) {
            int seg = (int)(i >> 20);
            src = (seg == 0) ? qw : (seg == 1) ? kw : (seg == 2) ? vw : ow;
            off = i & (M1 - 1);
        } else if (i < 8*M1) { src = w1; off = i - 4*M1; }
        else                 { src = w2; off = i - 8*M1; }
        float4 v = *(const float4*)(src + off);
        *(h162*)(out + i)     = __floats2half2_rn(v.x, v.y);
        *(h162*)(out + i + 2) = __floats2half2_rn(v.z, v.w);
    }
}

// batched transpose [B,E,S] fp32 -> [B,S,E] fp16 for 3 sources.
// grid.z = b + BB*src; src 0 = qimg with GRN1 applied, 1 = kimg, 2 = vimg.
__global__ __launch_bounds__(256) void trans3(
    const float* __restrict__ qimg, const float* __restrict__ kimg,
    const float* __restrict__ vimg,
    const float* __restrict__ sumsq, const float* __restrict__ meangx,
    const float* __restrict__ gamma, const float* __restrict__ beta,
    h16* __restrict__ oq, h16* __restrict__ ok, h16* __restrict__ ov)
{
    __shared__ float t[64][65];
    int bz = blockIdx.z;
    int b = bz % BB, src = bz / BB;
    const float* x = (src == 0) ? qimg : (src == 1) ? kimg : vimg;
    h16* o = (src == 0) ? oq : (src == 1) ? ok : ov;
    int sx = blockIdx.x * 64, cy = blockIdx.y * 64;
    int tid = threadIdx.x;
    int row = tid >> 4, col4 = (tid & 15) * 4;
    #pragma unroll
    for (int r = 0; r < 64; r += 16) {
        float4 v = *(const float4*)(x + ((long)b*EE + cy + row + r)*SS + sx + col4);
        t[row+r][col4+0] = v.x; t[row+r][col4+1] = v.y;
        t[row+r][col4+2] = v.z; t[row+r][col4+3] = v.w;
    }
    __syncthreads();
    float s0 = 1.f, s1 = 1.f, s2 = 1.f, s3 = 1.f;   // x multiplier
    float a0 = 0.f, a1 = 0.f, a2 = 0.f, a3 = 0.f;   // additive
    if (src == 0) {
        float4 sq = *(const float4*)(sumsq + b*EE + cy + col4);
        float4 g4 = *(const float4*)(gamma + cy + col4);
        float4 b4 = *(const float4*)(beta + cy + col4);
        float mg = meangx[b] + 1e-6f;
        s0 = 1.f + (1.f+g4.x)*sqrtf(sq.x)/mg;
        s1 = 1.f + (1.f+g4.y)*sqrtf(sq.y)/mg;
        s2 = 1.f + (1.f+g4.z)*sqrtf(sq.z)/mg;
        s3 = 1.f + (1.f+g4.w)*sqrtf(sq.w)/mg;
        a0 = b4.x; a1 = b4.y; a2 = b4.z; a3 = b4.w;
    }
    #pragma unroll
    for (int r = 0; r < 64; r += 16) {
        int s = row + r;
        float v0 = t[col4+0][s]*s0 + a0;
        float v1 = t[col4+1][s]*s1 + a1;
        float v2 = t[col4+2][s]*s2 + a2;
        float v3 = t[col4+3][s]*s3 + a3;
        long oi = ((long)b*SS + sx + s)*EE + cy + col4;
        *(h162*)(o + oi)     = __floats2half2_rn(v0, v1);
        *(h162*)(o + oi + 2) = __floats2half2_rn(v2, v3);
    }
}

// ---------------- small helpers ----------------
__inline__ __device__ void blockReduce2(float& a, float& b) {
    #pragma unroll
    for (int off = 16; off > 0; off >>= 1) {
        a += __shfl_down_sync(0xffffffffu, a, off);
        b += __shfl_down_sync(0xffffffffu, b, off);
    }
    __shared__ float sa[8], sb[8];
    int w = threadIdx.x >> 5, l = threadIdx.x & 31;
    if (l == 0) { sa[w] = a; sb[w] = b; }
    __syncthreads();
    if (w == 0) {
        a = (l < 8) ? sa[l] : 0.f;
        b = (l < 8) ? sb[l] : 0.f;
        #pragma unroll
        for (int off = 4; off > 0; off >>= 1) {
            a += __shfl_down_sync(0xffu, a, off);
            b += __shfl_down_sync(0xffu, b, off);
        }
        if (l == 0) { sa[0] = a; sb[0] = b; }
    }
    __syncthreads();
    a = sa[0]; b = sb[0];
}

__global__ void zero_f(float* __restrict__ p, int n) {
    int i = blockIdx.x * blockDim.x + threadIdx.x;
    if (i < n) p[i] = 0.f;
}

// ---------------- GRN reductions ----------------
__global__ __launch_bounds__(256) void grn_sumsq_cm(const float* __restrict__ x,
                                                    float* __restrict__ sumsq) {
    const float* xr = x + (long)blockIdx.x * SS;
    float acc = 0.f, dummy = 0.f;
    for (int i = threadIdx.x * 4; i < SS; i += 1024) {
        float4 v = *(const float4*)(xr + i);
        acc += v.x*v.x + v.y*v.y + v.z*v.z + v.w*v.w;
    }
    blockReduce2(acc, dummy);
    if (threadIdx.x == 0) sumsq[blockIdx.x] = acc;
}

__global__ __launch_bounds__(256) void grn_mean(const float* __restrict__ sumsq,
                                                float* __restrict__ meangx) {
    int b = blockIdx.x;
    float s = 0.f, dummy = 0.f;
    for (int c = threadIdx.x; c < EE; c += 256) s += sqrtf(sumsq[b*EE + c]);
    blockReduce2(s, dummy);
    if (threadIdx.x == 0) meangx[b] = s / (float)EE;
}

// GRN2 apply, token-major fp16 in, fp16 out
__global__ __launch_bounds__(256) void grn2_apply(const h16* __restrict__ x,
                                                  const float* __restrict__ sumsq,
                                                  const float* __restrict__ meangx,
                                                  const float* __restrict__ gamma,
                                                  const float* __restrict__ beta,
                                                  h16* __restrict__ o) {
    long i4 = ((long)blockIdx.x * 256 + threadIdx.x) * 4;
    int c0 = (int)(i4 & 1023);
    int b = (int)(i4 >> 22);
    float4 g4 = *(const float4*)(gamma + c0);
    float4 b4 = *(const float4*)(beta + c0);
    float4 s4 = *(const float4*)(sumsq + b*EE + c0);
    float mg = meangx[b] + 1e-6f;
    h162 xa = *(const h162*)(x + i4), xb = *(const h162*)(x + i4 + 2);
    float v0 = __half2float(xa.x), v1 = __half2float(xa.y);
    float v2 = __half2float(xb.x), v3 = __half2float(xb.y);
    float o0 = (1.f+g4.x) * v0 * (sqrtf(s4.x)/mg) + b4.x + v0;
    float o1 = (1.f+g4.y) * v1 * (sqrtf(s4.y)/mg) + b4.y + v1;
    float o2 = (1.f+g4.z) * v2 * (sqrtf(s4.z)/mg) + b4.z + v2;
    float o3 = (1.f+g4.w) * v3 * (sqrtf(s4.w)/mg) + b4.w + v3;
    *(h162*)(o + i4)     = __floats2half2_rn(o0, o1);
    *(h162*)(o + i4 + 2) = __floats2half2_rn(o2, o3);
}

// ---------------- LayerNorm + (elu+1), fp16 in/out, q & k in one launch ----
__global__ __launch_bounds__(256) void ln_elu_h2(h16* __restrict__ q,
                                                 h16* __restrict__ k,
                                                 const float* __restrict__ wq,
                                                 const float* __restrict__ bq,
                                                 const float* __restrict__ wk,
                                                 const float* __restrict__ bk) {
    int row = blockIdx.x;
    h16* xp;
    const float *w, *b;
    if (row < BNS) { xp = q + (long)row * EE; w = wq; b = bq; }
    else           { xp = k + (long)(row - BNS) * EE; w = wk; b = bk; }
    h162* xr = (h162*)xp;
    int tid = threadIdx.x;
    h162 p0 = xr[tid*2], p1 = xr[tid*2 + 1];
    float v0 = __half2float(p0.x), v1 = __half2float(p0.y);
    float v2 = __half2float(p1.x), v3 = __half2float(p1.y);
    float s  = v0 + v1 + v2 + v3;
    float sq = v0*v0 + v1*v1 + v2*v2 + v3*v3;
    blockReduce2(s, sq);
    float mean = s / (float)EE;
    float var = sq / (float)EE - mean*mean;
    float rstd = rsqrtf(var + 1e-5f);
    float4 wv = *(const float4*)(w + tid*4);
    float4 bv = *(const float4*)(b + tid*4);
    float y;
    y = (v0-mean)*rstd*wv.x + bv.x; v0 = (y > 0.f) ? y + 1.f : expf(y);
    y = (v1-mean)*rstd*wv.y + bv.y; v1 = (y > 0.f) ? y + 1.f : expf(y);
    y = (v2-mean)*rstd*wv.z + bv.z; v2 = (y > 0.f) ? y + 1.f : expf(y);
    y = (v3-mean)*rstd*wv.w + bv.w; v3 = (y > 0.f) ? y + 1.f : expf(y);
    xr[tid*2]     = __floats2half2_rn(v0, v1);
    xr[tid*2 + 1] = __floats2half2_rn(v2, v3);
}

// ---------------- linear attention (fp16 inputs) ----------------
__global__ __launch_bounds__(256) void kvsum_kernel(const h16* __restrict__ k,
                                                    const h16* __restrict__ v,
                                                    float* __restrict__ kv,
                                                    float* __restrict__ ksum) {
    int bh = blockIdx.x;
    int b = bh >> 4, h = bh & 15;
    int tid = threadIdx.x;
    __shared__ float ks[16][68], vs[16][68];
    int d0 = (tid >> 4) * 4, e0 = (tid & 15) * 4;
    float acc[4][4] = {};
    float accks[4] = {};
    long base = ((long)b * SS + (long)blockIdx.y * 256) * EE + h * DD;
    int ltok = tid >> 4, lc = (tid & 15) * 4;
    for (int t0 = 0; t0 < 256; t0 += 16) {
        long gi = base + (long)(t0+ltok)*EE + lc;
        h162 ka = *(const h162*)(k + gi), kb2 = *(const h162*)(k + gi + 2);
        h162 va = *(const h162*)(v + gi), vb2 = *(const h162*)(v + gi + 2);
        ks[ltok][lc+0] = __half2float(ka.x); ks[ltok][lc+1] = __half2float(ka.y);
        ks[ltok][lc+2] = __half2float(kb2.x); ks[ltok][lc+3] = __half2float(kb2.y);
        vs[ltok][lc+0] = __half2float(va.x); vs[ltok][lc+1] = __half2float(va.y);
        vs[ltok][lc+2] = __half2float(vb2.x); vs[ltok][lc+3] = __half2float(vb2.y);
        __syncthreads();
        #pragma unroll
        for (int t = 0; t < 16; t++) {
            float a[4], bb[4];
            #pragma unroll
            for (int i = 0; i < 4; i++) a[i] = ks[t][d0+i];
            #pragma unroll
            for (int j = 0; j < 4; j++) bb[j] = vs[t][e0+j];
            #pragma unroll
            for (int i = 0; i < 4; i++)
                #pragma unroll
                for (int j = 0; j < 4; j++) acc[i][j] += a[i]*bb[j];
            if (e0 == 0) {
                #pragma unroll
                for (int i = 0; i < 4; i++) accks[i] += a[i];
            }
        }
        __syncthreads();
    }
    long kvbase = (long)bh * DD * DD;
    #pragma unroll
    for (int i = 0; i < 4; i++)
        #pragma unroll
        for (int j = 0; j < 4; j++)
            atomicAdd(&kv[kvbase + (d0+i)*DD + e0+j], acc[i][j]);
    if (e0 == 0)
        #pragma unroll
        for (int i = 0; i < 4; i++) atomicAdd(&ksum[bh*DD + d0+i], accks[i]);
}

// attn = (q @ kv) / (q . ksum + 1e-8), fp16 in, fp16 out
__global__ __launch_bounds__(256) void attn_apply_kernel(const h16* __restrict__ q,
                                                         const float* __restrict__ kv,
                                                         const float* __restrict__ ksum,
                                                         h16* __restrict__ o) {
    int bh = blockIdx.x, sblk = blockIdx.y;
    int b = bh >> 4, h = bh & 15;
    int tid = threadIdx.x;
    __shared__ float qs[64][68];
    __shared__ float kvs[64][64];
    __shared__ float kss[64];
    long kvbase = (long)bh * DD * DD;
    #pragma unroll
    for (int r = 0; r < 4; r++) {
        int idx = (r*256 + tid) * 4;
        *(float4*)&kvs[idx >> 6][idx & 63] = *(const float4*)(kv + kvbase + idx);
    }
    if (tid < 64) kss[tid] = ksum[bh*DD + tid];
    long qbase = ((long)b * SS + (long)sblk * 64) * EE + h * DD;
    int ltok = tid >> 4, lc = (tid & 15) * 4;
    #pragma unroll
    for (int r = 0; r < 4; r++) {
        long gi = qbase + (long)(ltok + r*16)*EE + lc;
        h162 qa = *(const h162*)(q + gi), qb2 = *(const h162*)(q + gi + 2);
        qs[ltok + r*16][lc+0] = __half2float(qa.x);
        qs[ltok + r*16][lc+1] = __half2float(qa.y);
        qs[ltok + r*16][lc+2] = __half2float(qb2.x);
        qs[ltok + r*16][lc+3] = __half2float(qb2.y);
    }
    __syncthreads();
    int tok = tid >> 2, e0 = (tid & 3) * 16;
    float num[16] = {};
    float den = 0.f;
    #pragma unroll 8
    for (int d = 0; d < 64; d++) {
        float qd = qs[tok][d];
        den += qd * kss[d];
        #pragma unroll
        for (int j = 0; j < 16; j++) num[j] += qd * kvs[d][e0+j];
    }
    float r = 1.f / (den + 1e-8f);
    long obase = ((long)b * SS + (long)sblk * 64 + tok) * EE + h * DD + e0;
    #pragma unroll
    for (int j = 0; j < 16; j += 2)
        *(h162*)(o + obase + j) = __floats2half2_rn(num[j] * r, num[j+1] * r);
}

// ---------------- residual / transpose kernels (64x64 tiles) ----------------
// work(fp16) = qimg^T + oproj*ascal + fused GRN2 sumsq (from fp32 values)
__global__ __launch_bounds__(256) void make_working(const float* __restrict__ qimg,
                             const h16* __restrict__ attn_out,
                             const float* __restrict__ ascal,
                             h16* __restrict__ work,
                             float* __restrict__ sumsq) {
    __shared__ float t[64][65];
    __shared__ float ssq[64];
    int sx = blockIdx.x * 64, cy = blockIdx.y * 64, b = blockIdx.z;
    int tid = threadIdx.x;
    int row = tid >> 4, col4 = (tid & 15) * 4;
    #pragma unroll
    for (int r = 0; r < 64; r += 16) {
        float4 v = *(const float4*)(qimg + ((long)b*EE + cy + row + r)*SS + sx + col4);
        t[row+r][col4+0] = v.x; t[row+r][col4+1] = v.y;
        t[row+r][col4+2] = v.z; t[row+r][col4+3] = v.w;
    }
    if (tid < 64) ssq[tid] = 0.f;
    __syncthreads();
    float4 asc = *(const float4*)(ascal + cy + col4);
    float a0 = 0.f, a1 = 0.f, a2 = 0.f, a3 = 0.f;
    #pragma unroll
    for (int r = 0; r < 64; r += 16) {
        int s = row + r;
        long o = ((long)b*SS + sx + s)*EE + cy + col4;
        h162 at0 = *(const h162*)(attn_out + o);
        h162 at1 = *(const h162*)(attn_out + o + 2);
        float w0 = t[col4+0][s] + __half2float(at0.x) * asc.x;
        float w1 = t[col4+1][s] + __half2float(at0.y) * asc.y;
        float w2 = t[col4+2][s] + __half2float(at1.x) * asc.z;
        float w3 = t[col4+3][s] + __half2float(at1.y) * asc.w;
        *(h162*)(work + o)     = __floats2half2_rn(w0, w1);
        *(h162*)(work + o + 2) = __floats2half2_rn(w2, w3);
        a0 += w0*w0; a1 += w1*w1; a2 += w2*w2; a3 += w3*w3;
    }
    atomicAdd(&ssq[col4+0], a0);
    atomicAdd(&ssq[col4+1], a1);
    atomicAdd(&ssq[col4+2], a2);
    atomicAdd(&ssq[col4+3], a3);
    __syncthreads();
    if (tid < 64) atomicAdd(&sumsq[b*EE + cy + tid], ssq[tid]);
}

__global__ __launch_bounds__(256) void final_kernel(const float* __restrict__ qimg,
                             const h16* __restrict__ work,
                             const h16* __restrict__ ffn,
                             const float* __restrict__ fscal,
                             const float* __restrict__ finscal,
                             float* __restrict__ out) {
    __shared__ float t[64][65];
    int sx = blockIdx.x * 64, cy = blockIdx.y * 64, b = blockIdx.z;
    int tid = threadIdx.x;
    int row = tid >> 4, col4 = (tid & 15) * 4;
    float4 fs = *(const float4*)(fscal + cy + col4);
    float4 fin = *(const float4*)(finscal + cy + col4);
    #pragma unroll
    for (int r = 0; r < 64; r += 16) {
        int s = row + r;
        long o = ((long)b*SS + sx + s)*EE + cy + col4;
        h162 w0 = *(const h162*)(work + o), w1 = *(const h162*)(work + o + 2);
        h162 f0 = *(const h162*)(ffn + o),  f1 = *(const h162*)(ffn + o + 2);
        t[s][col4+0] = (__half2float(w0.x) + __half2float(f0.x)*fs.x)*fin.x;
        t[s][col4+1] = (__half2float(w0.y) + __half2float(f0.y)*fs.y)*fin.y;
        t[s][col4+2] = (__half2float(w1.x) + __half2float(f1.x)*fs.z)*fin.z;
        t[s][col4+3] = (__half2float(w1.y) + __half2float(f1.y)*fs.w)*fin.w;
    }
    __syncthreads();
    #pragma unroll
    for (int r = 0; r < 64; r += 16) {
        int c = row + r;
        long o = ((long)b*EE + cy + c)*SS + sx + col4;
        float4 qv = *(const float4*)(qimg + o);
        float4 ov;
        ov.x = qv.x + t[col4+0][c];
        ov.y = qv.y + t[col4+1][c];
        ov.z = qv.z + t[col4+2][c];
        ov.w = qv.w + t[col4+3][c];
        *(float4*)(out + o) = ov;
    }
}

// ---------------- host launcher ----------------
extern "C" void kernel_launch(void* const* d_in, const int* in_sizes, int n_in,
                              void* d_out, int out_size) {
    const float* qimg   = (const float*)d_in[0];
    const float* kimg   = (const float*)d_in[1];
    const float* vimg   = (const float*)d_in[2];
    const float* grn1_g = (const float*)d_in[3];
    const float* grn1_b = (const float*)d_in[4];
    const float* q_w    = (const float*)d_in[5];
    const float* q_b    = (const float*)d_in[6];
    const float* k_w    = (const float*)d_in[7];
    const float* k_b    = (const float*)d_in[8];
    const float* v_w    = (const float*)d_in[9];
    const float* v_b    = (const float*)d_in[10];
    const float* o_w    = (const float*)d_in[11];
    const float* o_b    = (const float*)d_in[12];
    const float* lnq_w  = (const float*)d_in[13];
    const float* lnq_b  = (const float*)d_in[14];
    const float* lnk_w  = (const float*)d_in[15];
    const float* lnk_b  = (const float*)d_in[16];
    const float* ascal  = (const float*)d_in[17];
    const float* grn2_g = (const float*)d_in[18];
    const float* grn2_b = (const float*)d_in[19];
    const float* w1     = (const float*)d_in[20];
    const float* b1     = (const float*)d_in[21];
    const float* w2     = (const float*)d_in[22];
    const float* b2     = (const float*)d_in[23];
    const float* fscal  = (const float*)d_in[24];
    const float* finscal= (const float*)d_in[25];

    float *kv, *sumsq, *meang;
    h16 *work, *xh, *wh, *hh, *o1, *o2;
    cudaGetSymbolAddress((void**)&work, g_work);
    cudaGetSymbolAddress((void**)&xh,   g_x);
    cudaGetSymbolAddress((void**)&wh,   g_w);
    cudaGetSymbolAddress((void**)&hh,   g_h);
    cudaGetSymbolAddress((void**)&o1,   g_o1);
    cudaGetSymbolAddress((void**)&o2,   g_o2);
    cudaGetSymbolAddress((void**)&kv,   g_kv);
    cudaGetSymbolAddress((void**)&sumsq,g_sumsq);
    cudaGetSymbolAddress((void**)&meang,g_meangx);
    float* ksum = kv + BB*HH*DD*DD;

    h16* qh = hh;                         // q/k/v alias ffn hidden (dead by then)
    h16* kh = hh + (long)BNS*EE;
    h16* vh = hh + 2L*BNS*EE;
    h16 *w_q = wh, *w_o = wh + 3*M1;
    h16 *w_1 = wh + 4*M1, *w_2 = wh + 8*M1;

    cudaFuncSetAttribute(gemm_hmma<1>, cudaFuncAttributeMaxDynamicSharedMemorySize, GSMEM);
    cudaFuncSetAttribute(gemm_hmma<2>, cudaFuncAttributeMaxDynamicSharedMemorySize, GSMEM);

    const long ES = (long)EE * SS;
    dim3 tgrid(SS/64, EE/64, BB);

    // All weight conversions in one launch
    cvt_weights<<<1184, 256>>>(q_w, k_w, v_w, o_w, w1, w2, wh);

    // GRN1 reductions on query image
    grn_sumsq_cm<<<BB*EE, 256>>>(qimg, sumsq);
    grn_mean<<<BB, 256>>>(sumsq, meang);

    // Batched transposes: qimg(+GRN1)->xh, kimg->o1, vimg->o2
    trans3<<<dim3(SS/64, EE/64, BB*3), 256>>>(qimg, kimg, vimg,
        sumsq, meang, grn1_g, grn1_b, xh, o1, o2);

    // Batched Q/K/V projections (grid.z = 3)
    gemm_hmma<2><<<dim3(EE/64, BNS/128, 3), 128, GSMEM>>>(
        xh, o1, o2, w_q, M1, q_b, k_b, v_b, qh, (long)BNS*EE, BNS, EE, EE);

    // LayerNorm + elu+1 on q and k (one launch, in place, fp16)
    ln_elu_h2<<<2*BNS, 256>>>(qh, kh, lnq_w, lnq_b, lnk_w, lnk_b);

    // linear attention (fp16 in, fp16 out)
    zero_f<<<(BB*HH*DD*DD + BB*HH*DD + 255)/256, 256>>>(kv, BB*HH*DD*DD + BB*HH*DD);
    kvsum_kernel<<<dim3(BB*HH, 16), 256>>>(kh, vh, kv, ksum);
    attn_apply_kernel<<<dim3(BB*HH, SS/64), 256>>>(qh, kv, ksum, xh);

    // O projection -> o1 (k staging dead)
    gemm_hmma<2><<<dim3(EE/64, BNS/128, 1), 128, GSMEM>>>(
        xh, nullptr, nullptr, w_o, 0, o_b, nullptr, nullptr, o1, 0, BNS, EE, EE);

    // working (fp16) = qimg^T + oproj * ascal (+ fused GRN2 sumsq)
    zero_f<<<(BB*EE + 255)/256, 256>>>(sumsq, BB*EE);
    make_working<<<tgrid, 256>>>(qimg, o1, ascal, work, sumsq);
    grn_mean<<<BB, 256>>>(sumsq, meang);
    grn2_apply<<<(int)(BB*ES/1024), 256>>>(work, sumsq, meang, grn2_g, grn2_b, xh);

    // FFN1: silu epilogue -> fp16 hidden
    gemm_hmma<1><<<dim3(E4/64, BNS/128, 1), 128, GSMEM>>>(
        xh, nullptr, nullptr, w_1, 0, b1, nullptr, nullptr, hh, 0, BNS, E4, EE);

    // FFN2 -> o2 (v staging dead)
    gemm_hmma<2><<<dim3(EE/64, BNS/128, 1), 128, GSMEM>>>(
        hh, nullptr, nullptr, w_2, 0, b2, nullptr, nullptr, o2, 0, BNS, EE, E4);

    // final residual (transpose back to channel-major)
    final_kernel<<<tgrid, 256>>>(qimg, work, o2, fscal, finscal, (float*)d_out);
}